// round 2
// baseline (speedup 1.0000x reference)
#include <cuda_runtime.h>
#include <math.h>

#define T_TOK 8192
#define D_DIM 2048
#define I_DIM 1024
#define E_NUM 32
#define K_TOP 8
#define P_NUM (T_TOK * K_TOP)

#define TM 64
#define TN 64
#define TKc 16

// ---- scratch (static device globals; no runtime allocation) ----
__device__ float g_h[(size_t)P_NUM * I_DIM];     // 268 MB: silu(x@Wg)*(x@Wu)*w per pair
__device__ float g_op[(size_t)P_NUM * D_DIM];    // 536 MB: per-pair down-proj partials
__device__ float g_pair_w[P_NUM];
__device__ int   g_pair_e[P_NUM];
__device__ int   g_counts[E_NUM];
__device__ int   g_offsets[E_NUM + 1];
__device__ int   g_cursor[E_NUM];
__device__ float g_probs_sum[E_NUM];
__device__ int   g_list[P_NUM];

// ---------------------------------------------------------------
__global__ void init_kernel() {
    int i = threadIdx.x;
    if (i < E_NUM) { g_counts[i] = 0; g_probs_sum[i] = 0.f; }
}

// One warp per token; lane == expert (E == 32).
__global__ void routing_kernel(const float* __restrict__ x,
                               const float* __restrict__ Wgate) {
    int gwarp = (blockIdx.x * blockDim.x + threadIdx.x) >> 5;
    int lane  = threadIdx.x & 31;
    if (gwarp >= T_TOK) return;

    const float* xr = x + (size_t)gwarp * D_DIM;
    float acc = 0.f;
#pragma unroll 4
    for (int d = 0; d < D_DIM; d++)
        acc += xr[d] * Wgate[d * E_NUM + lane];

    // full softmax over all experts (for aux loss)
    float m = acc;
    for (int o = 16; o; o >>= 1) m = fmaxf(m, __shfl_xor_sync(0xffffffffu, m, o));
    float pe = expf(acc - m);
    float s = pe;
    for (int o = 16; o; o >>= 1) s += __shfl_xor_sync(0xffffffffu, s, o);
    atomicAdd(&g_probs_sum[lane], pe / s);

    // iterative top-8 (lowest index wins ties, matching jax.lax.top_k)
    float v = acc;
    float selv = 0.f; int seli = 0;
#pragma unroll
    for (int k = 0; k < K_TOP; k++) {
        float mv = v;
        for (int o = 16; o; o >>= 1) mv = fmaxf(mv, __shfl_xor_sync(0xffffffffu, mv, o));
        unsigned b = __ballot_sync(0xffffffffu, v == mv);
        int src = __ffs(b) - 1;
        if (lane == k)   { selv = mv; seli = src; }
        if (lane == src) v = -INFINITY;
    }

    // softmax over the 8 selected logits (lane k holds k-th largest)
    float top0 = __shfl_sync(0xffffffffu, selv, 0);
    float ev = (lane < K_TOP) ? expf(selv - top0) : 0.f;
    float es = ev;
    for (int o = 16; o; o >>= 1) es += __shfl_xor_sync(0xffffffffu, es, o);

    if (lane < K_TOP) {
        int p = gwarp * K_TOP + lane;
        g_pair_w[p] = ev / es;
        g_pair_e[p] = seli;
        atomicAdd(&g_counts[seli], 1);
    }
}

__global__ void scan_kernel() {
    int lane = threadIdx.x;
    int c = g_counts[lane];
    int v = c;
    for (int o = 1; o < 32; o <<= 1) {
        int n = __shfl_up_sync(0xffffffffu, v, o);
        if (lane >= o) v += n;
    }
    int excl = v - c;
    g_offsets[lane] = excl;
    if (lane == 31) g_offsets[32] = v;
    g_cursor[lane] = excl;
}

__global__ void scatter_kernel() {
    int p = blockIdx.x * blockDim.x + threadIdx.x;
    if (p >= P_NUM) return;
    int e = g_pair_e[p];
    int pos = atomicAdd(&g_cursor[e], 1);
    g_list[pos] = p;
}

// ---- grouped GEMM 1: h = w * silu(X@Wg) * (X@Wu), per expert ----
__global__ __launch_bounds__(256) void gemm_gateup(const float* __restrict__ x,
                                                   const float* __restrict__ Wg,
                                                   const float* __restrict__ Wu) {
    int e = blockIdx.z;
    int start = g_offsets[e], end = g_offsets[e + 1];
    int rowBase = start + blockIdx.y * TM;
    if (rowBase >= end) return;
    int nRows = min(TM, end - rowBase);
    int colBase = blockIdx.x * TN;   // over I

    __shared__ float As[TKc][TM + 4];
    __shared__ float Bgs[TKc][TN];
    __shared__ float Bus[TKc][TN];
    __shared__ int   sP[TM];

    int tid = threadIdx.x;
    int tx = tid & 15, ty = tid >> 4;

    if (tid < TM) sP[tid] = g_list[rowBase + min(tid, nRows - 1)];
    __syncthreads();

    float c1[4][4] = {}, c2[4][4] = {};

    const float* wg_base = Wg + (size_t)e * D_DIM * I_DIM + colBase;
    const float* wu_base = Wu + (size_t)e * D_DIM * I_DIM + colBase;

    for (int k0 = 0; k0 < D_DIM; k0 += TKc) {
#pragma unroll
        for (int i = 0; i < 4; i++) {
            int li = tid + i * 256;
            int r = li >> 4, kk = li & 15;
            int t = sP[r] >> 3;
            As[kk][r] = x[(size_t)t * D_DIM + k0 + kk];
        }
#pragma unroll
        for (int i = 0; i < 4; i++) {
            int li = tid + i * 256;
            int kk = li >> 6, c = li & 63;
            size_t off = (size_t)(k0 + kk) * I_DIM + c;
            Bgs[kk][c] = wg_base[off];
            Bus[kk][c] = wu_base[off];
        }
        __syncthreads();
#pragma unroll
        for (int kk = 0; kk < TKc; kk++) {
            float a[4], bg[4], bu[4];
#pragma unroll
            for (int i = 0; i < 4; i++) a[i] = As[kk][ty * 4 + i];
#pragma unroll
            for (int j = 0; j < 4; j++) { bg[j] = Bgs[kk][tx * 4 + j]; bu[j] = Bus[kk][tx * 4 + j]; }
#pragma unroll
            for (int i = 0; i < 4; i++)
#pragma unroll
                for (int j = 0; j < 4; j++) {
                    c1[i][j] += a[i] * bg[j];
                    c2[i][j] += a[i] * bu[j];
                }
        }
        __syncthreads();
    }

#pragma unroll
    for (int i = 0; i < 4; i++) {
        int r = ty * 4 + i;
        if (r >= nRows) continue;
        int p = sP[r];
        float w = g_pair_w[p];
        float* hrow = g_h + (size_t)p * I_DIM + colBase;
#pragma unroll
        for (int j = 0; j < 4; j++) {
            float z = c1[i][j];
            float sg = z / (1.0f + expf(-z));
            hrow[tx * 4 + j] = w * sg * c2[i][j];
        }
    }
}

// ---- grouped GEMM 2: o_partial = h @ Wd, per expert ----
__global__ __launch_bounds__(256) void gemm_down(const float* __restrict__ Wd) {
    int e = blockIdx.z;
    int start = g_offsets[e], end = g_offsets[e + 1];
    int rowBase = start + blockIdx.y * TM;
    if (rowBase >= end) return;
    int nRows = min(TM, end - rowBase);
    int colBase = blockIdx.x * TN;   // over D

    __shared__ float As[TKc][TM + 4];
    __shared__ float Bs[TKc][TN];
    __shared__ int   sP[TM];

    int tid = threadIdx.x;
    int tx = tid & 15, ty = tid >> 4;

    if (tid < TM) sP[tid] = g_list[rowBase + min(tid, nRows - 1)];
    __syncthreads();

    float acc[4][4] = {};
    const float* wd_base = Wd + (size_t)e * I_DIM * D_DIM + colBase;

    for (int k0 = 0; k0 < I_DIM; k0 += TKc) {
#pragma unroll
        for (int i = 0; i < 4; i++) {
            int li = tid + i * 256;
            int r = li >> 4, kk = li & 15;
            As[kk][r] = g_h[(size_t)sP[r] * I_DIM + k0 + kk];
        }
#pragma unroll
        for (int i = 0; i < 4; i++) {
            int li = tid + i * 256;
            int kk = li >> 6, c = li & 63;
            Bs[kk][c] = wd_base[(size_t)(k0 + kk) * D_DIM + c];
        }
        __syncthreads();
#pragma unroll
        for (int kk = 0; kk < TKc; kk++) {
            float a[4], b[4];
#pragma unroll
            for (int i = 0; i < 4; i++) a[i] = As[kk][ty * 4 + i];
#pragma unroll
            for (int j = 0; j < 4; j++) b[j] = Bs[kk][tx * 4 + j];
#pragma unroll
            for (int i = 0; i < 4; i++)
#pragma unroll
                for (int j = 0; j < 4; j++) acc[i][j] += a[i] * b[j];
        }
        __syncthreads();
    }

#pragma unroll
    for (int i = 0; i < 4; i++) {
        int r = ty * 4 + i;
        if (r >= nRows) continue;
        int p = sP[r];
        float* orow = g_op + (size_t)p * D_DIM + colBase;
#pragma unroll
        for (int j = 0; j < 4; j++) orow[tx * 4 + j] = acc[i][j];
    }
}

// ---- combine: out[t] = sum over the token's 8 pairs (atomic-free) ----
__global__ void combine_kernel(float* __restrict__ out) {
    int idx = blockIdx.x * blockDim.x + threadIdx.x;
    int idx4 = idx * 4;
    if (idx4 >= T_TOK * D_DIM) return;
    int t = idx4 >> 11;            // /D_DIM
    int d = idx4 & (D_DIM - 1);
    float4 s = make_float4(0.f, 0.f, 0.f, 0.f);
#pragma unroll
    for (int k = 0; k < K_TOP; k++) {
        const float4 v = *reinterpret_cast<const float4*>(
            g_op + ((size_t)(t * K_TOP + k)) * D_DIM + d);
        s.x += v.x; s.y += v.y; s.z += v.z; s.w += v.w;
    }
    *reinterpret_cast<float4*>(out + idx4) = s;
}

__global__ void aux_kernel(float* __restrict__ out, int out_size) {
    int lane = threadIdx.x;
    float v = (lane < E_NUM) ? g_probs_sum[lane] * (float)g_counts[lane] : 0.f;
    for (int o = 16; o; o >>= 1) v += __shfl_xor_sync(0xffffffffu, v, o);
    if (lane == 0 && out_size > T_TOK * D_DIM)
        out[T_TOK * D_DIM] = v / ((float)T_TOK * (float)T_TOK);
}

// ---------------------------------------------------------------
extern "C" void kernel_launch(void* const* d_in, const int* in_sizes, int n_in,
                              void* d_out, int out_size) {
    const float* x     = (const float*)d_in[0];
    const float* Wgate = (const float*)d_in[1];
    const float* Wg    = (const float*)d_in[2];
    const float* Wu    = (const float*)d_in[3];
    const float* Wd    = (const float*)d_in[4];
    float* out = (float*)d_out;

    init_kernel<<<1, 32>>>();
    routing_kernel<<<T_TOK / 8, 256>>>(x, Wgate);
    scan_kernel<<<1, 32>>>();
    scatter_kernel<<<P_NUM / 256, 256>>>();

    dim3 g1(I_DIM / TN, T_TOK / TM, E_NUM);   // (16, 128, 32)
    gemm_gateup<<<g1, 256>>>(x, Wg, Wu);

    dim3 g2(D_DIM / TN, T_TOK / TM, E_NUM);   // (32, 128, 32)
    gemm_down<<<g2, 256>>>(Wd);

    combine_kernel<<<(T_TOK * D_DIM / 4) / 256, 256>>>(out);
    aux_kernel<<<1, 32>>>(out, out_size);
}

// round 4
// speedup vs baseline: 3.0779x; 3.0779x over previous
#include <cuda_runtime.h>
#include <cuda_bf16.h>
#include <math.h>

#define T_TOK 8192
#define D_DIM 2048
#define I_DIM 1024
#define E_NUM 32
#define K_TOP 8
#define P_NUM (T_TOK * K_TOP)

#define BM 128
#define BN 64
#define KB 32
#define A_STRIDE 40   // bf16 elems per A smem row (32 + 8 pad) -> 80B, conflict-free for ldmatrix
#define B_STRIDE 72   // bf16 elems per B smem row (64 + 8 pad) -> 144B, conflict-free for ldmatrix.trans

// ---- scratch (static device globals; no runtime allocation) ----
__device__ __nv_bfloat16 g_x_hi[(size_t)T_TOK * D_DIM];
__device__ __nv_bfloat16 g_x_lo[(size_t)T_TOK * D_DIM];
__device__ __nv_bfloat16 g_wg_hi[(size_t)E_NUM * D_DIM * I_DIM];
__device__ __nv_bfloat16 g_wg_lo[(size_t)E_NUM * D_DIM * I_DIM];
__device__ __nv_bfloat16 g_wu_hi[(size_t)E_NUM * D_DIM * I_DIM];
__device__ __nv_bfloat16 g_wu_lo[(size_t)E_NUM * D_DIM * I_DIM];
__device__ __nv_bfloat16 g_wd_hi[(size_t)E_NUM * I_DIM * D_DIM];
__device__ __nv_bfloat16 g_wd_lo[(size_t)E_NUM * I_DIM * D_DIM];
__device__ __nv_bfloat16 g_h_hi[(size_t)P_NUM * I_DIM];
__device__ __nv_bfloat16 g_h_lo[(size_t)P_NUM * I_DIM];
__device__ float g_op[(size_t)P_NUM * D_DIM];
__device__ float g_pair_w[P_NUM];
__device__ int   g_pair_e[P_NUM];
__device__ int   g_counts[E_NUM];
__device__ int   g_offsets[E_NUM + 1];
__device__ int   g_cursor[E_NUM];
__device__ float g_probs_sum[E_NUM];
__device__ int   g_list[P_NUM];

// ---- PTX helpers ----
#define LDSM_X4(R0,R1,R2,R3,ADDR) \
    asm volatile("ldmatrix.sync.aligned.m8n8.x4.shared.b16 {%0,%1,%2,%3}, [%4];" \
        : "=r"(R0),"=r"(R1),"=r"(R2),"=r"(R3) : "r"(ADDR))
#define LDSM_X4T(R0,R1,R2,R3,ADDR) \
    asm volatile("ldmatrix.sync.aligned.m8n8.x4.trans.shared.b16 {%0,%1,%2,%3}, [%4];" \
        : "=r"(R0),"=r"(R1),"=r"(R2),"=r"(R3) : "r"(ADDR))
#define MMA_BF16(C,A0,A1,A2,A3,B0,B1) \
    asm volatile("mma.sync.aligned.m16n8k16.row.col.f32.bf16.bf16.f32 " \
        "{%0,%1,%2,%3},{%4,%5,%6,%7},{%8,%9},{%0,%1,%2,%3};" \
        : "+f"((C)[0]),"+f"((C)[1]),"+f"((C)[2]),"+f"((C)[3]) \
        : "r"(A0),"r"(A1),"r"(A2),"r"(A3),"r"(B0),"r"(B1))

__device__ __forceinline__ void split_pack2(float a, float b, unsigned &hi, unsigned &lo) {
    __nv_bfloat16 ha = __float2bfloat16(a), hb = __float2bfloat16(b);
    float ra = a - __bfloat162float(ha);
    float rb = b - __bfloat162float(hb);
    __nv_bfloat162 hh = __halves2bfloat162(ha, hb);
    __nv_bfloat162 ll = __halves2bfloat162(__float2bfloat16(ra), __float2bfloat16(rb));
    hi = *reinterpret_cast<unsigned*>(&hh);
    lo = *reinterpret_cast<unsigned*>(&ll);
}

// ---------------------------------------------------------------
// Launch #1: init router state + pre-split x, Wg, Wu, Wd into bf16 hi/lo.
__global__ void convert_init_kernel(const float* __restrict__ x,
                                    const float* __restrict__ Wg,
                                    const float* __restrict__ Wu,
                                    const float* __restrict__ Wd) {
    if (blockIdx.x == 0 && threadIdx.x < E_NUM) {
        g_counts[threadIdx.x] = 0;
        g_probs_sum[threadIdx.x] = 0.f;
    }
    const size_t QX = (size_t)T_TOK * D_DIM / 4;
    const size_t QW = (size_t)E_NUM * D_DIM * I_DIM / 4;
    const size_t total = QX + 3 * QW;
    size_t q = (size_t)blockIdx.x * blockDim.x + threadIdx.x;
    size_t step = (size_t)gridDim.x * blockDim.x;
    for (; q < total; q += step) {
        const float* src; __nv_bfloat16 *hi, *lo; size_t i;
        if (q < QX)            { src = x;  hi = g_x_hi;  lo = g_x_lo;  i = q; }
        else if (q < QX + QW)  { src = Wg; hi = g_wg_hi; lo = g_wg_lo; i = q - QX; }
        else if (q < QX + 2*QW){ src = Wu; hi = g_wu_hi; lo = g_wu_lo; i = q - QX - QW; }
        else                   { src = Wd; hi = g_wd_hi; lo = g_wd_lo; i = q - QX - 2*QW; }
        float4 f = reinterpret_cast<const float4*>(src)[i];
        uint2 H, L;
        split_pack2(f.x, f.y, H.x, L.x);
        split_pack2(f.z, f.w, H.y, L.y);
        reinterpret_cast<uint2*>(hi)[i] = H;
        reinterpret_cast<uint2*>(lo)[i] = L;
    }
}

// Launch #2: one warp per token; lane == expert (E == 32). (fp32, exact routing)
__global__ void routing_kernel(const float* __restrict__ x,
                               const float* __restrict__ Wgate) {
    int gwarp = (blockIdx.x * blockDim.x + threadIdx.x) >> 5;
    int lane  = threadIdx.x & 31;
    if (gwarp >= T_TOK) return;

    const float* xr = x + (size_t)gwarp * D_DIM;
    float acc = 0.f;
#pragma unroll 4
    for (int d = 0; d < D_DIM; d++)
        acc += xr[d] * Wgate[d * E_NUM + lane];

    float m = acc;
    for (int o = 16; o; o >>= 1) m = fmaxf(m, __shfl_xor_sync(0xffffffffu, m, o));
    float pe = expf(acc - m);
    float s = pe;
    for (int o = 16; o; o >>= 1) s += __shfl_xor_sync(0xffffffffu, s, o);
    atomicAdd(&g_probs_sum[lane], pe / s);

    float v = acc;
    float selv = 0.f; int seli = 0;
#pragma unroll
    for (int k = 0; k < K_TOP; k++) {
        float mv = v;
        for (int o = 16; o; o >>= 1) mv = fmaxf(mv, __shfl_xor_sync(0xffffffffu, mv, o));
        unsigned b = __ballot_sync(0xffffffffu, v == mv);
        int src = __ffs(b) - 1;
        if (lane == k)   { selv = mv; seli = src; }
        if (lane == src) v = -INFINITY;
    }

    float top0 = __shfl_sync(0xffffffffu, selv, 0);
    float ev = (lane < K_TOP) ? expf(selv - top0) : 0.f;
    float es = ev;
    for (int o = 16; o; o >>= 1) es += __shfl_xor_sync(0xffffffffu, es, o);

    if (lane < K_TOP) {
        int p = gwarp * K_TOP + lane;
        g_pair_w[p] = ev / es;
        g_pair_e[p] = seli;
        atomicAdd(&g_counts[seli], 1);
    }
}

// Launch #3: scan + scatter fused (single block).
__global__ void scan_scatter_kernel() {
    int tid = threadIdx.x;
    if (tid < 32) {
        int c = g_counts[tid];
        int v = c;
        for (int o = 1; o < 32; o <<= 1) {
            int n = __shfl_up_sync(0xffffffffu, v, o);
            if (tid >= o) v += n;
        }
        int excl = v - c;
        g_offsets[tid] = excl;
        if (tid == 31) g_offsets[32] = v;
        g_cursor[tid] = excl;
    }
    __syncthreads();
    for (int p = tid; p < P_NUM; p += blockDim.x) {
        int e = g_pair_e[p];
        int pos = atomicAdd(&g_cursor[e], 1);
        g_list[pos] = p;
    }
}

// ---- Launch #4: grouped GEMM1 (tensor cores, bf16x3): h = w*silu(X@Wg)*(X@Wu) ----
__global__ __launch_bounds__(256) void gemm_gateup_mma() {
    int e = blockIdx.z;
    int start = g_offsets[e], end = g_offsets[e + 1];
    int rowBase = start + blockIdx.y * BM;
    if (rowBase >= end) return;
    int nRows = min(BM, end - rowBase);
    int colBase = blockIdx.x * BN;  // over I

    __shared__ __nv_bfloat16 sAh[BM * A_STRIDE], sAl[BM * A_STRIDE];
    __shared__ __nv_bfloat16 sBgh[KB * B_STRIDE], sBgl[KB * B_STRIDE];
    __shared__ __nv_bfloat16 sBuh[KB * B_STRIDE], sBul[KB * B_STRIDE];
    __shared__ int   sP[BM];
    __shared__ float sW[BM];

    int tid = threadIdx.x, lane = tid & 31, warp = tid >> 5;
    int wm = (warp & 3) * 32, wn = (warp >> 2) * 32;

    if (tid < BM) {
        int p = g_list[rowBase + min(tid, nRows - 1)];
        sP[tid] = p; sW[tid] = g_pair_w[p];
    }
    __syncthreads();

    unsigned sAh_u = (unsigned)__cvta_generic_to_shared(sAh);
    unsigned sAl_u = (unsigned)__cvta_generic_to_shared(sAl);
    unsigned sBgh_u = (unsigned)__cvta_generic_to_shared(sBgh);
    unsigned sBgl_u = (unsigned)__cvta_generic_to_shared(sBgl);
    unsigned sBuh_u = (unsigned)__cvta_generic_to_shared(sBuh);
    unsigned sBul_u = (unsigned)__cvta_generic_to_shared(sBul);

    // per-thread load coords
    int ar = tid >> 2, ac = (tid & 3) * 8;        // A: 64 rows/iter x 4 chunks
    int br = tid >> 3, bc = (tid & 7) * 8;        // B: 32 rows x 8 chunks
    // per-thread frag coords
    int arow = lane & 15, ahalf = (lane >> 4) * 8;
    int bk   = ((lane >> 3) & 1) * 8 + (lane & 7);
    int bn   = wn + (lane >> 4) * 8;

    float cg[2][4][4] = {}, cu[2][4][4] = {};
    uint4 pA0h, pA1h, pA0l, pA1l, pGh, pGl, pUh, pUl;

    const size_t wbase = (size_t)e * D_DIM * I_DIM + colBase;

#define G1_LOAD(k0) { \
    int t0 = sP[ar] >> 3, t1 = sP[ar + 64] >> 3; \
    size_t a0 = (size_t)t0 * D_DIM + (k0) + ac; \
    size_t a1 = (size_t)t1 * D_DIM + (k0) + ac; \
    pA0h = *reinterpret_cast<const uint4*>(g_x_hi + a0); \
    pA1h = *reinterpret_cast<const uint4*>(g_x_hi + a1); \
    pA0l = *reinterpret_cast<const uint4*>(g_x_lo + a0); \
    pA1l = *reinterpret_cast<const uint4*>(g_x_lo + a1); \
    size_t bo = wbase + (size_t)((k0) + br) * I_DIM + bc; \
    pGh = *reinterpret_cast<const uint4*>(g_wg_hi + bo); \
    pGl = *reinterpret_cast<const uint4*>(g_wg_lo + bo); \
    pUh = *reinterpret_cast<const uint4*>(g_wu_hi + bo); \
    pUl = *reinterpret_cast<const uint4*>(g_wu_lo + bo); }

#define G1_STORE() { \
    *reinterpret_cast<uint4*>(sAh + ar * A_STRIDE + ac) = pA0h; \
    *reinterpret_cast<uint4*>(sAh + (ar + 64) * A_STRIDE + ac) = pA1h; \
    *reinterpret_cast<uint4*>(sAl + ar * A_STRIDE + ac) = pA0l; \
    *reinterpret_cast<uint4*>(sAl + (ar + 64) * A_STRIDE + ac) = pA1l; \
    *reinterpret_cast<uint4*>(sBgh + br * B_STRIDE + bc) = pGh; \
    *reinterpret_cast<uint4*>(sBgl + br * B_STRIDE + bc) = pGl; \
    *reinterpret_cast<uint4*>(sBuh + br * B_STRIDE + bc) = pUh; \
    *reinterpret_cast<uint4*>(sBul + br * B_STRIDE + bc) = pUl; }

    G1_LOAD(0);
    G1_STORE();
    __syncthreads();

    for (int k0 = 0; k0 < D_DIM; k0 += KB) {
        bool nxt = (k0 + KB) < D_DIM;
        if (nxt) G1_LOAD(k0 + KB);

#pragma unroll
        for (int ks = 0; ks < 2; ks++) {
            unsigned ah[2][4], al[2][4];
#pragma unroll
            for (int mt = 0; mt < 2; mt++) {
                unsigned off = (unsigned)(((wm + mt * 16 + arow) * A_STRIDE + ks * 16 + ahalf) * 2);
                LDSM_X4(ah[mt][0], ah[mt][1], ah[mt][2], ah[mt][3], sAh_u + off);
                LDSM_X4(al[mt][0], al[mt][1], al[mt][2], al[mt][3], sAl_u + off);
            }
            unsigned boff0 = (unsigned)((((ks * 16 + bk) * B_STRIDE) + bn) * 2);
#pragma unroll
            for (int np = 0; np < 2; np++) {
                unsigned boff = boff0 + np * 32;  // +16 elems
                unsigned h0,h1,h2,h3,l0,l1,l2,l3;
                LDSM_X4T(h0,h1,h2,h3, sBgh_u + boff);
                LDSM_X4T(l0,l1,l2,l3, sBgl_u + boff);
#pragma unroll
                for (int mt = 0; mt < 2; mt++) {
                    MMA_BF16(cg[mt][2*np],   ah[mt][0],ah[mt][1],ah[mt][2],ah[mt][3], h0,h1);
                    MMA_BF16(cg[mt][2*np],   al[mt][0],al[mt][1],al[mt][2],al[mt][3], h0,h1);
                    MMA_BF16(cg[mt][2*np],   ah[mt][0],ah[mt][1],ah[mt][2],ah[mt][3], l0,l1);
                    MMA_BF16(cg[mt][2*np+1], ah[mt][0],ah[mt][1],ah[mt][2],ah[mt][3], h2,h3);
                    MMA_BF16(cg[mt][2*np+1], al[mt][0],al[mt][1],al[mt][2],al[mt][3], h2,h3);
                    MMA_BF16(cg[mt][2*np+1], ah[mt][0],ah[mt][1],ah[mt][2],ah[mt][3], l2,l3);
                }
            }
#pragma unroll
            for (int np = 0; np < 2; np++) {
                unsigned boff = boff0 + np * 32;
                unsigned h0,h1,h2,h3,l0,l1,l2,l3;
                LDSM_X4T(h0,h1,h2,h3, sBuh_u + boff);
                LDSM_X4T(l0,l1,l2,l3, sBul_u + boff);
#pragma unroll
                for (int mt = 0; mt < 2; mt++) {
                    MMA_BF16(cu[mt][2*np],   ah[mt][0],ah[mt][1],ah[mt][2],ah[mt][3], h0,h1);
                    MMA_BF16(cu[mt][2*np],   al[mt][0],al[mt][1],al[mt][2],al[mt][3], h0,h1);
                    MMA_BF16(cu[mt][2*np],   ah[mt][0],ah[mt][1],ah[mt][2],ah[mt][3], l0,l1);
                    MMA_BF16(cu[mt][2*np+1], ah[mt][0],ah[mt][1],ah[mt][2],ah[mt][3], h2,h3);
                    MMA_BF16(cu[mt][2*np+1], al[mt][0],al[mt][1],al[mt][2],al[mt][3], h2,h3);
                    MMA_BF16(cu[mt][2*np+1], ah[mt][0],ah[mt][1],ah[mt][2],ah[mt][3], l2,l3);
                }
            }
        }
        __syncthreads();
        if (nxt) { G1_STORE(); __syncthreads(); }
    }

    // epilogue: v = w * silu(gate) * up -> split to bf16 hi/lo
#pragma unroll
    for (int mt = 0; mt < 2; mt++)
#pragma unroll
    for (int half = 0; half < 2; half++) {
        int lr = wm + mt * 16 + (lane >> 2) + half * 8;
        if (lr < nRows) {
            int p = sP[lr]; float w = sW[lr];
            size_t base = (size_t)p * I_DIM;
#pragma unroll
            for (int nt = 0; nt < 4; nt++) {
                int col = colBase + wn + nt * 8 + (lane & 3) * 2;
                float z0 = cg[mt][nt][half*2], z1 = cg[mt][nt][half*2+1];
                float u0 = cu[mt][nt][half*2], u1 = cu[mt][nt][half*2+1];
                float v0 = w * u0 * z0 / (1.f + expf(-z0));
                float v1 = w * u1 * z1 / (1.f + expf(-z1));
                unsigned H, L;
                split_pack2(v0, v1, H, L);
                *reinterpret_cast<unsigned*>(g_h_hi + base + col) = H;
                *reinterpret_cast<unsigned*>(g_h_lo + base + col) = L;
            }
        }
    }
#undef G1_LOAD
#undef G1_STORE
}

// ---- Launch #5: grouped GEMM2 (tensor cores, bf16x3): o_partial = h @ Wd ----
__global__ __launch_bounds__(256) void gemm_down_mma() {
    int e = blockIdx.z;
    int start = g_offsets[e], end = g_offsets[e + 1];
    int rowBase = start + blockIdx.y * BM;
    if (rowBase >= end) return;
    int nRows = min(BM, end - rowBase);
    int colBase = blockIdx.x * BN;  // over D

    __shared__ __nv_bfloat16 sAh[BM * A_STRIDE], sAl[BM * A_STRIDE];
    __shared__ __nv_bfloat16 sBh[KB * B_STRIDE], sBl[KB * B_STRIDE];
    __shared__ int sP[BM];

    int tid = threadIdx.x, lane = tid & 31, warp = tid >> 5;
    int wm = (warp & 3) * 32, wn = (warp >> 2) * 32;

    if (tid < BM) sP[tid] = g_list[rowBase + min(tid, nRows - 1)];
    __syncthreads();

    unsigned sAh_u = (unsigned)__cvta_generic_to_shared(sAh);
    unsigned sAl_u = (unsigned)__cvta_generic_to_shared(sAl);
    unsigned sBh_u = (unsigned)__cvta_generic_to_shared(sBh);
    unsigned sBl_u = (unsigned)__cvta_generic_to_shared(sBl);

    int ar = tid >> 2, ac = (tid & 3) * 8;
    int br = tid >> 3, bc = (tid & 7) * 8;
    int arow = lane & 15, ahalf = (lane >> 4) * 8;
    int bk = ((lane >> 3) & 1) * 8 + (lane & 7);
    int bn = wn + (lane >> 4) * 8;

    float cc[2][4][4] = {};
    uint4 pA0h, pA1h, pA0l, pA1l, pBh, pBl;
    const size_t wbase = (size_t)e * I_DIM * D_DIM + colBase;

#define G2_LOAD(k0) { \
    size_t a0 = (size_t)sP[ar] * I_DIM + (k0) + ac; \
    size_t a1 = (size_t)sP[ar + 64] * I_DIM + (k0) + ac; \
    pA0h = *reinterpret_cast<const uint4*>(g_h_hi + a0); \
    pA1h = *reinterpret_cast<const uint4*>(g_h_hi + a1); \
    pA0l = *reinterpret_cast<const uint4*>(g_h_lo + a0); \
    pA1l = *reinterpret_cast<const uint4*>(g_h_lo + a1); \
    size_t bo = wbase + (size_t)((k0) + br) * D_DIM + bc; \
    pBh = *reinterpret_cast<const uint4*>(g_wd_hi + bo); \
    pBl = *reinterpret_cast<const uint4*>(g_wd_lo + bo); }

#define G2_STORE() { \
    *reinterpret_cast<uint4*>(sAh + ar * A_STRIDE + ac) = pA0h; \
    *reinterpret_cast<uint4*>(sAh + (ar + 64) * A_STRIDE + ac) = pA1h; \
    *reinterpret_cast<uint4*>(sAl + ar * A_STRIDE + ac) = pA0l; \
    *reinterpret_cast<uint4*>(sAl + (ar + 64) * A_STRIDE + ac) = pA1l; \
    *reinterpret_cast<uint4*>(sBh + br * B_STRIDE + bc) = pBh; \
    *reinterpret_cast<uint4*>(sBl + br * B_STRIDE + bc) = pBl; }

    G2_LOAD(0);
    G2_STORE();
    __syncthreads();

    for (int k0 = 0; k0 < I_DIM; k0 += KB) {
        bool nxt = (k0 + KB) < I_DIM;
        if (nxt) G2_LOAD(k0 + KB);

#pragma unroll
        for (int ks = 0; ks < 2; ks++) {
            unsigned ah[2][4], al[2][4];
#pragma unroll
            for (int mt = 0; mt < 2; mt++) {
                unsigned off = (unsigned)(((wm + mt * 16 + arow) * A_STRIDE + ks * 16 + ahalf) * 2);
                LDSM_X4(ah[mt][0], ah[mt][1], ah[mt][2], ah[mt][3], sAh_u + off);
                LDSM_X4(al[mt][0], al[mt][1], al[mt][2], al[mt][3], sAl_u + off);
            }
            unsigned boff0 = (unsigned)((((ks * 16 + bk) * B_STRIDE) + bn) * 2);
#pragma unroll
            for (int np = 0; np < 2; np++) {
                unsigned boff = boff0 + np * 32;
                unsigned h0,h1,h2,h3,l0,l1,l2,l3;
                LDSM_X4T(h0,h1,h2,h3, sBh_u + boff);
                LDSM_X4T(l0,l1,l2,l3, sBl_u + boff);
#pragma unroll
                for (int mt = 0; mt < 2; mt++) {
                    MMA_BF16(cc[mt][2*np],   ah[mt][0],ah[mt][1],ah[mt][2],ah[mt][3], h0,h1);
                    MMA_BF16(cc[mt][2*np],   al[mt][0],al[mt][1],al[mt][2],al[mt][3], h0,h1);
                    MMA_BF16(cc[mt][2*np],   ah[mt][0],ah[mt][1],ah[mt][2],ah[mt][3], l0,l1);
                    MMA_BF16(cc[mt][2*np+1], ah[mt][0],ah[mt][1],ah[mt][2],ah[mt][3], h2,h3);
                    MMA_BF16(cc[mt][2*np+1], al[mt][0],al[mt][1],al[mt][2],al[mt][3], h2,h3);
                    MMA_BF16(cc[mt][2*np+1], ah[mt][0],ah[mt][1],ah[mt][2],ah[mt][3], l2,l3);
                }
            }
        }
        __syncthreads();
        if (nxt) { G2_STORE(); __syncthreads(); }
    }

#pragma unroll
    for (int mt = 0; mt < 2; mt++)
#pragma unroll
    for (int half = 0; half < 2; half++) {
        int lr = wm + mt * 16 + (lane >> 2) + half * 8;
        if (lr < nRows) {
            int p = sP[lr];
            size_t base = (size_t)p * D_DIM;
#pragma unroll
            for (int nt = 0; nt < 4; nt++) {
                int col = colBase + wn + nt * 8 + (lane & 3) * 2;
                float2 v = make_float2(cc[mt][nt][half*2], cc[mt][nt][half*2+1]);
                *reinterpret_cast<float2*>(g_op + base + col) = v;
            }
        }
    }
#undef G2_LOAD
#undef G2_STORE
}

// ---- combine: out[t] = sum over the token's 8 pairs (atomic-free) ----
__global__ void combine_kernel(float* __restrict__ out) {
    int idx = blockIdx.x * blockDim.x + threadIdx.x;
    int idx4 = idx * 4;
    if (idx4 >= T_TOK * D_DIM) return;
    int t = idx4 >> 11;
    int d = idx4 & (D_DIM - 1);
    float4 s = make_float4(0.f, 0.f, 0.f, 0.f);
#pragma unroll
    for (int k = 0; k < K_TOP; k++) {
        const float4 v = *reinterpret_cast<const float4*>(
            g_op + ((size_t)(t * K_TOP + k)) * D_DIM + d);
        s.x += v.x; s.y += v.y; s.z += v.z; s.w += v.w;
    }
    *reinterpret_cast<float4*>(out + idx4) = s;
}

__global__ void aux_kernel(float* __restrict__ out, int out_size) {
    int lane = threadIdx.x;
    float v = (lane < E_NUM) ? g_probs_sum[lane] * (float)g_counts[lane] : 0.f;
    for (int o = 16; o; o >>= 1) v += __shfl_xor_sync(0xffffffffu, v, o);
    if (lane == 0 && out_size > T_TOK * D_DIM)
        out[T_TOK * D_DIM] = v / ((float)T_TOK * (float)T_TOK);
}

// ---------------------------------------------------------------
extern "C" void kernel_launch(void* const* d_in, const int* in_sizes, int n_in,
                              void* d_out, int out_size) {
    const float* x     = (const float*)d_in[0];
    const float* Wgate = (const float*)d_in[1];
    const float* Wg    = (const float*)d_in[2];
    const float* Wu    = (const float*)d_in[3];
    const float* Wd    = (const float*)d_in[4];
    float* out = (float*)d_out;

    convert_init_kernel<<<2048, 256>>>(x, Wg, Wu, Wd);
    routing_kernel<<<T_TOK / 8, 256>>>(x, Wgate);
    scan_scatter_kernel<<<1, 512>>>();

    dim3 g1(I_DIM / BN, T_TOK / BM, E_NUM);   // (16, 64, 32)
    gemm_gateup_mma<<<g1, 256>>>();

    dim3 g2(D_DIM / BN, T_TOK / BM, E_NUM);   // (32, 64, 32)
    gemm_down_mma<<<g2, 256>>>();

    combine_kernel<<<(T_TOK * D_DIM / 4) / 256, 256>>>(out);
    aux_kernel<<<1, 32>>>(out, out_size);
}

// round 7
// speedup vs baseline: 3.7982x; 1.2340x over previous
#include <cuda_runtime.h>
#include <cuda_bf16.h>
#include <math.h>
#include <stdint.h>

#define T_TOK 8192
#define D_DIM 2048
#define I_DIM 1024
#define E_NUM 32
#define K_TOP 8
#define P_NUM (T_TOK * K_TOP)

#define BM 128
#define BN 64
#define KB 32
#define A_STRIDE 40   // bf16 elems per A smem row (32 + 8 pad)
#define B_STRIDE 72   // bf16 elems per B smem row (64 + 8 pad)

#define ST_A (BM * A_STRIDE)   // 5120 elems
#define ST_B (KB * B_STRIDE)   // 2304 elems
#define G1_STAGE (2 * ST_A + 4 * ST_B)   // elems: 19456 (38912 B)
#define G2_STAGE (2 * ST_A + 2 * ST_B)   // elems: 14848 (29696 B)
#define S1 (D_DIM / KB)   // 64
#define S2 (I_DIM / KB)   // 32

// ---- scratch (static device globals; no runtime allocation) ----
__device__ __nv_bfloat16 g_x_hi[(size_t)T_TOK * D_DIM];
__device__ __nv_bfloat16 g_x_lo[(size_t)T_TOK * D_DIM];
__device__ __nv_bfloat16 g_wg_hi[(size_t)E_NUM * D_DIM * I_DIM];
__device__ __nv_bfloat16 g_wg_lo[(size_t)E_NUM * D_DIM * I_DIM];
__device__ __nv_bfloat16 g_wu_hi[(size_t)E_NUM * D_DIM * I_DIM];
__device__ __nv_bfloat16 g_wu_lo[(size_t)E_NUM * D_DIM * I_DIM];
__device__ __nv_bfloat16 g_wd_hi[(size_t)E_NUM * I_DIM * D_DIM];
__device__ __nv_bfloat16 g_wd_lo[(size_t)E_NUM * I_DIM * D_DIM];
__device__ __nv_bfloat16 g_h_hi[(size_t)P_NUM * I_DIM];
__device__ __nv_bfloat16 g_h_lo[(size_t)P_NUM * I_DIM];
__device__ float g_op[(size_t)P_NUM * D_DIM];
__device__ float g_pair_w[P_NUM];
__device__ int   g_pair_e[P_NUM];
__device__ int   g_counts[E_NUM];
__device__ int   g_offsets[E_NUM + 1];
__device__ int   g_cursor[E_NUM];
__device__ float g_probs_sum[E_NUM];
__device__ int   g_list[P_NUM];

// ---- PTX helpers ----
#define LDSM_X4(R0,R1,R2,R3,ADDR) \
    asm volatile("ldmatrix.sync.aligned.m8n8.x4.shared.b16 {%0,%1,%2,%3}, [%4];" \
        : "=r"(R0),"=r"(R1),"=r"(R2),"=r"(R3) : "r"(ADDR))
#define LDSM_X4T(R0,R1,R2,R3,ADDR) \
    asm volatile("ldmatrix.sync.aligned.m8n8.x4.trans.shared.b16 {%0,%1,%2,%3}, [%4];" \
        : "=r"(R0),"=r"(R1),"=r"(R2),"=r"(R3) : "r"(ADDR))
#define MMA_BF16(C,A0,A1,A2,A3,B0,B1) \
    asm volatile("mma.sync.aligned.m16n8k16.row.col.f32.bf16.bf16.f32 " \
        "{%0,%1,%2,%3},{%4,%5,%6,%7},{%8,%9},{%0,%1,%2,%3};" \
        : "+f"((C)[0]),"+f"((C)[1]),"+f"((C)[2]),"+f"((C)[3]) \
        : "r"(A0),"r"(A1),"r"(A2),"r"(A3),"r"(B0),"r"(B1))
#define CP16(dst, srcp) asm volatile("cp.async.cg.shared.global [%0], [%1], 16;" :: "r"(dst), "l"(srcp))
#define CP_COMMIT() asm volatile("cp.async.commit_group;" ::: "memory")
#define CP_WAIT1()  asm volatile("cp.async.wait_group 1;" ::: "memory")
#define CP_WAIT0()  asm volatile("cp.async.wait_group 0;" ::: "memory")

__device__ __forceinline__ uint32_t smem_u32(const void* p) {
    return (uint32_t)__cvta_generic_to_shared(p);
}
__device__ __forceinline__ void split_pack2(float a, float b, unsigned &hi, unsigned &lo) {
    __nv_bfloat16 ha = __float2bfloat16(a), hb = __float2bfloat16(b);
    float ra = a - __bfloat162float(ha);
    float rb = b - __bfloat162float(hb);
    __nv_bfloat162 hh = __halves2bfloat162(ha, hb);
    __nv_bfloat162 ll = __halves2bfloat162(__float2bfloat16(ra), __float2bfloat16(rb));
    hi = *reinterpret_cast<unsigned*>(&hh);
    lo = *reinterpret_cast<unsigned*>(&ll);
}

// ---------------------------------------------------------------
// Launch #1: init router state + pre-split x, Wg, Wu, Wd into bf16 hi/lo.
__global__ void convert_init_kernel(const float* __restrict__ x,
                                    const float* __restrict__ Wg,
                                    const float* __restrict__ Wu,
                                    const float* __restrict__ Wd) {
    if (blockIdx.x == 0 && threadIdx.x < E_NUM) {
        g_counts[threadIdx.x] = 0;
        g_probs_sum[threadIdx.x] = 0.f;
    }
    const size_t QX = (size_t)T_TOK * D_DIM / 4;
    const size_t QW = (size_t)E_NUM * D_DIM * I_DIM / 4;
    const size_t total = QX + 3 * QW;
    size_t q = (size_t)blockIdx.x * blockDim.x + threadIdx.x;
    size_t step = (size_t)gridDim.x * blockDim.x;
    for (; q < total; q += step) {
        const float* src; __nv_bfloat16 *hi, *lo; size_t i;
        if (q < QX)            { src = x;  hi = g_x_hi;  lo = g_x_lo;  i = q; }
        else if (q < QX + QW)  { src = Wg; hi = g_wg_hi; lo = g_wg_lo; i = q - QX; }
        else if (q < QX + 2*QW){ src = Wu; hi = g_wu_hi; lo = g_wu_lo; i = q - QX - QW; }
        else                   { src = Wd; hi = g_wd_hi; lo = g_wd_lo; i = q - QX - 2*QW; }
        float4 f = reinterpret_cast<const float4*>(src)[i];
        uint2 H, L;
        split_pack2(f.x, f.y, H.x, L.x);
        split_pack2(f.z, f.w, H.y, L.y);
        reinterpret_cast<uint2*>(hi)[i] = H;
        reinterpret_cast<uint2*>(lo)[i] = L;
    }
}

// Launch #2: one warp per token; lane == expert (E == 32). (fp32, exact routing)
__global__ void routing_kernel(const float* __restrict__ x,
                               const float* __restrict__ Wgate) {
    int gwarp = (blockIdx.x * blockDim.x + threadIdx.x) >> 5;
    int lane  = threadIdx.x & 31;
    if (gwarp >= T_TOK) return;

    const float* xr = x + (size_t)gwarp * D_DIM;
    float acc = 0.f;
#pragma unroll 4
    for (int d = 0; d < D_DIM; d++)
        acc += xr[d] * Wgate[d * E_NUM + lane];

    float m = acc;
    for (int o = 16; o; o >>= 1) m = fmaxf(m, __shfl_xor_sync(0xffffffffu, m, o));
    float pe = expf(acc - m);
    float s = pe;
    for (int o = 16; o; o >>= 1) s += __shfl_xor_sync(0xffffffffu, s, o);
    atomicAdd(&g_probs_sum[lane], pe / s);

    float v = acc;
    float selv = 0.f; int seli = 0;
#pragma unroll
    for (int k = 0; k < K_TOP; k++) {
        float mv = v;
        for (int o = 16; o; o >>= 1) mv = fmaxf(mv, __shfl_xor_sync(0xffffffffu, mv, o));
        unsigned b = __ballot_sync(0xffffffffu, v == mv);
        int src = __ffs(b) - 1;
        if (lane == k)   { selv = mv; seli = src; }
        if (lane == src) v = -INFINITY;
    }

    float top0 = __shfl_sync(0xffffffffu, selv, 0);
    float ev = (lane < K_TOP) ? expf(selv - top0) : 0.f;
    float es = ev;
    for (int o = 16; o; o >>= 1) es += __shfl_xor_sync(0xffffffffu, es, o);

    if (lane < K_TOP) {
        int p = gwarp * K_TOP + lane;
        g_pair_w[p] = ev / es;
        g_pair_e[p] = seli;
        atomicAdd(&g_counts[seli], 1);
    }
}

// Launch #3: scan + scatter fused (single block).
__global__ void scan_scatter_kernel() {
    int tid = threadIdx.x;
    if (tid < 32) {
        int c = g_counts[tid];
        int v = c;
        for (int o = 1; o < 32; o <<= 1) {
            int n = __shfl_up_sync(0xffffffffu, v, o);
            if (tid >= o) v += n;
        }
        int excl = v - c;
        g_offsets[tid] = excl;
        if (tid == 31) g_offsets[32] = v;
        g_cursor[tid] = excl;
    }
    __syncthreads();
    for (int p = tid; p < P_NUM; p += blockDim.x) {
        int e = g_pair_e[p];
        int pos = atomicAdd(&g_cursor[e], 1);
        g_list[pos] = p;
    }
}

// ---- cp.async stage loaders ----
__device__ __forceinline__ void g1_load(int tid, int k0, __nv_bfloat16* st,
                                        const int* sT,
                                        const __nv_bfloat16* bg_h, const __nv_bfloat16* bg_l,
                                        const __nv_bfloat16* bu_h, const __nv_bfloat16* bu_l) {
    __nv_bfloat16* sA = st;
    __nv_bfloat16* sB = st + 2 * ST_A;
#pragma unroll
    for (int i = 0; i < 2; i++) {
        int q = tid + i * 256;
        int r = q >> 2, c = (q & 3) * 8;
        size_t so = (size_t)sT[r] * D_DIM + k0 + c;
        uint32_t d = smem_u32(sA + r * A_STRIDE + c);
        CP16(d, g_x_hi + so);
        CP16(d + ST_A * 2, g_x_lo + so);
    }
    {
        int r = tid >> 3, c = (tid & 7) * 8;
        size_t so = (size_t)(k0 + r) * I_DIM + c;   // caller pre-offsets by colBase
        uint32_t d = smem_u32(sB + r * B_STRIDE + c);
        CP16(d,              bg_h + so);
        CP16(d + ST_B * 2,   bg_l + so);
        CP16(d + ST_B * 4,   bu_h + so);
        CP16(d + ST_B * 6,   bu_l + so);
    }
    CP_COMMIT();
}

__device__ __forceinline__ void g2_load(int tid, int k0, __nv_bfloat16* st,
                                        const int* sPp,
                                        const __nv_bfloat16* bd_h, const __nv_bfloat16* bd_l) {
    __nv_bfloat16* sA = st;
    __nv_bfloat16* sB = st + 2 * ST_A;
#pragma unroll
    for (int i = 0; i < 2; i++) {
        int q = tid + i * 256;
        int r = q >> 2, c = (q & 3) * 8;
        size_t so = (size_t)sPp[r] * I_DIM + k0 + c;
        uint32_t d = smem_u32(sA + r * A_STRIDE + c);
        CP16(d, g_h_hi + so);
        CP16(d + ST_A * 2, g_h_lo + so);
    }
    {
        int r = tid >> 3, c = (tid & 7) * 8;
        size_t so = (size_t)(k0 + r) * D_DIM + c;   // caller pre-offsets by colBase
        uint32_t d = smem_u32(sB + r * B_STRIDE + c);
        CP16(d,            bd_h + so);
        CP16(d + ST_B * 2, bd_l + so);
    }
    CP_COMMIT();
}

// ---- Launch #4: grouped GEMM1 (bf16x3, cp.async double buffer) ----
__global__ __launch_bounds__(256, 2) void gemm_gateup_mma() {
    extern __shared__ __nv_bfloat16 dyn[];
    int e = blockIdx.z;
    int start = g_offsets[e], end = g_offsets[e + 1];
    int rowBase = start + blockIdx.y * BM;
    if (rowBase >= end) return;
    int nRows = min(BM, end - rowBase);
    int colBase = blockIdx.x * BN;  // over I

    __shared__ int   sP[BM];
    __shared__ int   sT[BM];
    __shared__ float sW[BM];

    int tid = threadIdx.x, lane = tid & 31, warp = tid >> 5;
    int wm = (warp & 3) * 32, wn = (warp >> 2) * 32;

    if (tid < BM) {
        int p = g_list[rowBase + min(tid, nRows - 1)];
        sP[tid] = p; sT[tid] = p >> 3; sW[tid] = g_pair_w[p];
    }
    __syncthreads();

    const __nv_bfloat16* bg_h = g_wg_hi + (size_t)e * D_DIM * I_DIM + colBase;
    const __nv_bfloat16* bg_l = g_wg_lo + (size_t)e * D_DIM * I_DIM + colBase;
    const __nv_bfloat16* bu_h = g_wu_hi + (size_t)e * D_DIM * I_DIM + colBase;
    const __nv_bfloat16* bu_l = g_wu_lo + (size_t)e * D_DIM * I_DIM + colBase;

    int arow = lane & 15, ahalf = (lane >> 4) * 8;
    int bk   = ((lane >> 3) & 1) * 8 + (lane & 7);
    int bn   = wn + (lane >> 4) * 8;

    float cg[2][4][4] = {}, cu[2][4][4] = {};

    g1_load(tid, 0, dyn, sT, bg_h, bg_l, bu_h, bu_l);
    g1_load(tid, KB, dyn + G1_STAGE, sT, bg_h, bg_l, bu_h, bu_l);

    for (int s = 0; s < S1; s++) {
        if (s + 1 < S1) { CP_WAIT1(); } else { CP_WAIT0(); }
        __syncthreads();

        __nv_bfloat16* st = dyn + (s & 1) * G1_STAGE;
        uint32_t sA_u = smem_u32(st);
        uint32_t sB_u = smem_u32(st + 2 * ST_A);

#pragma unroll
        for (int ks = 0; ks < 2; ks++) {
            unsigned ah[2][4], al[2][4];
#pragma unroll
            for (int mt = 0; mt < 2; mt++) {
                unsigned off = (unsigned)(((wm + mt * 16 + arow) * A_STRIDE + ks * 16 + ahalf) * 2);
                LDSM_X4(ah[mt][0], ah[mt][1], ah[mt][2], ah[mt][3], sA_u + off);
                LDSM_X4(al[mt][0], al[mt][1], al[mt][2], al[mt][3], sA_u + ST_A * 2 + off);
            }
            unsigned boff0 = (unsigned)((((ks * 16 + bk) * B_STRIDE) + bn) * 2);
#pragma unroll
            for (int np = 0; np < 2; np++) {
                unsigned boff = boff0 + np * 32;
                unsigned h0,h1,h2,h3,l0,l1,l2,l3;
                LDSM_X4T(h0,h1,h2,h3, sB_u + boff);
                LDSM_X4T(l0,l1,l2,l3, sB_u + ST_B * 2 + boff);
#pragma unroll
                for (int mt = 0; mt < 2; mt++) {
                    MMA_BF16(cg[mt][2*np],   ah[mt][0],ah[mt][1],ah[mt][2],ah[mt][3], h0,h1);
                    MMA_BF16(cg[mt][2*np],   al[mt][0],al[mt][1],al[mt][2],al[mt][3], h0,h1);
                    MMA_BF16(cg[mt][2*np],   ah[mt][0],ah[mt][1],ah[mt][2],ah[mt][3], l0,l1);
                    MMA_BF16(cg[mt][2*np+1], ah[mt][0],ah[mt][1],ah[mt][2],ah[mt][3], h2,h3);
                    MMA_BF16(cg[mt][2*np+1], al[mt][0],al[mt][1],al[mt][2],al[mt][3], h2,h3);
                    MMA_BF16(cg[mt][2*np+1], ah[mt][0],ah[mt][1],ah[mt][2],ah[mt][3], l2,l3);
                }
            }
#pragma unroll
            for (int np = 0; np < 2; np++) {
                unsigned boff = boff0 + np * 32;
                unsigned h0,h1,h2,h3,l0,l1,l2,l3;
                LDSM_X4T(h0,h1,h2,h3, sB_u + ST_B * 4 + boff);
                LDSM_X4T(l0,l1,l2,l3, sB_u + ST_B * 6 + boff);
#pragma unroll
                for (int mt = 0; mt < 2; mt++) {
                    MMA_BF16(cu[mt][2*np],   ah[mt][0],ah[mt][1],ah[mt][2],ah[mt][3], h0,h1);
                    MMA_BF16(cu[mt][2*np],   al[mt][0],al[mt][1],al[mt][2],al[mt][3], h0,h1);
                    MMA_BF16(cu[mt][2*np],   ah[mt][0],ah[mt][1],ah[mt][2],ah[mt][3], l0,l1);
                    MMA_BF16(cu[mt][2*np+1], ah[mt][0],ah[mt][1],ah[mt][2],ah[mt][3], h2,h3);
                    MMA_BF16(cu[mt][2*np+1], al[mt][0],al[mt][1],al[mt][2],al[mt][3], h2,h3);
                    MMA_BF16(cu[mt][2*np+1], ah[mt][0],ah[mt][1],ah[mt][2],ah[mt][3], l2,l3);
                }
            }
        }
        __syncthreads();
        if (s + 2 < S1)
            g1_load(tid, (s + 2) * KB, dyn + (s & 1) * G1_STAGE, sT, bg_h, bg_l, bu_h, bu_l);
    }

    // epilogue: v = w * silu(gate) * up -> split to bf16 hi/lo
#pragma unroll
    for (int mt = 0; mt < 2; mt++)
#pragma unroll
    for (int half = 0; half < 2; half++) {
        int lr = wm + mt * 16 + (lane >> 2) + half * 8;
        if (lr < nRows) {
            int p = sP[lr]; float w = sW[lr];
            size_t base = (size_t)p * I_DIM;
#pragma unroll
            for (int nt = 0; nt < 4; nt++) {
                int col = colBase + wn + nt * 8 + (lane & 3) * 2;
                float z0 = cg[mt][nt][half*2], z1 = cg[mt][nt][half*2+1];
                float u0 = cu[mt][nt][half*2], u1 = cu[mt][nt][half*2+1];
                float v0 = w * u0 * z0 / (1.f + expf(-z0));
                float v1 = w * u1 * z1 / (1.f + expf(-z1));
                unsigned H, L;
                split_pack2(v0, v1, H, L);
                *reinterpret_cast<unsigned*>(g_h_hi + base + col) = H;
                *reinterpret_cast<unsigned*>(g_h_lo + base + col) = L;
            }
        }
    }
}

// ---- Launch #5: grouped GEMM2 (bf16x3, cp.async double buffer) ----
__global__ __launch_bounds__(256, 2) void gemm_down_mma() {
    extern __shared__ __nv_bfloat16 dyn[];
    int e = blockIdx.z;
    int start = g_offsets[e], end = g_offsets[e + 1];
    int rowBase = start + blockIdx.y * BM;
    if (rowBase >= end) return;
    int nRows = min(BM, end - rowBase);
    int colBase = blockIdx.x * BN;  // over D

    __shared__ int sP[BM];

    int tid = threadIdx.x, lane = tid & 31, warp = tid >> 5;
    int wm = (warp & 3) * 32, wn = (warp >> 2) * 32;

    if (tid < BM) sP[tid] = g_list[rowBase + min(tid, nRows - 1)];
    __syncthreads();

    const __nv_bfloat16* bd_h = g_wd_hi + (size_t)e * I_DIM * D_DIM + colBase;
    const __nv_bfloat16* bd_l = g_wd_lo + (size_t)e * I_DIM * D_DIM + colBase;

    int arow = lane & 15, ahalf = (lane >> 4) * 8;
    int bk = ((lane >> 3) & 1) * 8 + (lane & 7);
    int bn = wn + (lane >> 4) * 8;

    float cc[2][4][4] = {};

    g2_load(tid, 0, dyn, sP, bd_h, bd_l);
    g2_load(tid, KB, dyn + G2_STAGE, sP, bd_h, bd_l);

    for (int s = 0; s < S2; s++) {
        if (s + 1 < S2) { CP_WAIT1(); } else { CP_WAIT0(); }
        __syncthreads();

        __nv_bfloat16* st = dyn + (s & 1) * G2_STAGE;
        uint32_t sA_u = smem_u32(st);
        uint32_t sB_u = smem_u32(st + 2 * ST_A);

#pragma unroll
        for (int ks = 0; ks < 2; ks++) {
            unsigned ah[2][4], al[2][4];
#pragma unroll
            for (int mt = 0; mt < 2; mt++) {
                unsigned off = (unsigned)(((wm + mt * 16 + arow) * A_STRIDE + ks * 16 + ahalf) * 2);
                LDSM_X4(ah[mt][0], ah[mt][1], ah[mt][2], ah[mt][3], sA_u + off);
                LDSM_X4(al[mt][0], al[mt][1], al[mt][2], al[mt][3], sA_u + ST_A * 2 + off);
            }
            unsigned boff0 = (unsigned)((((ks * 16 + bk) * B_STRIDE) + bn) * 2);
#pragma unroll
            for (int np = 0; np < 2; np++) {
                unsigned boff = boff0 + np * 32;
                unsigned h0,h1,h2,h3,l0,l1,l2,l3;
                LDSM_X4T(h0,h1,h2,h3, sB_u + boff);
                LDSM_X4T(l0,l1,l2,l3, sB_u + ST_B * 2 + boff);
#pragma unroll
                for (int mt = 0; mt < 2; mt++) {
                    MMA_BF16(cc[mt][2*np],   ah[mt][0],ah[mt][1],ah[mt][2],ah[mt][3], h0,h1);
                    MMA_BF16(cc[mt][2*np],   al[mt][0],al[mt][1],al[mt][2],al[mt][3], h0,h1);
                    MMA_BF16(cc[mt][2*np],   ah[mt][0],ah[mt][1],ah[mt][2],ah[mt][3], l0,l1);
                    MMA_BF16(cc[mt][2*np+1], ah[mt][0],ah[mt][1],ah[mt][2],ah[mt][3], h2,h3);
                    MMA_BF16(cc[mt][2*np+1], al[mt][0],al[mt][1],al[mt][2],al[mt][3], h2,h3);
                    MMA_BF16(cc[mt][2*np+1], ah[mt][0],ah[mt][1],ah[mt][2],ah[mt][3], l2,l3);
                }
            }
        }
        __syncthreads();
        if (s + 2 < S2)
            g2_load(tid, (s + 2) * KB, dyn + (s & 1) * G2_STAGE, sP, bd_h, bd_l);
    }

#pragma unroll
    for (int mt = 0; mt < 2; mt++)
#pragma unroll
    for (int half = 0; half < 2; half++) {
        int lr = wm + mt * 16 + (lane >> 2) + half * 8;
        if (lr < nRows) {
            int p = sP[lr];
            size_t base = (size_t)p * D_DIM;
#pragma unroll
            for (int nt = 0; nt < 4; nt++) {
                int col = colBase + wn + nt * 8 + (lane & 3) * 2;
                float2 v = make_float2(cc[mt][nt][half*2], cc[mt][nt][half*2+1]);
                *reinterpret_cast<float2*>(g_op + base + col) = v;
            }
        }
    }
}

// ---- combine: out[t] = sum over the token's 8 pairs (atomic-free) ----
__global__ void combine_kernel(float* __restrict__ out) {
    int idx = blockIdx.x * blockDim.x + threadIdx.x;
    int idx4 = idx * 4;
    if (idx4 >= T_TOK * D_DIM) return;
    int t = idx4 >> 11;
    int d = idx4 & (D_DIM - 1);
    float4 s = make_float4(0.f, 0.f, 0.f, 0.f);
#pragma unroll
    for (int k = 0; k < K_TOP; k++) {
        const float4 v = *reinterpret_cast<const float4*>(
            g_op + ((size_t)(t * K_TOP + k)) * D_DIM + d);
        s.x += v.x; s.y += v.y; s.z += v.z; s.w += v.w;
    }
    *reinterpret_cast<float4*>(out + idx4) = s;
}

__global__ void aux_kernel(float* __restrict__ out, int out_size) {
    int lane = threadIdx.x;
    float v = (lane < E_NUM) ? g_probs_sum[lane] * (float)g_counts[lane] : 0.f;
    for (int o = 16; o; o >>= 1) v += __shfl_xor_sync(0xffffffffu, v, o);
    if (lane == 0 && out_size > T_TOK * D_DIM)
        out[T_TOK * D_DIM] = v / ((float)T_TOK * (float)T_TOK);
}

// ---------------------------------------------------------------
extern "C" void kernel_launch(void* const* d_in, const int* in_sizes, int n_in,
                              void* d_out, int out_size) {
    const float* x     = (const float*)d_in[0];
    const float* Wgate = (const float*)d_in[1];
    const float* Wg    = (const float*)d_in[2];
    const float* Wu    = (const float*)d_in[3];
    const float* Wd    = (const float*)d_in[4];
    float* out = (float*)d_out;

    // Unconditional (idempotent) — no static guards per harness contract.
    cudaFuncSetAttribute(gemm_gateup_mma, cudaFuncAttributeMaxDynamicSharedMemorySize,
                         2 * G1_STAGE * 2);
    cudaFuncSetAttribute(gemm_down_mma, cudaFuncAttributeMaxDynamicSharedMemorySize,
                         2 * G2_STAGE * 2);

    convert_init_kernel<<<2048, 256>>>(x, Wg, Wu, Wd);
    routing_kernel<<<T_TOK / 8, 256>>>(x, Wgate);
    scan_scatter_kernel<<<1, 512>>>();

    dim3 g1(I_DIM / BN, T_TOK / BM, E_NUM);   // (16, 64, 32)
    gemm_gateup_mma<<<g1, 256, 2 * G1_STAGE * 2>>>();

    dim3 g2(D_DIM / BN, T_TOK / BM, E_NUM);   // (32, 64, 32)
    gemm_down_mma<<<g2, 256, 2 * G2_STAGE * 2>>>();

    combine_kernel<<<(T_TOK * D_DIM / 4) / 256, 256>>>(out);
    aux_kernel<<<1, 32>>>(out, out_size);
}

// round 9
// speedup vs baseline: 3.8161x; 1.0047x over previous
#include <cuda_runtime.h>
#include <cuda_bf16.h>
#include <math.h>
#include <stdint.h>

#define T_TOK 8192
#define D_DIM 2048
#define I_DIM 1024
#define E_NUM 32
#define K_TOP 8
#define P_NUM (T_TOK * K_TOP)

#define BM 128
#define BN 64
#define KB 32
#define A_STRIDE 40   // bf16 elems per A smem row (32 + 8 pad)
#define B_STRIDE 72   // bf16 elems per B smem row (64 + 8 pad)

#define ST_A (BM * A_STRIDE)   // 5120 elems
#define ST_B (KB * B_STRIDE)   // 2304 elems
#define G1_STAGE (2 * ST_A + 4 * ST_B)   // elems: 19456 (38912 B)
#define G2_STAGE (2 * ST_A + 2 * ST_B)   // elems: 14848 (29696 B)
#define S1 (D_DIM / KB)   // 64
#define S2 (I_DIM / KB)   // 32

// ---- scratch (static device globals; no runtime allocation) ----
__device__ __nv_bfloat16 g_x_hi[(size_t)T_TOK * D_DIM];
__device__ __nv_bfloat16 g_x_lo[(size_t)T_TOK * D_DIM];
__device__ __nv_bfloat16 g_wg_hi[(size_t)E_NUM * D_DIM * I_DIM];
__device__ __nv_bfloat16 g_wg_lo[(size_t)E_NUM * D_DIM * I_DIM];
__device__ __nv_bfloat16 g_wu_hi[(size_t)E_NUM * D_DIM * I_DIM];
__device__ __nv_bfloat16 g_wu_lo[(size_t)E_NUM * D_DIM * I_DIM];
__device__ __nv_bfloat16 g_wd_hi[(size_t)E_NUM * I_DIM * D_DIM];
__device__ __nv_bfloat16 g_wd_lo[(size_t)E_NUM * I_DIM * D_DIM];
__device__ __nv_bfloat16 g_h_hi[(size_t)P_NUM * I_DIM];
__device__ __nv_bfloat16 g_h_lo[(size_t)P_NUM * I_DIM];
__device__ float g_op[(size_t)P_NUM * D_DIM];
__device__ float g_pair_w[P_NUM];
__device__ int   g_pair_e[P_NUM];
__device__ int   g_counts[E_NUM];
__device__ int   g_offsets[E_NUM + 1];
__device__ int   g_cursor[E_NUM];
__device__ float g_probs_sum[E_NUM];
__device__ int   g_list[P_NUM];

// ---- PTX helpers ----
#define LDSM_X4(R0,R1,R2,R3,ADDR) \
    asm volatile("ldmatrix.sync.aligned.m8n8.x4.shared.b16 {%0,%1,%2,%3}, [%4];" \
        : "=r"(R0),"=r"(R1),"=r"(R2),"=r"(R3) : "r"(ADDR))
#define LDSM_X4T(R0,R1,R2,R3,ADDR) \
    asm volatile("ldmatrix.sync.aligned.m8n8.x4.trans.shared.b16 {%0,%1,%2,%3}, [%4];" \
        : "=r"(R0),"=r"(R1),"=r"(R2),"=r"(R3) : "r"(ADDR))
#define MMA_BF16(C,A0,A1,A2,A3,B0,B1) \
    asm volatile("mma.sync.aligned.m16n8k16.row.col.f32.bf16.bf16.f32 " \
        "{%0,%1,%2,%3},{%4,%5,%6,%7},{%8,%9},{%0,%1,%2,%3};" \
        : "+f"((C)[0]),"+f"((C)[1]),"+f"((C)[2]),"+f"((C)[3]) \
        : "r"(A0),"r"(A1),"r"(A2),"r"(A3),"r"(B0),"r"(B1))
#define CP16(dst, srcp) asm volatile("cp.async.cg.shared.global [%0], [%1], 16;" :: "r"(dst), "l"(srcp))
#define CP_COMMIT() asm volatile("cp.async.commit_group;" ::: "memory")
#define CP_WAIT1()  asm volatile("cp.async.wait_group 1;" ::: "memory")
#define CP_WAIT0()  asm volatile("cp.async.wait_group 0;" ::: "memory")

__device__ __forceinline__ uint32_t smem_u32(const void* p) {
    return (uint32_t)__cvta_generic_to_shared(p);
}
__device__ __forceinline__ void split_pack2(float a, float b, unsigned &hi, unsigned &lo) {
    __nv_bfloat16 ha = __float2bfloat16(a), hb = __float2bfloat16(b);
    float ra = a - __bfloat162float(ha);
    float rb = b - __bfloat162float(hb);
    __nv_bfloat162 hh = __halves2bfloat162(ha, hb);
    __nv_bfloat162 ll = __halves2bfloat162(__float2bfloat16(ra), __float2bfloat16(rb));
    hi = *reinterpret_cast<unsigned*>(&hh);
    lo = *reinterpret_cast<unsigned*>(&ll);
}

// ---------------------------------------------------------------
// Launch #1: init router state + pre-split x, Wg, Wu, Wd into bf16 hi/lo.
__global__ void convert_init_kernel(const float* __restrict__ x,
                                    const float* __restrict__ Wg,
                                    const float* __restrict__ Wu,
                                    const float* __restrict__ Wd) {
    if (blockIdx.x == 0 && threadIdx.x < E_NUM) {
        g_counts[threadIdx.x] = 0;
        g_probs_sum[threadIdx.x] = 0.f;
    }
    const size_t QX = (size_t)T_TOK * D_DIM / 4;
    const size_t QW = (size_t)E_NUM * D_DIM * I_DIM / 4;
    const size_t total = QX + 3 * QW;
    size_t q = (size_t)blockIdx.x * blockDim.x + threadIdx.x;
    size_t step = (size_t)gridDim.x * blockDim.x;
    for (; q < total; q += step) {
        const float* src; __nv_bfloat16 *hi, *lo; size_t i;
        if (q < QX)            { src = x;  hi = g_x_hi;  lo = g_x_lo;  i = q; }
        else if (q < QX + QW)  { src = Wg; hi = g_wg_hi; lo = g_wg_lo; i = q - QX; }
        else if (q < QX + 2*QW){ src = Wu; hi = g_wu_hi; lo = g_wu_lo; i = q - QX - QW; }
        else                   { src = Wd; hi = g_wd_hi; lo = g_wd_lo; i = q - QX - 2*QW; }
        float4 f = reinterpret_cast<const float4*>(src)[i];
        uint2 H, L;
        split_pack2(f.x, f.y, H.x, L.x);
        split_pack2(f.z, f.w, H.y, L.y);
        reinterpret_cast<uint2*>(hi)[i] = H;
        reinterpret_cast<uint2*>(lo)[i] = L;
    }
}

// Launch #2: one warp per token; lane == expert (E == 32). (fp32, exact routing)
__global__ void routing_kernel(const float* __restrict__ x,
                               const float* __restrict__ Wgate) {
    int gwarp = (blockIdx.x * blockDim.x + threadIdx.x) >> 5;
    int lane  = threadIdx.x & 31;
    if (gwarp >= T_TOK) return;

    const float* xr = x + (size_t)gwarp * D_DIM;
    float acc = 0.f;
#pragma unroll 4
    for (int d = 0; d < D_DIM; d++)
        acc += xr[d] * Wgate[d * E_NUM + lane];

    float m = acc;
    for (int o = 16; o; o >>= 1) m = fmaxf(m, __shfl_xor_sync(0xffffffffu, m, o));
    float pe = expf(acc - m);
    float s = pe;
    for (int o = 16; o; o >>= 1) s += __shfl_xor_sync(0xffffffffu, s, o);
    atomicAdd(&g_probs_sum[lane], pe / s);

    float v = acc;
    float selv = 0.f; int seli = 0;
#pragma unroll
    for (int k = 0; k < K_TOP; k++) {
        float mv = v;
        for (int o = 16; o; o >>= 1) mv = fmaxf(mv, __shfl_xor_sync(0xffffffffu, mv, o));
        unsigned b = __ballot_sync(0xffffffffu, v == mv);
        int src = __ffs(b) - 1;
        if (lane == k)   { selv = mv; seli = src; }
        if (lane == src) v = -INFINITY;
    }

    float top0 = __shfl_sync(0xffffffffu, selv, 0);
    float ev = (lane < K_TOP) ? expf(selv - top0) : 0.f;
    float es = ev;
    for (int o = 16; o; o >>= 1) es += __shfl_xor_sync(0xffffffffu, es, o);

    if (lane < K_TOP) {
        int p = gwarp * K_TOP + lane;
        g_pair_w[p] = ev / es;
        g_pair_e[p] = seli;
        atomicAdd(&g_counts[seli], 1);
    }
}

// Launch #3: scan + scatter fused (single block).
__global__ void scan_scatter_kernel() {
    int tid = threadIdx.x;
    if (tid < 32) {
        int c = g_counts[tid];
        int v = c;
        for (int o = 1; o < 32; o <<= 1) {
            int n = __shfl_up_sync(0xffffffffu, v, o);
            if (tid >= o) v += n;
        }
        int excl = v - c;
        g_offsets[tid] = excl;
        if (tid == 31) g_offsets[32] = v;
        g_cursor[tid] = excl;
    }
    __syncthreads();
    for (int p = tid; p < P_NUM; p += blockDim.x) {
        int e = g_pair_e[p];
        int pos = atomicAdd(&g_cursor[e], 1);
        g_list[pos] = p;
    }
}

// ---- cp.async stage loaders ----
__device__ __forceinline__ void g1_load(int tid, int k0, __nv_bfloat16* st,
                                        const int* sT,
                                        const __nv_bfloat16* bg_h, const __nv_bfloat16* bg_l,
                                        const __nv_bfloat16* bu_h, const __nv_bfloat16* bu_l) {
    __nv_bfloat16* sA = st;
    __nv_bfloat16* sB = st + 2 * ST_A;
#pragma unroll
    for (int i = 0; i < 2; i++) {
        int q = tid + i * 256;
        int r = q >> 2, c = (q & 3) * 8;
        size_t so = (size_t)sT[r] * D_DIM + k0 + c;
        uint32_t d = smem_u32(sA + r * A_STRIDE + c);
        CP16(d, g_x_hi + so);
        CP16(d + ST_A * 2, g_x_lo + so);
    }
    {
        int r = tid >> 3, c = (tid & 7) * 8;
        size_t so = (size_t)(k0 + r) * I_DIM + c;   // caller pre-offsets by colBase
        uint32_t d = smem_u32(sB + r * B_STRIDE + c);
        CP16(d,              bg_h + so);
        CP16(d + ST_B * 2,   bg_l + so);
        CP16(d + ST_B * 4,   bu_h + so);
        CP16(d + ST_B * 6,   bu_l + so);
    }
    CP_COMMIT();
}

__device__ __forceinline__ void g2_load(int tid, int k0, __nv_bfloat16* st,
                                        const int* sPp,
                                        const __nv_bfloat16* bd_h, const __nv_bfloat16* bd_l) {
    __nv_bfloat16* sA = st;
    __nv_bfloat16* sB = st + 2 * ST_A;
#pragma unroll
    for (int i = 0; i < 2; i++) {
        int q = tid + i * 256;
        int r = q >> 2, c = (q & 3) * 8;
        size_t so = (size_t)sPp[r] * I_DIM + k0 + c;
        uint32_t d = smem_u32(sA + r * A_STRIDE + c);
        CP16(d, g_h_hi + so);
        CP16(d + ST_A * 2, g_h_lo + so);
    }
    {
        int r = tid >> 3, c = (tid & 7) * 8;
        size_t so = (size_t)(k0 + r) * D_DIM + c;   // caller pre-offsets by colBase
        uint32_t d = smem_u32(sB + r * B_STRIDE + c);
        CP16(d,            bd_h + so);
        CP16(d + ST_B * 2, bd_l + so);
    }
    CP_COMMIT();
}

// ---- Launch #4: grouped GEMM1 (bf16x3, cp.async 2-buffer, single sync/stage) ----
__global__ __launch_bounds__(256, 2) void gemm_gateup_mma() {
    extern __shared__ __nv_bfloat16 dyn[];
    int e = blockIdx.z;
    int start = g_offsets[e], end = g_offsets[e + 1];
    int rowBase = start + blockIdx.y * BM;
    if (rowBase >= end) return;
    int nRows = min(BM, end - rowBase);
    int colBase = blockIdx.x * BN;  // over I

    __shared__ int   sP[BM];
    __shared__ int   sT[BM];
    __shared__ float sW[BM];

    int tid = threadIdx.x, lane = tid & 31, warp = tid >> 5;
    int wm = (warp & 3) * 32, wn = (warp >> 2) * 32;

    if (tid < BM) {
        int p = g_list[rowBase + min(tid, nRows - 1)];
        sP[tid] = p; sT[tid] = p >> 3; sW[tid] = g_pair_w[p];
    }
    __syncthreads();

    const __nv_bfloat16* bg_h = g_wg_hi + (size_t)e * D_DIM * I_DIM + colBase;
    const __nv_bfloat16* bg_l = g_wg_lo + (size_t)e * D_DIM * I_DIM + colBase;
    const __nv_bfloat16* bu_h = g_wu_hi + (size_t)e * D_DIM * I_DIM + colBase;
    const __nv_bfloat16* bu_l = g_wu_lo + (size_t)e * D_DIM * I_DIM + colBase;

    int arow = lane & 15, ahalf = (lane >> 4) * 8;
    int bk   = ((lane >> 3) & 1) * 8 + (lane & 7);
    int bn   = wn + (lane >> 4) * 8;

    float cg[2][4][4] = {}, cu[2][4][4] = {};

    g1_load(tid, 0, dyn, sT, bg_h, bg_l, bu_h, bu_l);

#pragma unroll 2
    for (int s = 0; s < S1; s++) {
        // stage-s data arrived (only group s can be outstanding here)
        CP_WAIT0();
        __syncthreads();   // publishes stage s; proves stage s-1 reads of nxt done
        if (s + 1 < S1)
            g1_load(tid, (s + 1) * KB, dyn + ((s + 1) & 1) * G1_STAGE, sT, bg_h, bg_l, bu_h, bu_l);

        __nv_bfloat16* st = dyn + (s & 1) * G1_STAGE;
        uint32_t sA_u = smem_u32(st);
        uint32_t sB_u = smem_u32(st + 2 * ST_A);

#pragma unroll
        for (int ks = 0; ks < 2; ks++) {
            unsigned ah[2][4], al[2][4];
#pragma unroll
            for (int mt = 0; mt < 2; mt++) {
                unsigned off = (unsigned)(((wm + mt * 16 + arow) * A_STRIDE + ks * 16 + ahalf) * 2);
                LDSM_X4(ah[mt][0], ah[mt][1], ah[mt][2], ah[mt][3], sA_u + off);
                LDSM_X4(al[mt][0], al[mt][1], al[mt][2], al[mt][3], sA_u + ST_A * 2 + off);
            }
            unsigned boff0 = (unsigned)((((ks * 16 + bk) * B_STRIDE) + bn) * 2);
#pragma unroll
            for (int np = 0; np < 2; np++) {
                unsigned boff = boff0 + np * 32;
                unsigned h0,h1,h2,h3,l0,l1,l2,l3;
                LDSM_X4T(h0,h1,h2,h3, sB_u + boff);
                LDSM_X4T(l0,l1,l2,l3, sB_u + ST_B * 2 + boff);
#pragma unroll
                for (int mt = 0; mt < 2; mt++) {
                    MMA_BF16(cg[mt][2*np],   ah[mt][0],ah[mt][1],ah[mt][2],ah[mt][3], h0,h1);
                    MMA_BF16(cg[mt][2*np],   al[mt][0],al[mt][1],al[mt][2],al[mt][3], h0,h1);
                    MMA_BF16(cg[mt][2*np],   ah[mt][0],ah[mt][1],ah[mt][2],ah[mt][3], l0,l1);
                    MMA_BF16(cg[mt][2*np+1], ah[mt][0],ah[mt][1],ah[mt][2],ah[mt][3], h2,h3);
                    MMA_BF16(cg[mt][2*np+1], al[mt][0],al[mt][1],al[mt][2],al[mt][3], h2,h3);
                    MMA_BF16(cg[mt][2*np+1], ah[mt][0],ah[mt][1],ah[mt][2],ah[mt][3], l2,l3);
                }
            }
#pragma unroll
            for (int np = 0; np < 2; np++) {
                unsigned boff = boff0 + np * 32;
                unsigned h0,h1,h2,h3,l0,l1,l2,l3;
                LDSM_X4T(h0,h1,h2,h3, sB_u + ST_B * 4 + boff);
                LDSM_X4T(l0,l1,l2,l3, sB_u + ST_B * 6 + boff);
#pragma unroll
                for (int mt = 0; mt < 2; mt++) {
                    MMA_BF16(cu[mt][2*np],   ah[mt][0],ah[mt][1],ah[mt][2],ah[mt][3], h0,h1);
                    MMA_BF16(cu[mt][2*np],   al[mt][0],al[mt][1],al[mt][2],al[mt][3], h0,h1);
                    MMA_BF16(cu[mt][2*np],   ah[mt][0],ah[mt][1],ah[mt][2],ah[mt][3], l0,l1);
                    MMA_BF16(cu[mt][2*np+1], ah[mt][0],ah[mt][1],ah[mt][2],ah[mt][3], h2,h3);
                    MMA_BF16(cu[mt][2*np+1], al[mt][0],al[mt][1],al[mt][2],al[mt][3], h2,h3);
                    MMA_BF16(cu[mt][2*np+1], ah[mt][0],ah[mt][1],ah[mt][2],ah[mt][3], l2,l3);
                }
            }
        }
    }

    // epilogue: v = w * silu(gate) * up -> split to bf16 hi/lo
#pragma unroll
    for (int mt = 0; mt < 2; mt++)
#pragma unroll
    for (int half = 0; half < 2; half++) {
        int lr = wm + mt * 16 + (lane >> 2) + half * 8;
        if (lr < nRows) {
            int p = sP[lr]; float w = sW[lr];
            size_t base = (size_t)p * I_DIM;
#pragma unroll
            for (int nt = 0; nt < 4; nt++) {
                int col = colBase + wn + nt * 8 + (lane & 3) * 2;
                float z0 = cg[mt][nt][half*2], z1 = cg[mt][nt][half*2+1];
                float u0 = cu[mt][nt][half*2], u1 = cu[mt][nt][half*2+1];
                float v0 = w * u0 * z0 / (1.f + expf(-z0));
                float v1 = w * u1 * z1 / (1.f + expf(-z1));
                unsigned H, L;
                split_pack2(v0, v1, H, L);
                *reinterpret_cast<unsigned*>(g_h_hi + base + col) = H;
                *reinterpret_cast<unsigned*>(g_h_lo + base + col) = L;
            }
        }
    }
}

// ---- Launch #5: grouped GEMM2 (bf16x3, cp.async 3-buffer, single sync/stage) ----
__global__ __launch_bounds__(256, 2) void gemm_down_mma() {
    extern __shared__ __nv_bfloat16 dyn[];
    int e = blockIdx.z;
    int start = g_offsets[e], end = g_offsets[e + 1];
    int rowBase = start + blockIdx.y * BM;
    if (rowBase >= end) return;
    int nRows = min(BM, end - rowBase);
    int colBase = blockIdx.x * BN;  // over D

    __shared__ int sP[BM];

    int tid = threadIdx.x, lane = tid & 31, warp = tid >> 5;
    int wm = (warp & 3) * 32, wn = (warp >> 2) * 32;

    if (tid < BM) sP[tid] = g_list[rowBase + min(tid, nRows - 1)];
    __syncthreads();

    const __nv_bfloat16* bd_h = g_wd_hi + (size_t)e * I_DIM * D_DIM + colBase;
    const __nv_bfloat16* bd_l = g_wd_lo + (size_t)e * I_DIM * D_DIM + colBase;

    int arow = lane & 15, ahalf = (lane >> 4) * 8;
    int bk = ((lane >> 3) & 1) * 8 + (lane & 7);
    int bn = wn + (lane >> 4) * 8;

    float cc[2][4][4] = {};

    g2_load(tid, 0, dyn, sP, bd_h, bd_l);
    g2_load(tid, KB, dyn + G2_STAGE, sP, bd_h, bd_l);

#pragma unroll 3
    for (int s = 0; s < S2; s++) {
        // mid-loop: a group after s always exists -> WAIT1 proves group s done.
        // last iteration: group s IS the most recent -> must WAIT0.
        if (s + 1 < S2) { CP_WAIT1(); } else { CP_WAIT0(); }
        __syncthreads();   // publishes stage s; proves stage s-1 reads done
        if (s + 2 < S2)
            g2_load(tid, (s + 2) * KB, dyn + ((s + 2) % 3) * G2_STAGE, sP, bd_h, bd_l);

        __nv_bfloat16* st = dyn + (s % 3) * G2_STAGE;
        uint32_t sA_u = smem_u32(st);
        uint32_t sB_u = smem_u32(st + 2 * ST_A);

#pragma unroll
        for (int ks = 0; ks < 2; ks++) {
            unsigned ah[2][4], al[2][4];
#pragma unroll
            for (int mt = 0; mt < 2; mt++) {
                unsigned off = (unsigned)(((wm + mt * 16 + arow) * A_STRIDE + ks * 16 + ahalf) * 2);
                LDSM_X4(ah[mt][0], ah[mt][1], ah[mt][2], ah[mt][3], sA_u + off);
                LDSM_X4(al[mt][0], al[mt][1], al[mt][2], al[mt][3], sA_u + ST_A * 2 + off);
            }
            unsigned boff0 = (unsigned)((((ks * 16 + bk) * B_STRIDE) + bn) * 2);
#pragma unroll
            for (int np = 0; np < 2; np++) {
                unsigned boff = boff0 + np * 32;
                unsigned h0,h1,h2,h3,l0,l1,l2,l3;
                LDSM_X4T(h0,h1,h2,h3, sB_u + boff);
                LDSM_X4T(l0,l1,l2,l3, sB_u + ST_B * 2 + boff);
#pragma unroll
                for (int mt = 0; mt < 2; mt++) {
                    MMA_BF16(cc[mt][2*np],   ah[mt][0],ah[mt][1],ah[mt][2],ah[mt][3], h0,h1);
                    MMA_BF16(cc[mt][2*np],   al[mt][0],al[mt][1],al[mt][2],al[mt][3], h0,h1);
                    MMA_BF16(cc[mt][2*np],   ah[mt][0],ah[mt][1],ah[mt][2],ah[mt][3], l0,l1);
                    MMA_BF16(cc[mt][2*np+1], ah[mt][0],ah[mt][1],ah[mt][2],ah[mt][3], h2,h3);
                    MMA_BF16(cc[mt][2*np+1], al[mt][0],al[mt][1],al[mt][2],al[mt][3], h2,h3);
                    MMA_BF16(cc[mt][2*np+1], ah[mt][0],ah[mt][1],ah[mt][2],ah[mt][3], l2,l3);
                }
            }
        }
    }

#pragma unroll
    for (int mt = 0; mt < 2; mt++)
#pragma unroll
    for (int half = 0; half < 2; half++) {
        int lr = wm + mt * 16 + (lane >> 2) + half * 8;
        if (lr < nRows) {
            int p = sP[lr];
            size_t base = (size_t)p * D_DIM;
#pragma unroll
            for (int nt = 0; nt < 4; nt++) {
                int col = colBase + wn + nt * 8 + (lane & 3) * 2;
                float2 v = make_float2(cc[mt][nt][half*2], cc[mt][nt][half*2+1]);
                *reinterpret_cast<float2*>(g_op + base + col) = v;
            }
        }
    }
}

// ---- combine: out[t] = sum over the token's 8 pairs (atomic-free) ----
__global__ void combine_kernel(float* __restrict__ out) {
    int idx = blockIdx.x * blockDim.x + threadIdx.x;
    int idx4 = idx * 4;
    if (idx4 >= T_TOK * D_DIM) return;
    int t = idx4 >> 11;
    int d = idx4 & (D_DIM - 1);
    float4 s = make_float4(0.f, 0.f, 0.f, 0.f);
#pragma unroll
    for (int k = 0; k < K_TOP; k++) {
        const float4 v = *reinterpret_cast<const float4*>(
            g_op + ((size_t)(t * K_TOP + k)) * D_DIM + d);
        s.x += v.x; s.y += v.y; s.z += v.z; s.w += v.w;
    }
    *reinterpret_cast<float4*>(out + idx4) = s;
}

__global__ void aux_kernel(float* __restrict__ out, int out_size) {
    int lane = threadIdx.x;
    float v = (lane < E_NUM) ? g_probs_sum[lane] * (float)g_counts[lane] : 0.f;
    for (int o = 16; o; o >>= 1) v += __shfl_xor_sync(0xffffffffu, v, o);
    if (lane == 0 && out_size > T_TOK * D_DIM)
        out[T_TOK * D_DIM] = v / ((float)T_TOK * (float)T_TOK);
}

// ---------------------------------------------------------------
extern "C" void kernel_launch(void* const* d_in, const int* in_sizes, int n_in,
                              void* d_out, int out_size) {
    const float* x     = (const float*)d_in[0];
    const float* Wgate = (const float*)d_in[1];
    const float* Wg    = (const float*)d_in[2];
    const float* Wu    = (const float*)d_in[3];
    const float* Wd    = (const float*)d_in[4];
    float* out = (float*)d_out;

    // Unconditional (idempotent) — no static guards per harness contract.
    cudaFuncSetAttribute(gemm_gateup_mma, cudaFuncAttributeMaxDynamicSharedMemorySize,
                         2 * G1_STAGE * 2);
    cudaFuncSetAttribute(gemm_down_mma, cudaFuncAttributeMaxDynamicSharedMemorySize,
                         3 * G2_STAGE * 2);

    convert_init_kernel<<<2048, 256>>>(x, Wg, Wu, Wd);
    routing_kernel<<<T_TOK / 8, 256>>>(x, Wgate);
    scan_scatter_kernel<<<1, 512>>>();

    dim3 g1(I_DIM / BN, T_TOK / BM, E_NUM);   // (16, 64, 32)
    gemm_gateup_mma<<<g1, 256, 2 * G1_STAGE * 2>>>();

    dim3 g2(D_DIM / BN, T_TOK / BM, E_NUM);   // (32, 64, 32)
    gemm_down_mma<<<g2, 256, 3 * G2_STAGE * 2>>>();

    combine_kernel<<<(T_TOK * D_DIM / 4) / 256, 256>>>(out);
    aux_kernel<<<1, 32>>>(out, out_size);
}

// round 10
// speedup vs baseline: 5.0970x; 1.3356x over previous
#include <cuda_runtime.h>
#include <cuda_fp16.h>
#include <math.h>
#include <stdint.h>

#define T_TOK 8192
#define D_DIM 2048
#define I_DIM 1024
#define E_NUM 32
#define K_TOP 8
#define P_NUM (T_TOK * K_TOP)

#define BM 128
#define BN 64
#define KB 32
#define A_STRIDE 40   // fp16 elems per A smem row (32 + 8 pad)
#define B_STRIDE 72   // fp16 elems per B smem row (64 + 8 pad)

#define ST_A (BM * A_STRIDE)           // 5120 elems
#define ST_B (KB * B_STRIDE)           // 2304 elems
#define G1_STAGE (2 * ST_A + 2 * ST_B) // 14848 elems (29696 B)
#define G2_STAGE (2 * ST_A + 1 * ST_B) // 12544 elems (25088 B)
#define S1 (D_DIM / KB)   // 64
#define S2 (I_DIM / KB)   // 32

// ---- scratch (static device globals; no runtime allocation) ----
__device__ __half g_x_hi[(size_t)T_TOK * D_DIM];
__device__ __half g_x_lo[(size_t)T_TOK * D_DIM];
__device__ __half g_wg[(size_t)E_NUM * D_DIM * I_DIM];   // single fp16 (rounded)
__device__ __half g_wu[(size_t)E_NUM * D_DIM * I_DIM];
__device__ __half g_wd[(size_t)E_NUM * I_DIM * D_DIM];
__device__ __half g_h_hi[(size_t)P_NUM * I_DIM];
__device__ __half g_h_lo[(size_t)P_NUM * I_DIM];
__device__ float g_op[(size_t)P_NUM * D_DIM];
__device__ float g_pair_w[P_NUM];
__device__ int   g_pair_e[P_NUM];
__device__ int   g_counts[E_NUM];
__device__ int   g_offsets[E_NUM + 1];
__device__ int   g_cursor[E_NUM];
__device__ float g_probs_sum[E_NUM];
__device__ int   g_list[P_NUM];

// ---- PTX helpers ----
#define LDSM_X4(R0,R1,R2,R3,ADDR) \
    asm volatile("ldmatrix.sync.aligned.m8n8.x4.shared.b16 {%0,%1,%2,%3}, [%4];" \
        : "=r"(R0),"=r"(R1),"=r"(R2),"=r"(R3) : "r"(ADDR))
#define LDSM_X4T(R0,R1,R2,R3,ADDR) \
    asm volatile("ldmatrix.sync.aligned.m8n8.x4.trans.shared.b16 {%0,%1,%2,%3}, [%4];" \
        : "=r"(R0),"=r"(R1),"=r"(R2),"=r"(R3) : "r"(ADDR))
#define MMA_F16(C,A0,A1,A2,A3,B0,B1) \
    asm volatile("mma.sync.aligned.m16n8k16.row.col.f32.f16.f16.f32 " \
        "{%0,%1,%2,%3},{%4,%5,%6,%7},{%8,%9},{%0,%1,%2,%3};" \
        : "+f"((C)[0]),"+f"((C)[1]),"+f"((C)[2]),"+f"((C)[3]) \
        : "r"(A0),"r"(A1),"r"(A2),"r"(A3),"r"(B0),"r"(B1))
#define CP16(dst, srcp) asm volatile("cp.async.cg.shared.global [%0], [%1], 16;" :: "r"(dst), "l"(srcp))
#define CP_COMMIT() asm volatile("cp.async.commit_group;" ::: "memory")
#define CP_WAIT1()  asm volatile("cp.async.wait_group 1;" ::: "memory")
#define CP_WAIT0()  asm volatile("cp.async.wait_group 0;" ::: "memory")

__device__ __forceinline__ uint32_t smem_u32(const void* p) {
    return (uint32_t)__cvta_generic_to_shared(p);
}
// split two fp32 into fp16 hi/lo pairs (hi packs, lo packs)
__device__ __forceinline__ void split_pack2h(float a, float b, unsigned &hi, unsigned &lo) {
    __half ha = __float2half_rn(a), hb = __float2half_rn(b);
    float ra = a - __half2float(ha);
    float rb = b - __half2float(hb);
    __half2 hh = __halves2half2(ha, hb);
    __half2 ll = __halves2half2(__float2half_rn(ra), __float2half_rn(rb));
    hi = *reinterpret_cast<unsigned*>(&hh);
    lo = *reinterpret_cast<unsigned*>(&ll);
}
__device__ __forceinline__ unsigned round_pack2h(float a, float b) {
    __half2 hh = __halves2half2(__float2half_rn(a), __float2half_rn(b));
    return *reinterpret_cast<unsigned*>(&hh);
}

// ---------------------------------------------------------------
// Launch #1: init router state + convert: x -> fp16 hi/lo split, W -> single fp16.
__global__ void convert_init_kernel(const float* __restrict__ x,
                                    const float* __restrict__ Wg,
                                    const float* __restrict__ Wu,
                                    const float* __restrict__ Wd) {
    if (blockIdx.x == 0 && threadIdx.x < E_NUM) {
        g_counts[threadIdx.x] = 0;
        g_probs_sum[threadIdx.x] = 0.f;
    }
    const size_t QX = (size_t)T_TOK * D_DIM / 4;
    const size_t QW = (size_t)E_NUM * D_DIM * I_DIM / 4;
    const size_t total = QX + 3 * QW;
    size_t q = (size_t)blockIdx.x * blockDim.x + threadIdx.x;
    size_t step = (size_t)gridDim.x * blockDim.x;
    for (; q < total; q += step) {
        if (q < QX) {
            float4 f = reinterpret_cast<const float4*>(x)[q];
            uint2 H, L;
            split_pack2h(f.x, f.y, H.x, L.x);
            split_pack2h(f.z, f.w, H.y, L.y);
            reinterpret_cast<uint2*>(g_x_hi)[q] = H;
            reinterpret_cast<uint2*>(g_x_lo)[q] = L;
        } else {
            const float* src; __half* dst; size_t i = q - QX;
            if (i < QW)            { src = Wg; dst = g_wg; }
            else if (i < 2 * QW)   { src = Wu; dst = g_wu; i -= QW; }
            else                   { src = Wd; dst = g_wd; i -= 2 * QW; }
            float4 f = reinterpret_cast<const float4*>(src)[i];
            uint2 H;
            H.x = round_pack2h(f.x, f.y);
            H.y = round_pack2h(f.z, f.w);
            reinterpret_cast<uint2*>(dst)[i] = H;
        }
    }
}

// Launch #2: one warp per token; lane == expert (E == 32). (fp32, exact routing)
__global__ void routing_kernel(const float* __restrict__ x,
                               const float* __restrict__ Wgate) {
    int gwarp = (blockIdx.x * blockDim.x + threadIdx.x) >> 5;
    int lane  = threadIdx.x & 31;
    if (gwarp >= T_TOK) return;

    const float4* xr4 = reinterpret_cast<const float4*>(x + (size_t)gwarp * D_DIM);
    float acc = 0.f;
#pragma unroll 2
    for (int d4 = 0; d4 < D_DIM / 4; d4++) {
        float4 xv = xr4[d4];
        int d = d4 * 4;
        acc += xv.x * Wgate[(d + 0) * E_NUM + lane];
        acc += xv.y * Wgate[(d + 1) * E_NUM + lane];
        acc += xv.z * Wgate[(d + 2) * E_NUM + lane];
        acc += xv.w * Wgate[(d + 3) * E_NUM + lane];
    }

    float m = acc;
    for (int o = 16; o; o >>= 1) m = fmaxf(m, __shfl_xor_sync(0xffffffffu, m, o));
    float pe = expf(acc - m);
    float s = pe;
    for (int o = 16; o; o >>= 1) s += __shfl_xor_sync(0xffffffffu, s, o);
    atomicAdd(&g_probs_sum[lane], pe / s);

    float v = acc;
    float selv = 0.f; int seli = 0;
#pragma unroll
    for (int k = 0; k < K_TOP; k++) {
        float mv = v;
        for (int o = 16; o; o >>= 1) mv = fmaxf(mv, __shfl_xor_sync(0xffffffffu, mv, o));
        unsigned b = __ballot_sync(0xffffffffu, v == mv);
        int src = __ffs(b) - 1;
        if (lane == k)   { selv = mv; seli = src; }
        if (lane == src) v = -INFINITY;
    }

    float top0 = __shfl_sync(0xffffffffu, selv, 0);
    float ev = (lane < K_TOP) ? expf(selv - top0) : 0.f;
    float es = ev;
    for (int o = 16; o; o >>= 1) es += __shfl_xor_sync(0xffffffffu, es, o);

    if (lane < K_TOP) {
        int p = gwarp * K_TOP + lane;
        g_pair_w[p] = ev / es;
        g_pair_e[p] = seli;
        atomicAdd(&g_counts[seli], 1);
    }
}

// Launch #3: scan + scatter fused (single block).
__global__ void scan_scatter_kernel() {
    int tid = threadIdx.x;
    if (tid < 32) {
        int c = g_counts[tid];
        int v = c;
        for (int o = 1; o < 32; o <<= 1) {
            int n = __shfl_up_sync(0xffffffffu, v, o);
            if (tid >= o) v += n;
        }
        int excl = v - c;
        g_offsets[tid] = excl;
        if (tid == 31) g_offsets[32] = v;
        g_cursor[tid] = excl;
    }
    __syncthreads();
    for (int p = tid; p < P_NUM; p += blockDim.x) {
        int e = g_pair_e[p];
        int pos = atomicAdd(&g_cursor[e], 1);
        g_list[pos] = p;
    }
}

// ---- cp.async stage loaders ----
__device__ __forceinline__ void g1_load(int tid, int k0, __half* st,
                                        const int* sT,
                                        const __half* bg, const __half* bu) {
#pragma unroll
    for (int i = 0; i < 2; i++) {
        int q = tid + i * 256;
        int r = q >> 2, c = (q & 3) * 8;
        size_t so = (size_t)sT[r] * D_DIM + k0 + c;
        uint32_t d = smem_u32(st + r * A_STRIDE + c);
        CP16(d, g_x_hi + so);
        CP16(d + ST_A * 2, g_x_lo + so);
    }
    {
        int r = tid >> 3, c = (tid & 7) * 8;
        size_t so = (size_t)(k0 + r) * I_DIM + c;   // caller pre-offsets by colBase
        uint32_t d = smem_u32(st + 2 * ST_A + r * B_STRIDE + c);
        CP16(d,            bg + so);
        CP16(d + ST_B * 2, bu + so);
    }
    CP_COMMIT();
}

__device__ __forceinline__ void g2_load(int tid, int k0, __half* st,
                                        const int* sPp,
                                        const __half* bd) {
#pragma unroll
    for (int i = 0; i < 2; i++) {
        int q = tid + i * 256;
        int r = q >> 2, c = (q & 3) * 8;
        size_t so = (size_t)sPp[r] * I_DIM + k0 + c;
        uint32_t d = smem_u32(st + r * A_STRIDE + c);
        CP16(d, g_h_hi + so);
        CP16(d + ST_A * 2, g_h_lo + so);
    }
    {
        int r = tid >> 3, c = (tid & 7) * 8;
        size_t so = (size_t)(k0 + r) * D_DIM + c;   // caller pre-offsets by colBase
        uint32_t d = smem_u32(st + 2 * ST_A + r * B_STRIDE + c);
        CP16(d, bd + so);
    }
    CP_COMMIT();
}

// ---- Launch #4: grouped GEMM1 (fp16x2, cp.async 3-buffer, single sync/stage) ----
// D = (x_hi + x_lo) @ fp16(W) ; activation split exact, weight rounding ~2^-12.
__global__ __launch_bounds__(256, 2) void gemm_gateup_mma() {
    extern __shared__ __half dyn[];
    int e = blockIdx.z;
    int start = g_offsets[e], end = g_offsets[e + 1];
    int rowBase = start + blockIdx.y * BM;
    if (rowBase >= end) return;
    int nRows = min(BM, end - rowBase);
    int colBase = blockIdx.x * BN;  // over I

    __shared__ int   sP[BM];
    __shared__ int   sT[BM];
    __shared__ float sW[BM];

    int tid = threadIdx.x, lane = tid & 31, warp = tid >> 5;
    int wm = (warp & 3) * 32, wn = (warp >> 2) * 32;

    if (tid < BM) {
        int p = g_list[rowBase + min(tid, nRows - 1)];
        sP[tid] = p; sT[tid] = p >> 3; sW[tid] = g_pair_w[p];
    }
    __syncthreads();

    const __half* bg = g_wg + (size_t)e * D_DIM * I_DIM + colBase;
    const __half* bu = g_wu + (size_t)e * D_DIM * I_DIM + colBase;

    int arow = lane & 15, ahalf = (lane >> 4) * 8;
    int bk   = ((lane >> 3) & 1) * 8 + (lane & 7);
    int bn   = wn + (lane >> 4) * 8;

    float cg[2][4][4] = {}, cu[2][4][4] = {};

    g1_load(tid, 0, dyn, sT, bg, bu);
    g1_load(tid, KB, dyn + G1_STAGE, sT, bg, bu);

#pragma unroll 3
    for (int s = 0; s < S1; s++) {
        // mid-loop: a later group exists -> WAIT1 proves group s done; last: WAIT0.
        if (s + 1 < S1) { CP_WAIT1(); } else { CP_WAIT0(); }
        __syncthreads();   // publishes stage s; proves stage s-1 reads done
        if (s + 2 < S1)
            g1_load(tid, (s + 2) * KB, dyn + ((s + 2) % 3) * G1_STAGE, sT, bg, bu);

        __half* st = dyn + (s % 3) * G1_STAGE;
        uint32_t sA_u = smem_u32(st);
        uint32_t sB_u = smem_u32(st + 2 * ST_A);

#pragma unroll
        for (int ks = 0; ks < 2; ks++) {
            unsigned ah[2][4], al[2][4];
#pragma unroll
            for (int mt = 0; mt < 2; mt++) {
                unsigned off = (unsigned)(((wm + mt * 16 + arow) * A_STRIDE + ks * 16 + ahalf) * 2);
                LDSM_X4(ah[mt][0], ah[mt][1], ah[mt][2], ah[mt][3], sA_u + off);
                LDSM_X4(al[mt][0], al[mt][1], al[mt][2], al[mt][3], sA_u + ST_A * 2 + off);
            }
            unsigned boff0 = (unsigned)((((ks * 16 + bk) * B_STRIDE) + bn) * 2);
#pragma unroll
            for (int np = 0; np < 2; np++) {
                unsigned boff = boff0 + np * 32;
                unsigned b0,b1,b2,b3;
                LDSM_X4T(b0,b1,b2,b3, sB_u + boff);
#pragma unroll
                for (int mt = 0; mt < 2; mt++) {
                    MMA_F16(cg[mt][2*np],   ah[mt][0],ah[mt][1],ah[mt][2],ah[mt][3], b0,b1);
                    MMA_F16(cg[mt][2*np],   al[mt][0],al[mt][1],al[mt][2],al[mt][3], b0,b1);
                    MMA_F16(cg[mt][2*np+1], ah[mt][0],ah[mt][1],ah[mt][2],ah[mt][3], b2,b3);
                    MMA_F16(cg[mt][2*np+1], al[mt][0],al[mt][1],al[mt][2],al[mt][3], b2,b3);
                }
            }
#pragma unroll
            for (int np = 0; np < 2; np++) {
                unsigned boff = boff0 + np * 32;
                unsigned b0,b1,b2,b3;
                LDSM_X4T(b0,b1,b2,b3, sB_u + ST_B * 2 + boff);
#pragma unroll
                for (int mt = 0; mt < 2; mt++) {
                    MMA_F16(cu[mt][2*np],   ah[mt][0],ah[mt][1],ah[mt][2],ah[mt][3], b0,b1);
                    MMA_F16(cu[mt][2*np],   al[mt][0],al[mt][1],al[mt][2],al[mt][3], b0,b1);
                    MMA_F16(cu[mt][2*np+1], ah[mt][0],ah[mt][1],ah[mt][2],ah[mt][3], b2,b3);
                    MMA_F16(cu[mt][2*np+1], al[mt][0],al[mt][1],al[mt][2],al[mt][3], b2,b3);
                }
            }
        }
    }

    // epilogue: v = w * silu(gate) * up -> split to fp16 hi/lo
#pragma unroll
    for (int mt = 0; mt < 2; mt++)
#pragma unroll
    for (int half = 0; half < 2; half++) {
        int lr = wm + mt * 16 + (lane >> 2) + half * 8;
        if (lr < nRows) {
            int p = sP[lr]; float w = sW[lr];
            size_t base = (size_t)p * I_DIM;
#pragma unroll
            for (int nt = 0; nt < 4; nt++) {
                int col = colBase + wn + nt * 8 + (lane & 3) * 2;
                float z0 = cg[mt][nt][half*2], z1 = cg[mt][nt][half*2+1];
                float u0 = cu[mt][nt][half*2], u1 = cu[mt][nt][half*2+1];
                float v0 = w * u0 * z0 / (1.f + expf(-z0));
                float v1 = w * u1 * z1 / (1.f + expf(-z1));
                unsigned H, L;
                split_pack2h(v0, v1, H, L);
                *reinterpret_cast<unsigned*>(g_h_hi + base + col) = H;
                *reinterpret_cast<unsigned*>(g_h_lo + base + col) = L;
            }
        }
    }
}

// ---- Launch #5: grouped GEMM2 (fp16x2, cp.async 3-buffer, single sync/stage) ----
__global__ __launch_bounds__(256, 2) void gemm_down_mma() {
    extern __shared__ __half dyn[];
    int e = blockIdx.z;
    int start = g_offsets[e], end = g_offsets[e + 1];
    int rowBase = start + blockIdx.y * BM;
    if (rowBase >= end) return;
    int nRows = min(BM, end - rowBase);
    int colBase = blockIdx.x * BN;  // over D

    __shared__ int sP[BM];

    int tid = threadIdx.x, lane = tid & 31, warp = tid >> 5;
    int wm = (warp & 3) * 32, wn = (warp >> 2) * 32;

    if (tid < BM) sP[tid] = g_list[rowBase + min(tid, nRows - 1)];
    __syncthreads();

    const __half* bd = g_wd + (size_t)e * I_DIM * D_DIM + colBase;

    int arow = lane & 15, ahalf = (lane >> 4) * 8;
    int bk = ((lane >> 3) & 1) * 8 + (lane & 7);
    int bn = wn + (lane >> 4) * 8;

    float cc[2][4][4] = {};

    g2_load(tid, 0, dyn, sP, bd);
    g2_load(tid, KB, dyn + G2_STAGE, sP, bd);

#pragma unroll 3
    for (int s = 0; s < S2; s++) {
        if (s + 1 < S2) { CP_WAIT1(); } else { CP_WAIT0(); }
        __syncthreads();
        if (s + 2 < S2)
            g2_load(tid, (s + 2) * KB, dyn + ((s + 2) % 3) * G2_STAGE, sP, bd);

        __half* st = dyn + (s % 3) * G2_STAGE;
        uint32_t sA_u = smem_u32(st);
        uint32_t sB_u = smem_u32(st + 2 * ST_A);

#pragma unroll
        for (int ks = 0; ks < 2; ks++) {
            unsigned ah[2][4], al[2][4];
#pragma unroll
            for (int mt = 0; mt < 2; mt++) {
                unsigned off = (unsigned)(((wm + mt * 16 + arow) * A_STRIDE + ks * 16 + ahalf) * 2);
                LDSM_X4(ah[mt][0], ah[mt][1], ah[mt][2], ah[mt][3], sA_u + off);
                LDSM_X4(al[mt][0], al[mt][1], al[mt][2], al[mt][3], sA_u + ST_A * 2 + off);
            }
            unsigned boff0 = (unsigned)((((ks * 16 + bk) * B_STRIDE) + bn) * 2);
#pragma unroll
            for (int np = 0; np < 2; np++) {
                unsigned boff = boff0 + np * 32;
                unsigned b0,b1,b2,b3;
                LDSM_X4T(b0,b1,b2,b3, sB_u + boff);
#pragma unroll
                for (int mt = 0; mt < 2; mt++) {
                    MMA_F16(cc[mt][2*np],   ah[mt][0],ah[mt][1],ah[mt][2],ah[mt][3], b0,b1);
                    MMA_F16(cc[mt][2*np],   al[mt][0],al[mt][1],al[mt][2],al[mt][3], b0,b1);
                    MMA_F16(cc[mt][2*np+1], ah[mt][0],ah[mt][1],ah[mt][2],ah[mt][3], b2,b3);
                    MMA_F16(cc[mt][2*np+1], al[mt][0],al[mt][1],al[mt][2],al[mt][3], b2,b3);
                }
            }
        }
    }

#pragma unroll
    for (int mt = 0; mt < 2; mt++)
#pragma unroll
    for (int half = 0; half < 2; half++) {
        int lr = wm + mt * 16 + (lane >> 2) + half * 8;
        if (lr < nRows) {
            int p = sP[lr];
            size_t base = (size_t)p * D_DIM;
#pragma unroll
            for (int nt = 0; nt < 4; nt++) {
                int col = colBase + wn + nt * 8 + (lane & 3) * 2;
                float2 v = make_float2(cc[mt][nt][half*2], cc[mt][nt][half*2+1]);
                *reinterpret_cast<float2*>(g_op + base + col) = v;
            }
        }
    }
}

// ---- combine: out[t] = sum over the token's 8 pairs (atomic-free) ----
__global__ void combine_kernel(float* __restrict__ out) {
    int idx = blockIdx.x * blockDim.x + threadIdx.x;
    int idx4 = idx * 4;
    if (idx4 >= T_TOK * D_DIM) return;
    int t = idx4 >> 11;
    int d = idx4 & (D_DIM - 1);
    float4 s = make_float4(0.f, 0.f, 0.f, 0.f);
#pragma unroll
    for (int k = 0; k < K_TOP; k++) {
        const float4 v = *reinterpret_cast<const float4*>(
            g_op + ((size_t)(t * K_TOP + k)) * D_DIM + d);
        s.x += v.x; s.y += v.y; s.z += v.z; s.w += v.w;
    }
    *reinterpret_cast<float4*>(out + idx4) = s;
}

__global__ void aux_kernel(float* __restrict__ out, int out_size) {
    int lane = threadIdx.x;
    float v = (lane < E_NUM) ? g_probs_sum[lane] * (float)g_counts[lane] : 0.f;
    for (int o = 16; o; o >>= 1) v += __shfl_xor_sync(0xffffffffu, v, o);
    if (lane == 0 && out_size > T_TOK * D_DIM)
        out[T_TOK * D_DIM] = v / ((float)T_TOK * (float)T_TOK);
}

// ---------------------------------------------------------------
extern "C" void kernel_launch(void* const* d_in, const int* in_sizes, int n_in,
                              void* d_out, int out_size) {
    const float* x     = (const float*)d_in[0];
    const float* Wgate = (const float*)d_in[1];
    const float* Wg    = (const float*)d_in[2];
    const float* Wu    = (const float*)d_in[3];
    const float* Wd    = (const float*)d_in[4];
    float* out = (float*)d_out;

    // Unconditional (idempotent) — no static guards per harness contract.
    cudaFuncSetAttribute(gemm_gateup_mma, cudaFuncAttributeMaxDynamicSharedMemorySize,
                         3 * G1_STAGE * 2);
    cudaFuncSetAttribute(gemm_down_mma, cudaFuncAttributeMaxDynamicSharedMemorySize,
                         3 * G2_STAGE * 2);

    convert_init_kernel<<<2048, 256>>>(x, Wg, Wu, Wd);
    routing_kernel<<<T_TOK / 8, 256>>>(x, Wgate);
    scan_scatter_kernel<<<1, 512>>>();

    dim3 g1(I_DIM / BN, T_TOK / BM, E_NUM);   // (16, 64, 32)
    gemm_gateup_mma<<<g1, 256, 3 * G1_STAGE * 2>>>();

    dim3 g2(D_DIM / BN, T_TOK / BM, E_NUM);   // (32, 64, 32)
    gemm_down_mma<<<g2, 256, 3 * G2_STAGE * 2>>>();

    combine_kernel<<<(T_TOK * D_DIM / 4) / 256, 256>>>(out);
    aux_kernel<<<1, 32>>>(out, out_size);
}

// round 11
// speedup vs baseline: 5.8832x; 1.1542x over previous
#include <cuda_runtime.h>
#include <cuda_fp16.h>
#include <math.h>
#include <stdint.h>

#define T_TOK 8192
#define D_DIM 2048
#define I_DIM 1024
#define E_NUM 32
#define K_TOP 8
#define P_NUM (T_TOK * K_TOP)

#define BM 128
#define BN 64
#define KB 32
#define A_STRIDE 40   // fp16 elems per A smem row (32 + 8 pad)
#define B_STRIDE 72   // fp16 elems per B smem row (64 + 8 pad)

#define ST_A (BM * A_STRIDE)           // 5120 elems
#define ST_B (KB * B_STRIDE)           // 2304 elems
#define G1_STAGE (2 * ST_A + 2 * ST_B) // 14848 elems (29696 B)
#define G2_STAGE (ST_A + ST_B)         // 7424 elems  (14848 B)
#define S1 (D_DIM / KB)   // 64
#define S2 (I_DIM / KB)   // 32

// ---- scratch (static device globals; no runtime allocation) ----
__device__ __half g_x_hi[(size_t)T_TOK * D_DIM];
__device__ __half g_x_lo[(size_t)T_TOK * D_DIM];
__device__ __half g_wg[(size_t)E_NUM * D_DIM * I_DIM];   // single fp16 (rounded)
__device__ __half g_wu[(size_t)E_NUM * D_DIM * I_DIM];
__device__ __half g_wd[(size_t)E_NUM * I_DIM * D_DIM];
__device__ __half g_h[(size_t)P_NUM * I_DIM];            // single fp16 (rounded)
__device__ float g_op[(size_t)P_NUM * D_DIM];
__device__ float g_pair_w[P_NUM];
__device__ int   g_pair_e[P_NUM];
__device__ int   g_counts[E_NUM];
__device__ int   g_offsets[E_NUM + 1];
__device__ int   g_cursor[E_NUM];
__device__ float g_probs_sum[E_NUM];
__device__ int   g_list[P_NUM];

// ---- PTX helpers ----
#define LDSM_X4(R0,R1,R2,R3,ADDR) \
    asm volatile("ldmatrix.sync.aligned.m8n8.x4.shared.b16 {%0,%1,%2,%3}, [%4];" \
        : "=r"(R0),"=r"(R1),"=r"(R2),"=r"(R3) : "r"(ADDR))
#define LDSM_X4T(R0,R1,R2,R3,ADDR) \
    asm volatile("ldmatrix.sync.aligned.m8n8.x4.trans.shared.b16 {%0,%1,%2,%3}, [%4];" \
        : "=r"(R0),"=r"(R1),"=r"(R2),"=r"(R3) : "r"(ADDR))
#define MMA_F16(C,A0,A1,A2,A3,B0,B1) \
    asm volatile("mma.sync.aligned.m16n8k16.row.col.f32.f16.f16.f32 " \
        "{%0,%1,%2,%3},{%4,%5,%6,%7},{%8,%9},{%0,%1,%2,%3};" \
        : "+f"((C)[0]),"+f"((C)[1]),"+f"((C)[2]),"+f"((C)[3]) \
        : "r"(A0),"r"(A1),"r"(A2),"r"(A3),"r"(B0),"r"(B1))
#define CP16(dst, srcp) asm volatile("cp.async.cg.shared.global [%0], [%1], 16;" :: "r"(dst), "l"(srcp))
#define CP_COMMIT() asm volatile("cp.async.commit_group;" ::: "memory")
#define CP_WAIT1()  asm volatile("cp.async.wait_group 1;" ::: "memory")
#define CP_WAIT0()  asm volatile("cp.async.wait_group 0;" ::: "memory")

__device__ __forceinline__ uint32_t smem_u32(const void* p) {
    return (uint32_t)__cvta_generic_to_shared(p);
}
// split two fp32 into fp16 hi/lo pairs (hi packs, lo packs)
__device__ __forceinline__ void split_pack2h(float a, float b, unsigned &hi, unsigned &lo) {
    __half ha = __float2half_rn(a), hb = __float2half_rn(b);
    float ra = a - __half2float(ha);
    float rb = b - __half2float(hb);
    __half2 hh = __halves2half2(ha, hb);
    __half2 ll = __halves2half2(__float2half_rn(ra), __float2half_rn(rb));
    hi = *reinterpret_cast<unsigned*>(&hh);
    lo = *reinterpret_cast<unsigned*>(&ll);
}
__device__ __forceinline__ unsigned round_pack2h(float a, float b) {
    __half2 hh = __halves2half2(__float2half_rn(a), __float2half_rn(b));
    return *reinterpret_cast<unsigned*>(&hh);
}

// ---------------------------------------------------------------
// Launch #1: init router state + convert: x -> fp16 hi/lo split, W -> single fp16.
__global__ void convert_init_kernel(const float* __restrict__ x,
                                    const float* __restrict__ Wg,
                                    const float* __restrict__ Wu,
                                    const float* __restrict__ Wd) {
    if (blockIdx.x == 0 && threadIdx.x < E_NUM) {
        g_counts[threadIdx.x] = 0;
        g_probs_sum[threadIdx.x] = 0.f;
    }
    const size_t QX = (size_t)T_TOK * D_DIM / 4;
    const size_t QW = (size_t)E_NUM * D_DIM * I_DIM / 4;
    const size_t total = QX + 3 * QW;
    size_t q = (size_t)blockIdx.x * blockDim.x + threadIdx.x;
    size_t step = (size_t)gridDim.x * blockDim.x;
    for (; q < total; q += step) {
        if (q < QX) {
            float4 f = reinterpret_cast<const float4*>(x)[q];
            uint2 H, L;
            split_pack2h(f.x, f.y, H.x, L.x);
            split_pack2h(f.z, f.w, H.y, L.y);
            reinterpret_cast<uint2*>(g_x_hi)[q] = H;
            reinterpret_cast<uint2*>(g_x_lo)[q] = L;
        } else {
            const float* src; __half* dst; size_t i = q - QX;
            if (i < QW)            { src = Wg; dst = g_wg; }
            else if (i < 2 * QW)   { src = Wu; dst = g_wu; i -= QW; }
            else                   { src = Wd; dst = g_wd; i -= 2 * QW; }
            float4 f = reinterpret_cast<const float4*>(src)[i];
            uint2 H;
            H.x = round_pack2h(f.x, f.y);
            H.y = round_pack2h(f.z, f.w);
            reinterpret_cast<uint2*>(dst)[i] = H;
        }
    }
}

// Launch #2: one warp per token; lane == expert (E == 32). (fp32, exact routing)
__global__ void routing_kernel(const float* __restrict__ x,
                               const float* __restrict__ Wgate) {
    int gwarp = (blockIdx.x * blockDim.x + threadIdx.x) >> 5;
    int lane  = threadIdx.x & 31;
    if (gwarp >= T_TOK) return;

    const float4* xr4 = reinterpret_cast<const float4*>(x + (size_t)gwarp * D_DIM);
    float acc = 0.f;
#pragma unroll 2
    for (int d4 = 0; d4 < D_DIM / 4; d4++) {
        float4 xv = xr4[d4];
        int d = d4 * 4;
        acc += xv.x * Wgate[(d + 0) * E_NUM + lane];
        acc += xv.y * Wgate[(d + 1) * E_NUM + lane];
        acc += xv.z * Wgate[(d + 2) * E_NUM + lane];
        acc += xv.w * Wgate[(d + 3) * E_NUM + lane];
    }

    float m = acc;
    for (int o = 16; o; o >>= 1) m = fmaxf(m, __shfl_xor_sync(0xffffffffu, m, o));
    float pe = expf(acc - m);
    float s = pe;
    for (int o = 16; o; o >>= 1) s += __shfl_xor_sync(0xffffffffu, s, o);
    atomicAdd(&g_probs_sum[lane], pe / s);

    float v = acc;
    float selv = 0.f; int seli = 0;
#pragma unroll
    for (int k = 0; k < K_TOP; k++) {
        float mv = v;
        for (int o = 16; o; o >>= 1) mv = fmaxf(mv, __shfl_xor_sync(0xffffffffu, mv, o));
        unsigned b = __ballot_sync(0xffffffffu, v == mv);
        int src = __ffs(b) - 1;
        if (lane == k)   { selv = mv; seli = src; }
        if (lane == src) v = -INFINITY;
    }

    float top0 = __shfl_sync(0xffffffffu, selv, 0);
    float ev = (lane < K_TOP) ? expf(selv - top0) : 0.f;
    float es = ev;
    for (int o = 16; o; o >>= 1) es += __shfl_xor_sync(0xffffffffu, es, o);

    if (lane < K_TOP) {
        int p = gwarp * K_TOP + lane;
        g_pair_w[p] = ev / es;
        g_pair_e[p] = seli;
        atomicAdd(&g_counts[seli], 1);
    }
}

// Launch #3: scan + scatter fused (single block).
__global__ void scan_scatter_kernel() {
    int tid = threadIdx.x;
    if (tid < 32) {
        int c = g_counts[tid];
        int v = c;
        for (int o = 1; o < 32; o <<= 1) {
            int n = __shfl_up_sync(0xffffffffu, v, o);
            if (tid >= o) v += n;
        }
        int excl = v - c;
        g_offsets[tid] = excl;
        if (tid == 31) g_offsets[32] = v;
        g_cursor[tid] = excl;
    }
    __syncthreads();
    for (int p = tid; p < P_NUM; p += blockDim.x) {
        int e = g_pair_e[p];
        int pos = atomicAdd(&g_cursor[e], 1);
        g_list[pos] = p;
    }
}

// ---- cp.async stage loaders ----
__device__ __forceinline__ void g1_load(int tid, int k0, __half* st,
                                        const int* sT,
                                        const __half* bg, const __half* bu) {
#pragma unroll
    for (int i = 0; i < 2; i++) {
        int q = tid + i * 256;
        int r = q >> 2, c = (q & 3) * 8;
        size_t so = (size_t)sT[r] * D_DIM + k0 + c;
        uint32_t d = smem_u32(st + r * A_STRIDE + c);
        CP16(d, g_x_hi + so);
        CP16(d + ST_A * 2, g_x_lo + so);
    }
    {
        int r = tid >> 3, c = (tid & 7) * 8;
        size_t so = (size_t)(k0 + r) * I_DIM + c;   // caller pre-offsets by colBase
        uint32_t d = smem_u32(st + 2 * ST_A + r * B_STRIDE + c);
        CP16(d,            bg + so);
        CP16(d + ST_B * 2, bu + so);
    }
    CP_COMMIT();
}

__device__ __forceinline__ void g2_load(int tid, int k0, __half* st,
                                        const int* sPp,
                                        const __half* bd) {
#pragma unroll
    for (int i = 0; i < 2; i++) {
        int q = tid + i * 256;
        int r = q >> 2, c = (q & 3) * 8;
        size_t so = (size_t)sPp[r] * I_DIM + k0 + c;
        CP16(smem_u32(st + r * A_STRIDE + c), g_h + so);
    }
    {
        int r = tid >> 3, c = (tid & 7) * 8;
        size_t so = (size_t)(k0 + r) * D_DIM + c;   // caller pre-offsets by colBase
        CP16(smem_u32(st + ST_A + r * B_STRIDE + c), bd + so);
    }
    CP_COMMIT();
}

// ---- Launch #4: grouped GEMM1 (fp16x2, cp.async 3-buffer, single sync/stage) ----
// D = (x_hi + x_lo) @ fp16(W) ; activation split exact, weight rounding ~2^-12.
__global__ __launch_bounds__(256, 2) void gemm_gateup_mma() {
    extern __shared__ __half dyn[];
    int e = blockIdx.z;
    int start = g_offsets[e], end = g_offsets[e + 1];
    int rowBase = start + blockIdx.y * BM;
    if (rowBase >= end) return;
    int nRows = min(BM, end - rowBase);
    int colBase = blockIdx.x * BN;  // over I

    __shared__ int   sP[BM];
    __shared__ int   sT[BM];
    __shared__ float sW[BM];

    int tid = threadIdx.x, lane = tid & 31, warp = tid >> 5;
    int wm = (warp & 3) * 32, wn = (warp >> 2) * 32;

    if (tid < BM) {
        int p = g_list[rowBase + min(tid, nRows - 1)];
        sP[tid] = p; sT[tid] = p >> 3; sW[tid] = g_pair_w[p];
    }
    __syncthreads();

    const __half* bg = g_wg + (size_t)e * D_DIM * I_DIM + colBase;
    const __half* bu = g_wu + (size_t)e * D_DIM * I_DIM + colBase;

    int arow = lane & 15, ahalf = (lane >> 4) * 8;
    int bk   = ((lane >> 3) & 1) * 8 + (lane & 7);
    int bn   = wn + (lane >> 4) * 8;

    float cg[2][4][4] = {}, cu[2][4][4] = {};

    g1_load(tid, 0, dyn, sT, bg, bu);
    g1_load(tid, KB, dyn + G1_STAGE, sT, bg, bu);

#pragma unroll 3
    for (int s = 0; s < S1; s++) {
        // mid-loop: a later group exists -> WAIT1 proves group s done; last: WAIT0.
        if (s + 1 < S1) { CP_WAIT1(); } else { CP_WAIT0(); }
        __syncthreads();   // publishes stage s; proves stage s-1 reads done
        if (s + 2 < S1)
            g1_load(tid, (s + 2) * KB, dyn + ((s + 2) % 3) * G1_STAGE, sT, bg, bu);

        __half* st = dyn + (s % 3) * G1_STAGE;
        uint32_t sA_u = smem_u32(st);
        uint32_t sB_u = smem_u32(st + 2 * ST_A);

#pragma unroll
        for (int ks = 0; ks < 2; ks++) {
            unsigned ah[2][4], al[2][4];
#pragma unroll
            for (int mt = 0; mt < 2; mt++) {
                unsigned off = (unsigned)(((wm + mt * 16 + arow) * A_STRIDE + ks * 16 + ahalf) * 2);
                LDSM_X4(ah[mt][0], ah[mt][1], ah[mt][2], ah[mt][3], sA_u + off);
                LDSM_X4(al[mt][0], al[mt][1], al[mt][2], al[mt][3], sA_u + ST_A * 2 + off);
            }
            unsigned boff0 = (unsigned)((((ks * 16 + bk) * B_STRIDE) + bn) * 2);
#pragma unroll
            for (int np = 0; np < 2; np++) {
                unsigned boff = boff0 + np * 32;
                unsigned b0,b1,b2,b3;
                LDSM_X4T(b0,b1,b2,b3, sB_u + boff);
#pragma unroll
                for (int mt = 0; mt < 2; mt++) {
                    MMA_F16(cg[mt][2*np],   ah[mt][0],ah[mt][1],ah[mt][2],ah[mt][3], b0,b1);
                    MMA_F16(cg[mt][2*np],   al[mt][0],al[mt][1],al[mt][2],al[mt][3], b0,b1);
                    MMA_F16(cg[mt][2*np+1], ah[mt][0],ah[mt][1],ah[mt][2],ah[mt][3], b2,b3);
                    MMA_F16(cg[mt][2*np+1], al[mt][0],al[mt][1],al[mt][2],al[mt][3], b2,b3);
                }
            }
#pragma unroll
            for (int np = 0; np < 2; np++) {
                unsigned boff = boff0 + np * 32;
                unsigned b0,b1,b2,b3;
                LDSM_X4T(b0,b1,b2,b3, sB_u + ST_B * 2 + boff);
#pragma unroll
                for (int mt = 0; mt < 2; mt++) {
                    MMA_F16(cu[mt][2*np],   ah[mt][0],ah[mt][1],ah[mt][2],ah[mt][3], b0,b1);
                    MMA_F16(cu[mt][2*np],   al[mt][0],al[mt][1],al[mt][2],al[mt][3], b0,b1);
                    MMA_F16(cu[mt][2*np+1], ah[mt][0],ah[mt][1],ah[mt][2],ah[mt][3], b2,b3);
                    MMA_F16(cu[mt][2*np+1], al[mt][0],al[mt][1],al[mt][2],al[mt][3], b2,b3);
                }
            }
        }
    }

    // epilogue: v = w * silu(gate) * up -> single fp16 (h already noise-floored
    // by weight rounding; exact split is precision below the noise)
#pragma unroll
    for (int mt = 0; mt < 2; mt++)
#pragma unroll
    for (int half = 0; half < 2; half++) {
        int lr = wm + mt * 16 + (lane >> 2) + half * 8;
        if (lr < nRows) {
            int p = sP[lr]; float w = sW[lr];
            size_t base = (size_t)p * I_DIM;
#pragma unroll
            for (int nt = 0; nt < 4; nt++) {
                int col = colBase + wn + nt * 8 + (lane & 3) * 2;
                float z0 = cg[mt][nt][half*2], z1 = cg[mt][nt][half*2+1];
                float u0 = cu[mt][nt][half*2], u1 = cu[mt][nt][half*2+1];
                float v0 = w * u0 * z0 / (1.f + expf(-z0));
                float v1 = w * u1 * z1 / (1.f + expf(-z1));
                *reinterpret_cast<unsigned*>(g_h + base + col) = round_pack2h(v0, v1);
            }
        }
    }
}

// ---- Launch #5: grouped GEMM2 (fp16x1, cp.async 3-buffer, single sync/stage) ----
__global__ __launch_bounds__(256, 2) void gemm_down_mma() {
    extern __shared__ __half dyn[];
    int e = blockIdx.z;
    int start = g_offsets[e], end = g_offsets[e + 1];
    int rowBase = start + blockIdx.y * BM;
    if (rowBase >= end) return;
    int nRows = min(BM, end - rowBase);
    int colBase = blockIdx.x * BN;  // over D

    __shared__ int sP[BM];

    int tid = threadIdx.x, lane = tid & 31, warp = tid >> 5;
    int wm = (warp & 3) * 32, wn = (warp >> 2) * 32;

    if (tid < BM) sP[tid] = g_list[rowBase + min(tid, nRows - 1)];
    __syncthreads();

    const __half* bd = g_wd + (size_t)e * I_DIM * D_DIM + colBase;

    int arow = lane & 15, ahalf = (lane >> 4) * 8;
    int bk = ((lane >> 3) & 1) * 8 + (lane & 7);
    int bn = wn + (lane >> 4) * 8;

    float cc[2][4][4] = {};

    g2_load(tid, 0, dyn, sP, bd);
    g2_load(tid, KB, dyn + G2_STAGE, sP, bd);

#pragma unroll 3
    for (int s = 0; s < S2; s++) {
        if (s + 1 < S2) { CP_WAIT1(); } else { CP_WAIT0(); }
        __syncthreads();
        if (s + 2 < S2)
            g2_load(tid, (s + 2) * KB, dyn + ((s + 2) % 3) * G2_STAGE, sP, bd);

        __half* st = dyn + (s % 3) * G2_STAGE;
        uint32_t sA_u = smem_u32(st);
        uint32_t sB_u = smem_u32(st + ST_A);

#pragma unroll
        for (int ks = 0; ks < 2; ks++) {
            unsigned ah[2][4];
#pragma unroll
            for (int mt = 0; mt < 2; mt++) {
                unsigned off = (unsigned)(((wm + mt * 16 + arow) * A_STRIDE + ks * 16 + ahalf) * 2);
                LDSM_X4(ah[mt][0], ah[mt][1], ah[mt][2], ah[mt][3], sA_u + off);
            }
            unsigned boff0 = (unsigned)((((ks * 16 + bk) * B_STRIDE) + bn) * 2);
#pragma unroll
            for (int np = 0; np < 2; np++) {
                unsigned boff = boff0 + np * 32;
                unsigned b0,b1,b2,b3;
                LDSM_X4T(b0,b1,b2,b3, sB_u + boff);
#pragma unroll
                for (int mt = 0; mt < 2; mt++) {
                    MMA_F16(cc[mt][2*np],   ah[mt][0],ah[mt][1],ah[mt][2],ah[mt][3], b0,b1);
                    MMA_F16(cc[mt][2*np+1], ah[mt][0],ah[mt][1],ah[mt][2],ah[mt][3], b2,b3);
                }
            }
        }
    }

#pragma unroll
    for (int mt = 0; mt < 2; mt++)
#pragma unroll
    for (int half = 0; half < 2; half++) {
        int lr = wm + mt * 16 + (lane >> 2) + half * 8;
        if (lr < nRows) {
            int p = sP[lr];
            size_t base = (size_t)p * D_DIM;
#pragma unroll
            for (int nt = 0; nt < 4; nt++) {
                int col = colBase + wn + nt * 8 + (lane & 3) * 2;
                float2 v = make_float2(cc[mt][nt][half*2], cc[mt][nt][half*2+1]);
                *reinterpret_cast<float2*>(g_op + base + col) = v;
            }
        }
    }
}

// ---- combine: out[t] = sum over the token's 8 pairs (atomic-free) ----
__global__ void combine_kernel(float* __restrict__ out) {
    int idx = blockIdx.x * blockDim.x + threadIdx.x;
    int idx4 = idx * 4;
    if (idx4 >= T_TOK * D_DIM) return;
    int t = idx4 >> 11;
    int d = idx4 & (D_DIM - 1);
    float4 s = make_float4(0.f, 0.f, 0.f, 0.f);
#pragma unroll
    for (int k = 0; k < K_TOP; k++) {
        const float4 v = *reinterpret_cast<const float4*>(
            g_op + ((size_t)(t * K_TOP + k)) * D_DIM + d);
        s.x += v.x; s.y += v.y; s.z += v.z; s.w += v.w;
    }
    *reinterpret_cast<float4*>(out + idx4) = s;
}

__global__ void aux_kernel(float* __restrict__ out, int out_size) {
    int lane = threadIdx.x;
    float v = (lane < E_NUM) ? g_probs_sum[lane] * (float)g_counts[lane] : 0.f;
    for (int o = 16; o; o >>= 1) v += __shfl_xor_sync(0xffffffffu, v, o);
    if (lane == 0 && out_size > T_TOK * D_DIM)
        out[T_TOK * D_DIM] = v / ((float)T_TOK * (float)T_TOK);
}

// ---------------------------------------------------------------
extern "C" void kernel_launch(void* const* d_in, const int* in_sizes, int n_in,
                              void* d_out, int out_size) {
    const float* x     = (const float*)d_in[0];
    const float* Wgate = (const float*)d_in[1];
    const float* Wg    = (const float*)d_in[2];
    const float* Wu    = (const float*)d_in[3];
    const float* Wd    = (const float*)d_in[4];
    float* out = (float*)d_out;

    // Unconditional (idempotent) — no static guards per harness contract.
    cudaFuncSetAttribute(gemm_gateup_mma, cudaFuncAttributeMaxDynamicSharedMemorySize,
                         3 * G1_STAGE * 2);
    cudaFuncSetAttribute(gemm_down_mma, cudaFuncAttributeMaxDynamicSharedMemorySize,
                         3 * G2_STAGE * 2);

    convert_init_kernel<<<2048, 256>>>(x, Wg, Wu, Wd);
    routing_kernel<<<T_TOK / 8, 256>>>(x, Wgate);
    scan_scatter_kernel<<<1, 512>>>();

    dim3 g1(I_DIM / BN, T_TOK / BM, E_NUM);   // (16, 64, 32)
    gemm_gateup_mma<<<g1, 256, 3 * G1_STAGE * 2>>>();

    dim3 g2(D_DIM / BN, T_TOK / BM, E_NUM);   // (32, 64, 32)
    gemm_down_mma<<<g2, 256, 3 * G2_STAGE * 2>>>();

    combine_kernel<<<(T_TOK * D_DIM / 4) / 256, 256>>>(out);
    aux_kernel<<<1, 32>>>(out, out_size);
}

// round 12
// speedup vs baseline: 8.2822x; 1.4078x over previous
#include <cuda_runtime.h>
#include <cuda_fp16.h>
#include <math.h>
#include <stdint.h>

#define T_TOK 8192
#define D_DIM 2048
#define I_DIM 1024
#define E_NUM 32
#define K_TOP 8
#define P_NUM (T_TOK * K_TOP)

#define BM 128
#define BN 64
#define KB 32
#define A_STRIDE 40   // fp16 elems per A smem row (32 + 8 pad)
#define B_STRIDE 72   // fp16 elems per B smem row (64 + 8 pad)

#define ST_A (BM * A_STRIDE)           // 5120 elems
#define ST_B (KB * B_STRIDE)           // 2304 elems
#define G1_STAGE (ST_A + 2 * ST_B)     // 9728 elems  (19456 B)
#define G2_STAGE (ST_A + ST_B)         // 7424 elems  (14848 B)
#define S1 (D_DIM / KB)   // 64
#define S2 (I_DIM / KB)   // 32

// ---- scratch (static device globals; no runtime allocation) ----
__device__ __half g_x[(size_t)T_TOK * D_DIM];            // single fp16 (rounded)
__device__ __half g_wg[(size_t)E_NUM * D_DIM * I_DIM];   // single fp16 (rounded)
__device__ __half g_wu[(size_t)E_NUM * D_DIM * I_DIM];
__device__ __half g_wd[(size_t)E_NUM * I_DIM * D_DIM];
__device__ __half g_h[(size_t)P_NUM * I_DIM];            // single fp16 (rounded)
__device__ float g_op[(size_t)P_NUM * D_DIM];
__device__ float g_pair_w[P_NUM];
__device__ int   g_pair_e[P_NUM];
__device__ int   g_counts[E_NUM];
__device__ int   g_offsets[E_NUM + 1];
__device__ int   g_cursor[E_NUM];
__device__ float g_probs_sum[E_NUM];
__device__ int   g_list[P_NUM];

// ---- PTX helpers ----
#define LDSM_X4(R0,R1,R2,R3,ADDR) \
    asm volatile("ldmatrix.sync.aligned.m8n8.x4.shared.b16 {%0,%1,%2,%3}, [%4];" \
        : "=r"(R0),"=r"(R1),"=r"(R2),"=r"(R3) : "r"(ADDR))
#define LDSM_X4T(R0,R1,R2,R3,ADDR) \
    asm volatile("ldmatrix.sync.aligned.m8n8.x4.trans.shared.b16 {%0,%1,%2,%3}, [%4];" \
        : "=r"(R0),"=r"(R1),"=r"(R2),"=r"(R3) : "r"(ADDR))
#define MMA_F16(C,A0,A1,A2,A3,B0,B1) \
    asm volatile("mma.sync.aligned.m16n8k16.row.col.f32.f16.f16.f32 " \
        "{%0,%1,%2,%3},{%4,%5,%6,%7},{%8,%9},{%0,%1,%2,%3};" \
        : "+f"((C)[0]),"+f"((C)[1]),"+f"((C)[2]),"+f"((C)[3]) \
        : "r"(A0),"r"(A1),"r"(A2),"r"(A3),"r"(B0),"r"(B1))
#define CP16(dst, srcp) asm volatile("cp.async.cg.shared.global [%0], [%1], 16;" :: "r"(dst), "l"(srcp))
#define CP_COMMIT() asm volatile("cp.async.commit_group;" ::: "memory")
#define CP_WAIT1()  asm volatile("cp.async.wait_group 1;" ::: "memory")
#define CP_WAIT0()  asm volatile("cp.async.wait_group 0;" ::: "memory")

__device__ __forceinline__ uint32_t smem_u32(const void* p) {
    return (uint32_t)__cvta_generic_to_shared(p);
}
__device__ __forceinline__ unsigned round_pack2h(float a, float b) {
    __half2 hh = __halves2half2(__float2half_rn(a), __float2half_rn(b));
    return *reinterpret_cast<unsigned*>(&hh);
}

// ---------------------------------------------------------------
// Launch #1: init router state + convert x, Wg, Wu, Wd -> single fp16.
__global__ void convert_init_kernel(const float* __restrict__ x,
                                    const float* __restrict__ Wg,
                                    const float* __restrict__ Wu,
                                    const float* __restrict__ Wd) {
    if (blockIdx.x == 0 && threadIdx.x < E_NUM) {
        g_counts[threadIdx.x] = 0;
        g_probs_sum[threadIdx.x] = 0.f;
    }
    const size_t QX = (size_t)T_TOK * D_DIM / 4;
    const size_t QW = (size_t)E_NUM * D_DIM * I_DIM / 4;
    const size_t total = QX + 3 * QW;
    size_t q = (size_t)blockIdx.x * blockDim.x + threadIdx.x;
    size_t step = (size_t)gridDim.x * blockDim.x;
    for (; q < total; q += step) {
        const float* src; __half* dst; size_t i;
        if (q < QX)               { src = x;  dst = g_x;  i = q; }
        else if (q < QX + QW)     { src = Wg; dst = g_wg; i = q - QX; }
        else if (q < QX + 2 * QW) { src = Wu; dst = g_wu; i = q - QX - QW; }
        else                      { src = Wd; dst = g_wd; i = q - QX - 2 * QW; }
        float4 f = reinterpret_cast<const float4*>(src)[i];
        uint2 H;
        H.x = round_pack2h(f.x, f.y);
        H.y = round_pack2h(f.z, f.w);
        reinterpret_cast<uint2*>(dst)[i] = H;
    }
}

// Launch #2: one warp per token; lane == expert (E == 32). (fp32, exact routing)
__global__ void routing_kernel(const float* __restrict__ x,
                               const float* __restrict__ Wgate) {
    int gwarp = (blockIdx.x * blockDim.x + threadIdx.x) >> 5;
    int lane  = threadIdx.x & 31;
    if (gwarp >= T_TOK) return;

    const float4* xr4 = reinterpret_cast<const float4*>(x + (size_t)gwarp * D_DIM);
    float acc = 0.f;
#pragma unroll 2
    for (int d4 = 0; d4 < D_DIM / 4; d4++) {
        float4 xv = xr4[d4];
        int d = d4 * 4;
        acc += xv.x * Wgate[(d + 0) * E_NUM + lane];
        acc += xv.y * Wgate[(d + 1) * E_NUM + lane];
        acc += xv.z * Wgate[(d + 2) * E_NUM + lane];
        acc += xv.w * Wgate[(d + 3) * E_NUM + lane];
    }

    float m = acc;
    for (int o = 16; o; o >>= 1) m = fmaxf(m, __shfl_xor_sync(0xffffffffu, m, o));
    float pe = expf(acc - m);
    float s = pe;
    for (int o = 16; o; o >>= 1) s += __shfl_xor_sync(0xffffffffu, s, o);
    atomicAdd(&g_probs_sum[lane], pe / s);

    float v = acc;
    float selv = 0.f; int seli = 0;
#pragma unroll
    for (int k = 0; k < K_TOP; k++) {
        float mv = v;
        for (int o = 16; o; o >>= 1) mv = fmaxf(mv, __shfl_xor_sync(0xffffffffu, mv, o));
        unsigned b = __ballot_sync(0xffffffffu, v == mv);
        int src = __ffs(b) - 1;
        if (lane == k)   { selv = mv; seli = src; }
        if (lane == src) v = -INFINITY;
    }

    float top0 = __shfl_sync(0xffffffffu, selv, 0);
    float ev = (lane < K_TOP) ? expf(selv - top0) : 0.f;
    float es = ev;
    for (int o = 16; o; o >>= 1) es += __shfl_xor_sync(0xffffffffu, es, o);

    if (lane < K_TOP) {
        int p = gwarp * K_TOP + lane;
        g_pair_w[p] = ev / es;
        g_pair_e[p] = seli;
        atomicAdd(&g_counts[seli], 1);
    }
}

// Launch #3: scan + scatter fused (single block).
__global__ void scan_scatter_kernel() {
    int tid = threadIdx.x;
    if (tid < 32) {
        int c = g_counts[tid];
        int v = c;
        for (int o = 1; o < 32; o <<= 1) {
            int n = __shfl_up_sync(0xffffffffu, v, o);
            if (tid >= o) v += n;
        }
        int excl = v - c;
        g_offsets[tid] = excl;
        if (tid == 31) g_offsets[32] = v;
        g_cursor[tid] = excl;
    }
    __syncthreads();
    for (int p = tid; p < P_NUM; p += blockDim.x) {
        int e = g_pair_e[p];
        int pos = atomicAdd(&g_cursor[e], 1);
        g_list[pos] = p;
    }
}

// ---- cp.async stage loaders ----
__device__ __forceinline__ void g1_load(int tid, int k0, __half* st,
                                        const int* sT,
                                        const __half* bg, const __half* bu) {
#pragma unroll
    for (int i = 0; i < 2; i++) {
        int q = tid + i * 256;
        int r = q >> 2, c = (q & 3) * 8;
        size_t so = (size_t)sT[r] * D_DIM + k0 + c;
        CP16(smem_u32(st + r * A_STRIDE + c), g_x + so);
    }
    {
        int r = tid >> 3, c = (tid & 7) * 8;
        size_t so = (size_t)(k0 + r) * I_DIM + c;   // caller pre-offsets by colBase
        uint32_t d = smem_u32(st + ST_A + r * B_STRIDE + c);
        CP16(d,            bg + so);
        CP16(d + ST_B * 2, bu + so);
    }
    CP_COMMIT();
}

__device__ __forceinline__ void g2_load(int tid, int k0, __half* st,
                                        const int* sPp,
                                        const __half* bd) {
#pragma unroll
    for (int i = 0; i < 2; i++) {
        int q = tid + i * 256;
        int r = q >> 2, c = (q & 3) * 8;
        size_t so = (size_t)sPp[r] * I_DIM + k0 + c;
        CP16(smem_u32(st + r * A_STRIDE + c), g_h + so);
    }
    {
        int r = tid >> 3, c = (tid & 7) * 8;
        size_t so = (size_t)(k0 + r) * D_DIM + c;   // caller pre-offsets by colBase
        CP16(smem_u32(st + ST_A + r * B_STRIDE + c), bd + so);
    }
    CP_COMMIT();
}

// ---- Launch #4: grouped GEMM1 (fp16x1, cp.async 3-buffer, single sync/stage) ----
__global__ __launch_bounds__(256, 2) void gemm_gateup_mma() {
    extern __shared__ __half dyn[];
    int e = blockIdx.z;
    int start = g_offsets[e], end = g_offsets[e + 1];
    int rowBase = start + blockIdx.y * BM;
    if (rowBase >= end) return;
    int nRows = min(BM, end - rowBase);
    int colBase = blockIdx.x * BN;  // over I

    __shared__ int   sP[BM];
    __shared__ int   sT[BM];
    __shared__ float sW[BM];

    int tid = threadIdx.x, lane = tid & 31, warp = tid >> 5;
    int wm = (warp & 3) * 32, wn = (warp >> 2) * 32;

    if (tid < BM) {
        int p = g_list[rowBase + min(tid, nRows - 1)];
        sP[tid] = p; sT[tid] = p >> 3; sW[tid] = g_pair_w[p];
    }
    __syncthreads();

    const __half* bg = g_wg + (size_t)e * D_DIM * I_DIM + colBase;
    const __half* bu = g_wu + (size_t)e * D_DIM * I_DIM + colBase;

    int arow = lane & 15, ahalf = (lane >> 4) * 8;
    int bk   = ((lane >> 3) & 1) * 8 + (lane & 7);
    int bn   = wn + (lane >> 4) * 8;

    float cg[2][4][4] = {}, cu[2][4][4] = {};

    g1_load(tid, 0, dyn, sT, bg, bu);
    g1_load(tid, KB, dyn + G1_STAGE, sT, bg, bu);

#pragma unroll 3
    for (int s = 0; s < S1; s++) {
        // mid-loop: a later group exists -> WAIT1 proves group s done; last: WAIT0.
        if (s + 1 < S1) { CP_WAIT1(); } else { CP_WAIT0(); }
        __syncthreads();   // publishes stage s; proves stage s-1 reads done
        if (s + 2 < S1)
            g1_load(tid, (s + 2) * KB, dyn + ((s + 2) % 3) * G1_STAGE, sT, bg, bu);

        __half* st = dyn + (s % 3) * G1_STAGE;
        uint32_t sA_u = smem_u32(st);
        uint32_t sB_u = smem_u32(st + ST_A);

#pragma unroll
        for (int ks = 0; ks < 2; ks++) {
            unsigned ah[2][4];
#pragma unroll
            for (int mt = 0; mt < 2; mt++) {
                unsigned off = (unsigned)(((wm + mt * 16 + arow) * A_STRIDE + ks * 16 + ahalf) * 2);
                LDSM_X4(ah[mt][0], ah[mt][1], ah[mt][2], ah[mt][3], sA_u + off);
            }
            unsigned boff0 = (unsigned)((((ks * 16 + bk) * B_STRIDE) + bn) * 2);
#pragma unroll
            for (int np = 0; np < 2; np++) {
                unsigned boff = boff0 + np * 32;
                unsigned b0,b1,b2,b3;
                LDSM_X4T(b0,b1,b2,b3, sB_u + boff);
#pragma unroll
                for (int mt = 0; mt < 2; mt++) {
                    MMA_F16(cg[mt][2*np],   ah[mt][0],ah[mt][1],ah[mt][2],ah[mt][3], b0,b1);
                    MMA_F16(cg[mt][2*np+1], ah[mt][0],ah[mt][1],ah[mt][2],ah[mt][3], b2,b3);
                }
            }
#pragma unroll
            for (int np = 0; np < 2; np++) {
                unsigned boff = boff0 + np * 32;
                unsigned b0,b1,b2,b3;
                LDSM_X4T(b0,b1,b2,b3, sB_u + ST_B * 2 + boff);
#pragma unroll
                for (int mt = 0; mt < 2; mt++) {
                    MMA_F16(cu[mt][2*np],   ah[mt][0],ah[mt][1],ah[mt][2],ah[mt][3], b0,b1);
                    MMA_F16(cu[mt][2*np+1], ah[mt][0],ah[mt][1],ah[mt][2],ah[mt][3], b2,b3);
                }
            }
        }
    }

    // epilogue: v = w * silu(gate) * up -> single fp16
#pragma unroll
    for (int mt = 0; mt < 2; mt++)
#pragma unroll
    for (int half = 0; half < 2; half++) {
        int lr = wm + mt * 16 + (lane >> 2) + half * 8;
        if (lr < nRows) {
            int p = sP[lr]; float w = sW[lr];
            size_t base = (size_t)p * I_DIM;
#pragma unroll
            for (int nt = 0; nt < 4; nt++) {
                int col = colBase + wn + nt * 8 + (lane & 3) * 2;
                float z0 = cg[mt][nt][half*2], z1 = cg[mt][nt][half*2+1];
                float u0 = cu[mt][nt][half*2], u1 = cu[mt][nt][half*2+1];
                float v0 = w * u0 * z0 / (1.f + expf(-z0));
                float v1 = w * u1 * z1 / (1.f + expf(-z1));
                *reinterpret_cast<unsigned*>(g_h + base + col) = round_pack2h(v0, v1);
            }
        }
    }
}

// ---- Launch #5: grouped GEMM2 (fp16x1, cp.async 3-buffer, single sync/stage) ----
__global__ __launch_bounds__(256, 2) void gemm_down_mma() {
    extern __shared__ __half dyn[];
    int e = blockIdx.z;
    int start = g_offsets[e], end = g_offsets[e + 1];
    int rowBase = start + blockIdx.y * BM;
    if (rowBase >= end) return;
    int nRows = min(BM, end - rowBase);
    int colBase = blockIdx.x * BN;  // over D

    __shared__ int sP[BM];

    int tid = threadIdx.x, lane = tid & 31, warp = tid >> 5;
    int wm = (warp & 3) * 32, wn = (warp >> 2) * 32;

    if (tid < BM) sP[tid] = g_list[rowBase + min(tid, nRows - 1)];
    __syncthreads();

    const __half* bd = g_wd + (size_t)e * I_DIM * D_DIM + colBase;

    int arow = lane & 15, ahalf = (lane >> 4) * 8;
    int bk = ((lane >> 3) & 1) * 8 + (lane & 7);
    int bn = wn + (lane >> 4) * 8;

    float cc[2][4][4] = {};

    g2_load(tid, 0, dyn, sP, bd);
    g2_load(tid, KB, dyn + G2_STAGE, sP, bd);

#pragma unroll 3
    for (int s = 0; s < S2; s++) {
        if (s + 1 < S2) { CP_WAIT1(); } else { CP_WAIT0(); }
        __syncthreads();
        if (s + 2 < S2)
            g2_load(tid, (s + 2) * KB, dyn + ((s + 2) % 3) * G2_STAGE, sP, bd);

        __half* st = dyn + (s % 3) * G2_STAGE;
        uint32_t sA_u = smem_u32(st);
        uint32_t sB_u = smem_u32(st + ST_A);

#pragma unroll
        for (int ks = 0; ks < 2; ks++) {
            unsigned ah[2][4];
#pragma unroll
            for (int mt = 0; mt < 2; mt++) {
                unsigned off = (unsigned)(((wm + mt * 16 + arow) * A_STRIDE + ks * 16 + ahalf) * 2);
                LDSM_X4(ah[mt][0], ah[mt][1], ah[mt][2], ah[mt][3], sA_u + off);
            }
            unsigned boff0 = (unsigned)((((ks * 16 + bk) * B_STRIDE) + bn) * 2);
#pragma unroll
            for (int np = 0; np < 2; np++) {
                unsigned boff = boff0 + np * 32;
                unsigned b0,b1,b2,b3;
                LDSM_X4T(b0,b1,b2,b3, sB_u + boff);
#pragma unroll
                for (int mt = 0; mt < 2; mt++) {
                    MMA_F16(cc[mt][2*np],   ah[mt][0],ah[mt][1],ah[mt][2],ah[mt][3], b0,b1);
                    MMA_F16(cc[mt][2*np+1], ah[mt][0],ah[mt][1],ah[mt][2],ah[mt][3], b2,b3);
                }
            }
        }
    }

#pragma unroll
    for (int mt = 0; mt < 2; mt++)
#pragma unroll
    for (int half = 0; half < 2; half++) {
        int lr = wm + mt * 16 + (lane >> 2) + half * 8;
        if (lr < nRows) {
            int p = sP[lr];
            size_t base = (size_t)p * D_DIM;
#pragma unroll
            for (int nt = 0; nt < 4; nt++) {
                int col = colBase + wn + nt * 8 + (lane & 3) * 2;
                float2 v = make_float2(cc[mt][nt][half*2], cc[mt][nt][half*2+1]);
                *reinterpret_cast<float2*>(g_op + base + col) = v;
            }
        }
    }
}

// ---- combine: out[t] = sum over the token's 8 pairs (atomic-free) ----
__global__ void combine_kernel(float* __restrict__ out) {
    int idx = blockIdx.x * blockDim.x + threadIdx.x;
    int idx4 = idx * 4;
    if (idx4 >= T_TOK * D_DIM) return;
    int t = idx4 >> 11;
    int d = idx4 & (D_DIM - 1);
    float4 s = make_float4(0.f, 0.f, 0.f, 0.f);
#pragma unroll
    for (int k = 0; k < K_TOP; k++) {
        const float4 v = *reinterpret_cast<const float4*>(
            g_op + ((size_t)(t * K_TOP + k)) * D_DIM + d);
        s.x += v.x; s.y += v.y; s.z += v.z; s.w += v.w;
    }
    *reinterpret_cast<float4*>(out + idx4) = s;
}

__global__ void aux_kernel(float* __restrict__ out, int out_size) {
    int lane = threadIdx.x;
    float v = (lane < E_NUM) ? g_probs_sum[lane] * (float)g_counts[lane] : 0.f;
    for (int o = 16; o; o >>= 1) v += __shfl_xor_sync(0xffffffffu, v, o);
    if (lane == 0 && out_size > T_TOK * D_DIM)
        out[T_TOK * D_DIM] = v / ((float)T_TOK * (float)T_TOK);
}

// ---------------------------------------------------------------
extern "C" void kernel_launch(void* const* d_in, const int* in_sizes, int n_in,
                              void* d_out, int out_size) {
    const float* x     = (const float*)d_in[0];
    const float* Wgate = (const float*)d_in[1];
    const float* Wg    = (const float*)d_in[2];
    const float* Wu    = (const float*)d_in[3];
    const float* Wd    = (const float*)d_in[4];
    float* out = (float*)d_out;

    // Unconditional (idempotent) — no static guards per harness contract.
    cudaFuncSetAttribute(gemm_gateup_mma, cudaFuncAttributeMaxDynamicSharedMemorySize,
                         3 * G1_STAGE * 2);
    cudaFuncSetAttribute(gemm_down_mma, cudaFuncAttributeMaxDynamicSharedMemorySize,
                         3 * G2_STAGE * 2);

    convert_init_kernel<<<2048, 256>>>(x, Wg, Wu, Wd);
    routing_kernel<<<T_TOK / 8, 256>>>(x, Wgate);
    scan_scatter_kernel<<<1, 512>>>();

    dim3 g1(I_DIM / BN, T_TOK / BM, E_NUM);   // (16, 64, 32)
    gemm_gateup_mma<<<g1, 256, 3 * G1_STAGE * 2>>>();

    dim3 g2(D_DIM / BN, T_TOK / BM, E_NUM);   // (32, 64, 32)
    gemm_down_mma<<<g2, 256, 3 * G2_STAGE * 2>>>();

    combine_kernel<<<(T_TOK * D_DIM / 4) / 256, 256>>>(out);
    aux_kernel<<<1, 32>>>(out, out_size);
}

// round 13
// speedup vs baseline: 8.6657x; 1.0463x over previous
#include <cuda_runtime.h>
#include <cuda_fp16.h>
#include <math.h>
#include <stdint.h>

#define T_TOK 8192
#define D_DIM 2048
#define I_DIM 1024
#define E_NUM 32
#define K_TOP 8
#define P_NUM (T_TOK * K_TOP)

#define BM 128
#define BN 64
#define KB 32
#define A_STRIDE 40   // fp16 elems per A smem row (32 + 8 pad)
#define B_STRIDE 72   // fp16 elems per B smem row (64 + 8 pad)

#define ST_A (BM * A_STRIDE)           // 5120 elems
#define ST_B (KB * B_STRIDE)           // 2304 elems
#define G1_STAGE (ST_A + 2 * ST_B)     // 9728 elems  (19456 B)
#define G2_STAGE (ST_A + ST_B)         // 7424 elems  (14848 B)
#define S1 (D_DIM / KB)   // 64
#define S2 (I_DIM / KB)   // 32

// ---- scratch (static device globals; no runtime allocation) ----
__device__ __half g_x[(size_t)T_TOK * D_DIM];            // single fp16 (rounded)
__device__ __half g_wg[(size_t)E_NUM * D_DIM * I_DIM];   // single fp16 (rounded)
__device__ __half g_wu[(size_t)E_NUM * D_DIM * I_DIM];
__device__ __half g_wd[(size_t)E_NUM * I_DIM * D_DIM];
__device__ __half g_h[(size_t)P_NUM * I_DIM];            // single fp16 (rounded)
__device__ __half g_op[(size_t)P_NUM * D_DIM];           // fp16 partials
__device__ float g_pair_w[P_NUM];
__device__ int   g_pair_e[P_NUM];
__device__ int   g_counts[E_NUM];
__device__ int   g_offsets[E_NUM + 1];
__device__ int   g_cursor[E_NUM];
__device__ float g_probs_sum[E_NUM];
__device__ int   g_list[P_NUM];

// ---- PTX helpers ----
#define LDSM_X4(R0,R1,R2,R3,ADDR) \
    asm volatile("ldmatrix.sync.aligned.m8n8.x4.shared.b16 {%0,%1,%2,%3}, [%4];" \
        : "=r"(R0),"=r"(R1),"=r"(R2),"=r"(R3) : "r"(ADDR))
#define LDSM_X4T(R0,R1,R2,R3,ADDR) \
    asm volatile("ldmatrix.sync.aligned.m8n8.x4.trans.shared.b16 {%0,%1,%2,%3}, [%4];" \
        : "=r"(R0),"=r"(R1),"=r"(R2),"=r"(R3) : "r"(ADDR))
#define MMA_F16(C,A0,A1,A2,A3,B0,B1) \
    asm volatile("mma.sync.aligned.m16n8k16.row.col.f32.f16.f16.f32 " \
        "{%0,%1,%2,%3},{%4,%5,%6,%7},{%8,%9},{%0,%1,%2,%3};" \
        : "+f"((C)[0]),"+f"((C)[1]),"+f"((C)[2]),"+f"((C)[3]) \
        : "r"(A0),"r"(A1),"r"(A2),"r"(A3),"r"(B0),"r"(B1))
#define CP16(dst, srcp) asm volatile("cp.async.cg.shared.global [%0], [%1], 16;" :: "r"(dst), "l"(srcp))
#define CP_COMMIT() asm volatile("cp.async.commit_group;" ::: "memory")
#define CP_WAIT2()  asm volatile("cp.async.wait_group 2;" ::: "memory")
#define CP_WAIT1()  asm volatile("cp.async.wait_group 1;" ::: "memory")
#define CP_WAIT0()  asm volatile("cp.async.wait_group 0;" ::: "memory")

__device__ __forceinline__ uint32_t smem_u32(const void* p) {
    return (uint32_t)__cvta_generic_to_shared(p);
}
__device__ __forceinline__ unsigned round_pack2h(float a, float b) {
    __half2 hh = __halves2half2(__float2half_rn(a), __float2half_rn(b));
    return *reinterpret_cast<unsigned*>(&hh);
}

// ---------------------------------------------------------------
// Launch #1: init router state + convert x, Wg, Wu, Wd -> single fp16.
__global__ void convert_init_kernel(const float* __restrict__ x,
                                    const float* __restrict__ Wg,
                                    const float* __restrict__ Wu,
                                    const float* __restrict__ Wd) {
    if (blockIdx.x == 0 && threadIdx.x < E_NUM) {
        g_counts[threadIdx.x] = 0;
        g_probs_sum[threadIdx.x] = 0.f;
    }
    const size_t QX = (size_t)T_TOK * D_DIM / 4;
    const size_t QW = (size_t)E_NUM * D_DIM * I_DIM / 4;
    const size_t total = QX + 3 * QW;
    size_t q = (size_t)blockIdx.x * blockDim.x + threadIdx.x;
    size_t step = (size_t)gridDim.x * blockDim.x;
    for (; q < total; q += step) {
        const float* src; __half* dst; size_t i;
        if (q < QX)               { src = x;  dst = g_x;  i = q; }
        else if (q < QX + QW)     { src = Wg; dst = g_wg; i = q - QX; }
        else if (q < QX + 2 * QW) { src = Wu; dst = g_wu; i = q - QX - QW; }
        else                      { src = Wd; dst = g_wd; i = q - QX - 2 * QW; }
        float4 f = reinterpret_cast<const float4*>(src)[i];
        uint2 H;
        H.x = round_pack2h(f.x, f.y);
        H.y = round_pack2h(f.z, f.w);
        reinterpret_cast<uint2*>(dst)[i] = H;
    }
}

// Launch #2: one warp per token; lane == expert (E == 32). (fp32, exact routing)
__global__ void routing_kernel(const float* __restrict__ x,
                               const float* __restrict__ Wgate) {
    int gwarp = (blockIdx.x * blockDim.x + threadIdx.x) >> 5;
    int lane  = threadIdx.x & 31;
    if (gwarp >= T_TOK) return;

    const float4* xr4 = reinterpret_cast<const float4*>(x + (size_t)gwarp * D_DIM);
    float a0 = 0.f, a1 = 0.f, a2 = 0.f, a3 = 0.f;
#pragma unroll 2
    for (int d4 = 0; d4 < D_DIM / 4; d4++) {
        float4 xv = xr4[d4];
        int d = d4 * 4;
        a0 += xv.x * Wgate[(d + 0) * E_NUM + lane];
        a1 += xv.y * Wgate[(d + 1) * E_NUM + lane];
        a2 += xv.z * Wgate[(d + 2) * E_NUM + lane];
        a3 += xv.w * Wgate[(d + 3) * E_NUM + lane];
    }
    float acc = (a0 + a1) + (a2 + a3);

    float m = acc;
    for (int o = 16; o; o >>= 1) m = fmaxf(m, __shfl_xor_sync(0xffffffffu, m, o));
    float pe = expf(acc - m);
    float s = pe;
    for (int o = 16; o; o >>= 1) s += __shfl_xor_sync(0xffffffffu, s, o);
    atomicAdd(&g_probs_sum[lane], pe / s);

    float v = acc;
    float selv = 0.f; int seli = 0;
#pragma unroll
    for (int k = 0; k < K_TOP; k++) {
        float mv = v;
        for (int o = 16; o; o >>= 1) mv = fmaxf(mv, __shfl_xor_sync(0xffffffffu, mv, o));
        unsigned b = __ballot_sync(0xffffffffu, v == mv);
        int src = __ffs(b) - 1;
        if (lane == k)   { selv = mv; seli = src; }
        if (lane == src) v = -INFINITY;
    }

    float top0 = __shfl_sync(0xffffffffu, selv, 0);
    float ev = (lane < K_TOP) ? expf(selv - top0) : 0.f;
    float es = ev;
    for (int o = 16; o; o >>= 1) es += __shfl_xor_sync(0xffffffffu, es, o);

    if (lane < K_TOP) {
        int p = gwarp * K_TOP + lane;
        g_pair_w[p] = ev / es;
        g_pair_e[p] = seli;
        atomicAdd(&g_counts[seli], 1);
    }
}

// Launch #3: scan (single warp).
__global__ void scan_kernel() {
    int lane = threadIdx.x;
    int c = g_counts[lane];
    int v = c;
    for (int o = 1; o < 32; o <<= 1) {
        int n = __shfl_up_sync(0xffffffffu, v, o);
        if (lane >= o) v += n;
    }
    int excl = v - c;
    g_offsets[lane] = excl;
    if (lane == 31) g_offsets[32] = v;
    g_cursor[lane] = excl;
}

// Launch #4: scatter (grid-wide; g_list order is schedule-dependent but every
// per-row result and the combine read locations are fixed -> output bits deterministic).
__global__ void scatter_kernel() {
    int p = blockIdx.x * blockDim.x + threadIdx.x;
    if (p >= P_NUM) return;
    int e = g_pair_e[p];
    int pos = atomicAdd(&g_cursor[e], 1);
    g_list[pos] = p;
}

// ---- cp.async stage loaders ----
__device__ __forceinline__ void g1_load(int tid, int k0, __half* st,
                                        const int* sT,
                                        const __half* bg, const __half* bu) {
#pragma unroll
    for (int i = 0; i < 2; i++) {
        int q = tid + i * 256;
        int r = q >> 2, c = (q & 3) * 8;
        size_t so = (size_t)sT[r] * D_DIM + k0 + c;
        CP16(smem_u32(st + r * A_STRIDE + c), g_x + so);
    }
    {
        int r = tid >> 3, c = (tid & 7) * 8;
        size_t so = (size_t)(k0 + r) * I_DIM + c;   // caller pre-offsets by colBase
        uint32_t d = smem_u32(st + ST_A + r * B_STRIDE + c);
        CP16(d,            bg + so);
        CP16(d + ST_B * 2, bu + so);
    }
    CP_COMMIT();
}

__device__ __forceinline__ void g2_load(int tid, int k0, __half* st,
                                        const int* sPp,
                                        const __half* bd) {
#pragma unroll
    for (int i = 0; i < 2; i++) {
        int q = tid + i * 256;
        int r = q >> 2, c = (q & 3) * 8;
        size_t so = (size_t)sPp[r] * I_DIM + k0 + c;
        CP16(smem_u32(st + r * A_STRIDE + c), g_h + so);
    }
    {
        int r = tid >> 3, c = (tid & 7) * 8;
        size_t so = (size_t)(k0 + r) * D_DIM + c;   // caller pre-offsets by colBase
        CP16(smem_u32(st + ST_A + r * B_STRIDE + c), bd + so);
    }
    CP_COMMIT();
}

// guarantee group s has completed: wait until outstanding <= (#groups committed after s)
#define STAGE_WAIT(s, S) do { \
    if ((s) + 2 < (S))      { CP_WAIT2(); } \
    else if ((s) + 1 < (S)) { CP_WAIT1(); } \
    else                    { CP_WAIT0(); } \
} while (0)

// ---- Launch #5: grouped GEMM1 (fp16x1, cp.async 4-buffer, single sync/stage) ----
__global__ __launch_bounds__(256, 2) void gemm_gateup_mma() {
    extern __shared__ __half dyn[];
    int e = blockIdx.z;
    int start = g_offsets[e], end = g_offsets[e + 1];
    int rowBase = start + blockIdx.y * BM;
    if (rowBase >= end) return;
    int nRows = min(BM, end - rowBase);
    int colBase = blockIdx.x * BN;  // over I

    __shared__ int   sP[BM];
    __shared__ int   sT[BM];
    __shared__ float sW[BM];

    int tid = threadIdx.x, lane = tid & 31, warp = tid >> 5;
    int wm = (warp & 3) * 32, wn = (warp >> 2) * 32;

    if (tid < BM) {
        int p = g_list[rowBase + min(tid, nRows - 1)];
        sP[tid] = p; sT[tid] = p >> 3; sW[tid] = g_pair_w[p];
    }
    __syncthreads();

    const __half* bg = g_wg + (size_t)e * D_DIM * I_DIM + colBase;
    const __half* bu = g_wu + (size_t)e * D_DIM * I_DIM + colBase;

    int arow = lane & 15, ahalf = (lane >> 4) * 8;
    int bk   = ((lane >> 3) & 1) * 8 + (lane & 7);
    int bn   = wn + (lane >> 4) * 8;

    float cg[2][4][4] = {}, cu[2][4][4] = {};

    g1_load(tid, 0, dyn, sT, bg, bu);
    g1_load(tid, KB, dyn + G1_STAGE, sT, bg, bu);
    g1_load(tid, 2 * KB, dyn + 2 * G1_STAGE, sT, bg, bu);

#pragma unroll 4
    for (int s = 0; s < S1; s++) {
        STAGE_WAIT(s, S1);
        __syncthreads();   // publishes stage s; proves stage s-1 reads done
        if (s + 3 < S1)
            g1_load(tid, (s + 3) * KB, dyn + ((s + 3) & 3) * G1_STAGE, sT, bg, bu);

        __half* st = dyn + (s & 3) * G1_STAGE;
        uint32_t sA_u = smem_u32(st);
        uint32_t sB_u = smem_u32(st + ST_A);

#pragma unroll
        for (int ks = 0; ks < 2; ks++) {
            unsigned ah[2][4];
#pragma unroll
            for (int mt = 0; mt < 2; mt++) {
                unsigned off = (unsigned)(((wm + mt * 16 + arow) * A_STRIDE + ks * 16 + ahalf) * 2);
                LDSM_X4(ah[mt][0], ah[mt][1], ah[mt][2], ah[mt][3], sA_u + off);
            }
            unsigned boff0 = (unsigned)((((ks * 16 + bk) * B_STRIDE) + bn) * 2);
#pragma unroll
            for (int np = 0; np < 2; np++) {
                unsigned boff = boff0 + np * 32;
                unsigned b0,b1,b2,b3;
                LDSM_X4T(b0,b1,b2,b3, sB_u + boff);
#pragma unroll
                for (int mt = 0; mt < 2; mt++) {
                    MMA_F16(cg[mt][2*np],   ah[mt][0],ah[mt][1],ah[mt][2],ah[mt][3], b0,b1);
                    MMA_F16(cg[mt][2*np+1], ah[mt][0],ah[mt][1],ah[mt][2],ah[mt][3], b2,b3);
                }
            }
#pragma unroll
            for (int np = 0; np < 2; np++) {
                unsigned boff = boff0 + np * 32;
                unsigned b0,b1,b2,b3;
                LDSM_X4T(b0,b1,b2,b3, sB_u + ST_B * 2 + boff);
#pragma unroll
                for (int mt = 0; mt < 2; mt++) {
                    MMA_F16(cu[mt][2*np],   ah[mt][0],ah[mt][1],ah[mt][2],ah[mt][3], b0,b1);
                    MMA_F16(cu[mt][2*np+1], ah[mt][0],ah[mt][1],ah[mt][2],ah[mt][3], b2,b3);
                }
            }
        }
    }

    // epilogue: v = w * silu(gate) * up -> single fp16
#pragma unroll
    for (int mt = 0; mt < 2; mt++)
#pragma unroll
    for (int half = 0; half < 2; half++) {
        int lr = wm + mt * 16 + (lane >> 2) + half * 8;
        if (lr < nRows) {
            int p = sP[lr]; float w = sW[lr];
            size_t base = (size_t)p * I_DIM;
#pragma unroll
            for (int nt = 0; nt < 4; nt++) {
                int col = colBase + wn + nt * 8 + (lane & 3) * 2;
                float z0 = cg[mt][nt][half*2], z1 = cg[mt][nt][half*2+1];
                float u0 = cu[mt][nt][half*2], u1 = cu[mt][nt][half*2+1];
                float v0 = w * u0 * z0 / (1.f + expf(-z0));
                float v1 = w * u1 * z1 / (1.f + expf(-z1));
                *reinterpret_cast<unsigned*>(g_h + base + col) = round_pack2h(v0, v1);
            }
        }
    }
}

// ---- Launch #6: grouped GEMM2 (fp16x1, cp.async 4-buffer, single sync/stage) ----
__global__ __launch_bounds__(256, 2) void gemm_down_mma() {
    extern __shared__ __half dyn[];
    int e = blockIdx.z;
    int start = g_offsets[e], end = g_offsets[e + 1];
    int rowBase = start + blockIdx.y * BM;
    if (rowBase >= end) return;
    int nRows = min(BM, end - rowBase);
    int colBase = blockIdx.x * BN;  // over D

    __shared__ int sP[BM];

    int tid = threadIdx.x, lane = tid & 31, warp = tid >> 5;
    int wm = (warp & 3) * 32, wn = (warp >> 2) * 32;

    if (tid < BM) sP[tid] = g_list[rowBase + min(tid, nRows - 1)];
    __syncthreads();

    const __half* bd = g_wd + (size_t)e * I_DIM * D_DIM + colBase;

    int arow = lane & 15, ahalf = (lane >> 4) * 8;
    int bk = ((lane >> 3) & 1) * 8 + (lane & 7);
    int bn = wn + (lane >> 4) * 8;

    float cc[2][4][4] = {};

    g2_load(tid, 0, dyn, sP, bd);
    g2_load(tid, KB, dyn + G2_STAGE, sP, bd);
    g2_load(tid, 2 * KB, dyn + 2 * G2_STAGE, sP, bd);

#pragma unroll 4
    for (int s = 0; s < S2; s++) {
        STAGE_WAIT(s, S2);
        __syncthreads();
        if (s + 3 < S2)
            g2_load(tid, (s + 3) * KB, dyn + ((s + 3) & 3) * G2_STAGE, sP, bd);

        __half* st = dyn + (s & 3) * G2_STAGE;
        uint32_t sA_u = smem_u32(st);
        uint32_t sB_u = smem_u32(st + ST_A);

#pragma unroll
        for (int ks = 0; ks < 2; ks++) {
            unsigned ah[2][4];
#pragma unroll
            for (int mt = 0; mt < 2; mt++) {
                unsigned off = (unsigned)(((wm + mt * 16 + arow) * A_STRIDE + ks * 16 + ahalf) * 2);
                LDSM_X4(ah[mt][0], ah[mt][1], ah[mt][2], ah[mt][3], sA_u + off);
            }
            unsigned boff0 = (unsigned)((((ks * 16 + bk) * B_STRIDE) + bn) * 2);
#pragma unroll
            for (int np = 0; np < 2; np++) {
                unsigned boff = boff0 + np * 32;
                unsigned b0,b1,b2,b3;
                LDSM_X4T(b0,b1,b2,b3, sB_u + boff);
#pragma unroll
                for (int mt = 0; mt < 2; mt++) {
                    MMA_F16(cc[mt][2*np],   ah[mt][0],ah[mt][1],ah[mt][2],ah[mt][3], b0,b1);
                    MMA_F16(cc[mt][2*np+1], ah[mt][0],ah[mt][1],ah[mt][2],ah[mt][3], b2,b3);
                }
            }
        }
    }

#pragma unroll
    for (int mt = 0; mt < 2; mt++)
#pragma unroll
    for (int half = 0; half < 2; half++) {
        int lr = wm + mt * 16 + (lane >> 2) + half * 8;
        if (lr < nRows) {
            int p = sP[lr];
            size_t base = (size_t)p * D_DIM;
#pragma unroll
            for (int nt = 0; nt < 4; nt++) {
                int col = colBase + wn + nt * 8 + (lane & 3) * 2;
                *reinterpret_cast<unsigned*>(g_op + base + col) =
                    round_pack2h(cc[mt][nt][half*2], cc[mt][nt][half*2+1]);
            }
        }
    }
}

// ---- combine: out[t] = sum over the token's 8 pairs (atomic-free, fp32 sum of fp16 partials) ----
__global__ void combine_kernel(float* __restrict__ out) {
    int idx = blockIdx.x * blockDim.x + threadIdx.x;
    int idx4 = idx * 4;
    if (idx4 >= T_TOK * D_DIM) return;
    int t = idx4 >> 11;
    int d = idx4 & (D_DIM - 1);
    float4 s = make_float4(0.f, 0.f, 0.f, 0.f);
#pragma unroll
    for (int k = 0; k < K_TOP; k++) {
        uint2 v = *reinterpret_cast<const uint2*>(
            g_op + ((size_t)(t * K_TOP + k)) * D_DIM + d);
        __half2 h01 = *reinterpret_cast<__half2*>(&v.x);
        __half2 h23 = *reinterpret_cast<__half2*>(&v.y);
        float2 f01 = __half22float2(h01);
        float2 f23 = __half22float2(h23);
        s.x += f01.x; s.y += f01.y; s.z += f23.x; s.w += f23.y;
    }
    *reinterpret_cast<float4*>(out + idx4) = s;
}

__global__ void aux_kernel(float* __restrict__ out, int out_size) {
    int lane = threadIdx.x;
    float v = (lane < E_NUM) ? g_probs_sum[lane] * (float)g_counts[lane] : 0.f;
    for (int o = 16; o; o >>= 1) v += __shfl_xor_sync(0xffffffffu, v, o);
    if (lane == 0 && out_size > T_TOK * D_DIM)
        out[T_TOK * D_DIM] = v / ((float)T_TOK * (float)T_TOK);
}

// ---------------------------------------------------------------
extern "C" void kernel_launch(void* const* d_in, const int* in_sizes, int n_in,
                              void* d_out, int out_size) {
    const float* x     = (const float*)d_in[0];
    const float* Wgate = (const float*)d_in[1];
    const float* Wg    = (const float*)d_in[2];
    const float* Wu    = (const float*)d_in[3];
    const float* Wd    = (const float*)d_in[4];
    float* out = (float*)d_out;

    // Unconditional (idempotent) — no static guards per harness contract.
    cudaFuncSetAttribute(gemm_gateup_mma, cudaFuncAttributeMaxDynamicSharedMemorySize,
                         4 * G1_STAGE * 2);
    cudaFuncSetAttribute(gemm_down_mma, cudaFuncAttributeMaxDynamicSharedMemorySize,
                         4 * G2_STAGE * 2);

    convert_init_kernel<<<4096, 256>>>(x, Wg, Wu, Wd);
    routing_kernel<<<T_TOK / 8, 256>>>(x, Wgate);
    scan_kernel<<<1, 32>>>();
    scatter_kernel<<<P_NUM / 256, 256>>>();

    dim3 g1(I_DIM / BN, T_TOK / BM, E_NUM);   // (16, 64, 32)
    gemm_gateup_mma<<<g1, 256, 4 * G1_STAGE * 2>>>();

    dim3 g2(D_DIM / BN, T_TOK / BM, E_NUM);   // (32, 64, 32)
    gemm_down_mma<<<g2, 256, 4 * G2_STAGE * 2>>>();

    combine_kernel<<<(T_TOK * D_DIM / 4) / 256, 256>>>(out);
    aux_kernel<<<1, 32>>>(out, out_size);
}

// round 14
// speedup vs baseline: 8.9231x; 1.0297x over previous
#include <cuda_runtime.h>
#include <cuda_fp16.h>
#include <math.h>
#include <stdint.h>

#define T_TOK 8192
#define D_DIM 2048
#define I_DIM 1024
#define E_NUM 32
#define K_TOP 8
#define P_NUM (T_TOK * K_TOP)

#define BM 128
#define BN 64
#define KB 64
#define A_STRIDE 72   // fp16 elems per A smem row (64 + 8 pad) -> 144B, conflict-free LDSM
#define B_STRIDE 72   // fp16 elems per B smem row (64 + 8 pad)

#define ST_A (BM * A_STRIDE)           // 9216 elems
#define ST_B (KB * B_STRIDE)           // 4608 elems
#define G1_STAGE (ST_A + 2 * ST_B)     // 18432 elems (36864 B)
#define G2_STAGE (ST_A + ST_B)         // 13824 elems (27648 B)
#define S1 (D_DIM / KB)   // 32
#define S2 (I_DIM / KB)   // 16

// ---- scratch (static device globals; no runtime allocation) ----
__device__ __half g_x[(size_t)T_TOK * D_DIM];            // single fp16 (rounded)
__device__ __half g_wg[(size_t)E_NUM * D_DIM * I_DIM];   // single fp16 (rounded)
__device__ __half g_wu[(size_t)E_NUM * D_DIM * I_DIM];
__device__ __half g_wd[(size_t)E_NUM * I_DIM * D_DIM];
__device__ __half g_h[(size_t)P_NUM * I_DIM];            // single fp16 (rounded)
__device__ __half g_op[(size_t)P_NUM * D_DIM];           // fp16 partials
__device__ float g_pair_w[P_NUM];
__device__ int   g_pair_e[P_NUM];
__device__ int   g_counts[E_NUM];
__device__ int   g_offsets[E_NUM + 1];
__device__ int   g_cursor[E_NUM];
__device__ float g_probs_sum[E_NUM];
__device__ int   g_list[P_NUM];

// ---- PTX helpers ----
#define LDSM_X4(R0,R1,R2,R3,ADDR) \
    asm volatile("ldmatrix.sync.aligned.m8n8.x4.shared.b16 {%0,%1,%2,%3}, [%4];" \
        : "=r"(R0),"=r"(R1),"=r"(R2),"=r"(R3) : "r"(ADDR))
#define LDSM_X4T(R0,R1,R2,R3,ADDR) \
    asm volatile("ldmatrix.sync.aligned.m8n8.x4.trans.shared.b16 {%0,%1,%2,%3}, [%4];" \
        : "=r"(R0),"=r"(R1),"=r"(R2),"=r"(R3) : "r"(ADDR))
#define MMA_F16(C,A0,A1,A2,A3,B0,B1) \
    asm volatile("mma.sync.aligned.m16n8k16.row.col.f32.f16.f16.f32 " \
        "{%0,%1,%2,%3},{%4,%5,%6,%7},{%8,%9},{%0,%1,%2,%3};" \
        : "+f"((C)[0]),"+f"((C)[1]),"+f"((C)[2]),"+f"((C)[3]) \
        : "r"(A0),"r"(A1),"r"(A2),"r"(A3),"r"(B0),"r"(B1))
#define CP16(dst, srcp) asm volatile("cp.async.cg.shared.global [%0], [%1], 16;" :: "r"(dst), "l"(srcp))
#define CP_COMMIT() asm volatile("cp.async.commit_group;" ::: "memory")
#define CP_WAIT1()  asm volatile("cp.async.wait_group 1;" ::: "memory")
#define CP_WAIT0()  asm volatile("cp.async.wait_group 0;" ::: "memory")

__device__ __forceinline__ uint32_t smem_u32(const void* p) {
    return (uint32_t)__cvta_generic_to_shared(p);
}
__device__ __forceinline__ unsigned round_pack2h(float a, float b) {
    __half2 hh = __halves2half2(__float2half_rn(a), __float2half_rn(b));
    return *reinterpret_cast<unsigned*>(&hh);
}

// ---------------------------------------------------------------
// Launch #1: init router state + convert x, Wg, Wu, Wd -> single fp16.
__global__ void convert_init_kernel(const float* __restrict__ x,
                                    const float* __restrict__ Wg,
                                    const float* __restrict__ Wu,
                                    const float* __restrict__ Wd) {
    if (blockIdx.x == 0 && threadIdx.x < E_NUM) {
        g_counts[threadIdx.x] = 0;
        g_probs_sum[threadIdx.x] = 0.f;
    }
    const size_t QX = (size_t)T_TOK * D_DIM / 4;
    const size_t QW = (size_t)E_NUM * D_DIM * I_DIM / 4;
    const size_t total = QX + 3 * QW;
    size_t q = (size_t)blockIdx.x * blockDim.x + threadIdx.x;
    size_t step = (size_t)gridDim.x * blockDim.x;
    for (; q < total; q += step) {
        const float* src; __half* dst; size_t i;
        if (q < QX)               { src = x;  dst = g_x;  i = q; }
        else if (q < QX + QW)     { src = Wg; dst = g_wg; i = q - QX; }
        else if (q < QX + 2 * QW) { src = Wu; dst = g_wu; i = q - QX - QW; }
        else                      { src = Wd; dst = g_wd; i = q - QX - 2 * QW; }
        float4 f = reinterpret_cast<const float4*>(src)[i];
        uint2 H;
        H.x = round_pack2h(f.x, f.y);
        H.y = round_pack2h(f.z, f.w);
        reinterpret_cast<uint2*>(dst)[i] = H;
    }
}

// Launch #2: one warp per token; lane == expert (E == 32). (fp32, exact routing)
__global__ void routing_kernel(const float* __restrict__ x,
                               const float* __restrict__ Wgate) {
    int gwarp = (blockIdx.x * blockDim.x + threadIdx.x) >> 5;
    int lane  = threadIdx.x & 31;
    if (gwarp >= T_TOK) return;

    const float4* xr4 = reinterpret_cast<const float4*>(x + (size_t)gwarp * D_DIM);
    float a0 = 0.f, a1 = 0.f, a2 = 0.f, a3 = 0.f;
#pragma unroll 2
    for (int d4 = 0; d4 < D_DIM / 4; d4++) {
        float4 xv = xr4[d4];
        int d = d4 * 4;
        a0 += xv.x * Wgate[(d + 0) * E_NUM + lane];
        a1 += xv.y * Wgate[(d + 1) * E_NUM + lane];
        a2 += xv.z * Wgate[(d + 2) * E_NUM + lane];
        a3 += xv.w * Wgate[(d + 3) * E_NUM + lane];
    }
    float acc = (a0 + a1) + (a2 + a3);

    float m = acc;
    for (int o = 16; o; o >>= 1) m = fmaxf(m, __shfl_xor_sync(0xffffffffu, m, o));
    float pe = expf(acc - m);
    float s = pe;
    for (int o = 16; o; o >>= 1) s += __shfl_xor_sync(0xffffffffu, s, o);
    atomicAdd(&g_probs_sum[lane], pe / s);

    float v = acc;
    float selv = 0.f; int seli = 0;
#pragma unroll
    for (int k = 0; k < K_TOP; k++) {
        float mv = v;
        for (int o = 16; o; o >>= 1) mv = fmaxf(mv, __shfl_xor_sync(0xffffffffu, mv, o));
        unsigned b = __ballot_sync(0xffffffffu, v == mv);
        int src = __ffs(b) - 1;
        if (lane == k)   { selv = mv; seli = src; }
        if (lane == src) v = -INFINITY;
    }

    float top0 = __shfl_sync(0xffffffffu, selv, 0);
    float ev = (lane < K_TOP) ? expf(selv - top0) : 0.f;
    float es = ev;
    for (int o = 16; o; o >>= 1) es += __shfl_xor_sync(0xffffffffu, es, o);

    if (lane < K_TOP) {
        int p = gwarp * K_TOP + lane;
        g_pair_w[p] = ev / es;
        g_pair_e[p] = seli;
        atomicAdd(&g_counts[seli], 1);
    }
}

// Launch #3: scan (single warp).
__global__ void scan_kernel() {
    int lane = threadIdx.x;
    int c = g_counts[lane];
    int v = c;
    for (int o = 1; o < 32; o <<= 1) {
        int n = __shfl_up_sync(0xffffffffu, v, o);
        if (lane >= o) v += n;
    }
    int excl = v - c;
    g_offsets[lane] = excl;
    if (lane == 31) g_offsets[32] = v;
    g_cursor[lane] = excl;
}

// Launch #4: scatter (grid-wide; g_list order is schedule-dependent but every
// per-row result and the combine read locations are fixed -> output bits deterministic).
__global__ void scatter_kernel() {
    int p = blockIdx.x * blockDim.x + threadIdx.x;
    if (p >= P_NUM) return;
    int e = g_pair_e[p];
    int pos = atomicAdd(&g_cursor[e], 1);
    g_list[pos] = p;
}

// ---- cp.async stage loaders (KB = 64) ----
__device__ __forceinline__ void g1_load(int tid, int k0, __half* st,
                                        const int* sT,
                                        const __half* bg, const __half* bu) {
#pragma unroll
    for (int i = 0; i < 4; i++) {
        int q = tid + i * 256;
        int r = q >> 3, c = (q & 7) * 8;
        size_t so = (size_t)sT[r] * D_DIM + k0 + c;
        CP16(smem_u32(st + r * A_STRIDE + c), g_x + so);
    }
#pragma unroll
    for (int i = 0; i < 2; i++) {
        int q = tid + i * 256;
        int r = q >> 3, c = (q & 7) * 8;
        size_t so = (size_t)(k0 + r) * I_DIM + c;   // caller pre-offsets by colBase
        uint32_t d = smem_u32(st + ST_A + r * B_STRIDE + c);
        CP16(d,            bg + so);
        CP16(d + ST_B * 2, bu + so);
    }
    CP_COMMIT();
}

__device__ __forceinline__ void g2_load(int tid, int k0, __half* st,
                                        const int* sPp,
                                        const __half* bd) {
#pragma unroll
    for (int i = 0; i < 4; i++) {
        int q = tid + i * 256;
        int r = q >> 3, c = (q & 7) * 8;
        size_t so = (size_t)sPp[r] * I_DIM + k0 + c;
        CP16(smem_u32(st + r * A_STRIDE + c), g_h + so);
    }
#pragma unroll
    for (int i = 0; i < 2; i++) {
        int q = tid + i * 256;
        int r = q >> 3, c = (q & 7) * 8;
        size_t so = (size_t)(k0 + r) * D_DIM + c;   // caller pre-offsets by colBase
        CP16(smem_u32(st + ST_A + r * B_STRIDE + c), bd + so);
    }
    CP_COMMIT();
}

// ---- Launch #5: grouped GEMM1 (fp16x1, KB=64, 3-buffer, single sync/stage) ----
__global__ __launch_bounds__(256, 2) void gemm_gateup_mma() {
    extern __shared__ __half dyn[];
    int e = blockIdx.z;
    int start = g_offsets[e], end = g_offsets[e + 1];
    int rowBase = start + blockIdx.y * BM;
    if (rowBase >= end) return;
    int nRows = min(BM, end - rowBase);
    int colBase = blockIdx.x * BN;  // over I

    __shared__ int   sP[BM];
    __shared__ int   sT[BM];
    __shared__ float sW[BM];

    int tid = threadIdx.x, lane = tid & 31, warp = tid >> 5;
    int wm = (warp & 3) * 32, wn = (warp >> 2) * 32;

    if (tid < BM) {
        int p = g_list[rowBase + min(tid, nRows - 1)];
        sP[tid] = p; sT[tid] = p >> 3; sW[tid] = g_pair_w[p];
    }
    __syncthreads();

    const __half* bg = g_wg + (size_t)e * D_DIM * I_DIM + colBase;
    const __half* bu = g_wu + (size_t)e * D_DIM * I_DIM + colBase;

    int arow = lane & 15, ahalf = (lane >> 4) * 8;
    int bk   = ((lane >> 3) & 1) * 8 + (lane & 7);
    int bn   = wn + (lane >> 4) * 8;

    float cg[2][4][4] = {}, cu[2][4][4] = {};

    g1_load(tid, 0, dyn, sT, bg, bu);
    g1_load(tid, KB, dyn + G1_STAGE, sT, bg, bu);

#pragma unroll 3
    for (int s = 0; s < S1; s++) {
        // in flight: groups s, s+1 -> WAIT1 proves group s done; last: WAIT0.
        if (s + 1 < S1) { CP_WAIT1(); } else { CP_WAIT0(); }
        __syncthreads();   // publishes stage s; proves stage s-1 reads done
        if (s + 2 < S1)
            g1_load(tid, (s + 2) * KB, dyn + ((s + 2) % 3) * G1_STAGE, sT, bg, bu);

        __half* st = dyn + (s % 3) * G1_STAGE;
        uint32_t sA_u = smem_u32(st);
        uint32_t sB_u = smem_u32(st + ST_A);

#pragma unroll
        for (int ks = 0; ks < 4; ks++) {
            unsigned ah[2][4];
#pragma unroll
            for (int mt = 0; mt < 2; mt++) {
                unsigned off = (unsigned)(((wm + mt * 16 + arow) * A_STRIDE + ks * 16 + ahalf) * 2);
                LDSM_X4(ah[mt][0], ah[mt][1], ah[mt][2], ah[mt][3], sA_u + off);
            }
            unsigned boff0 = (unsigned)((((ks * 16 + bk) * B_STRIDE) + bn) * 2);
#pragma unroll
            for (int np = 0; np < 2; np++) {
                unsigned boff = boff0 + np * 32;
                unsigned b0,b1,b2,b3;
                LDSM_X4T(b0,b1,b2,b3, sB_u + boff);
#pragma unroll
                for (int mt = 0; mt < 2; mt++) {
                    MMA_F16(cg[mt][2*np],   ah[mt][0],ah[mt][1],ah[mt][2],ah[mt][3], b0,b1);
                    MMA_F16(cg[mt][2*np+1], ah[mt][0],ah[mt][1],ah[mt][2],ah[mt][3], b2,b3);
                }
            }
#pragma unroll
            for (int np = 0; np < 2; np++) {
                unsigned boff = boff0 + np * 32;
                unsigned b0,b1,b2,b3;
                LDSM_X4T(b0,b1,b2,b3, sB_u + ST_B * 2 + boff);
#pragma unroll
                for (int mt = 0; mt < 2; mt++) {
                    MMA_F16(cu[mt][2*np],   ah[mt][0],ah[mt][1],ah[mt][2],ah[mt][3], b0,b1);
                    MMA_F16(cu[mt][2*np+1], ah[mt][0],ah[mt][1],ah[mt][2],ah[mt][3], b2,b3);
                }
            }
        }
    }

    // epilogue: v = w * silu(gate) * up -> single fp16
#pragma unroll
    for (int mt = 0; mt < 2; mt++)
#pragma unroll
    for (int half = 0; half < 2; half++) {
        int lr = wm + mt * 16 + (lane >> 2) + half * 8;
        if (lr < nRows) {
            int p = sP[lr]; float w = sW[lr];
            size_t base = (size_t)p * I_DIM;
#pragma unroll
            for (int nt = 0; nt < 4; nt++) {
                int col = colBase + wn + nt * 8 + (lane & 3) * 2;
                float z0 = cg[mt][nt][half*2], z1 = cg[mt][nt][half*2+1];
                float u0 = cu[mt][nt][half*2], u1 = cu[mt][nt][half*2+1];
                float v0 = w * u0 * z0 / (1.f + expf(-z0));
                float v1 = w * u1 * z1 / (1.f + expf(-z1));
                *reinterpret_cast<unsigned*>(g_h + base + col) = round_pack2h(v0, v1);
            }
        }
    }
}

// ---- Launch #6: grouped GEMM2 (fp16x1, KB=64, 3-buffer, single sync/stage) ----
__global__ __launch_bounds__(256, 2) void gemm_down_mma() {
    extern __shared__ __half dyn[];
    int e = blockIdx.z;
    int start = g_offsets[e], end = g_offsets[e + 1];
    int rowBase = start + blockIdx.y * BM;
    if (rowBase >= end) return;
    int nRows = min(BM, end - rowBase);
    int colBase = blockIdx.x * BN;  // over D

    __shared__ int sP[BM];

    int tid = threadIdx.x, lane = tid & 31, warp = tid >> 5;
    int wm = (warp & 3) * 32, wn = (warp >> 2) * 32;

    if (tid < BM) sP[tid] = g_list[rowBase + min(tid, nRows - 1)];
    __syncthreads();

    const __half* bd = g_wd + (size_t)e * I_DIM * D_DIM + colBase;

    int arow = lane & 15, ahalf = (lane >> 4) * 8;
    int bk = ((lane >> 3) & 1) * 8 + (lane & 7);
    int bn = wn + (lane >> 4) * 8;

    float cc[2][4][4] = {};

    g2_load(tid, 0, dyn, sP, bd);
    g2_load(tid, KB, dyn + G2_STAGE, sP, bd);

#pragma unroll 3
    for (int s = 0; s < S2; s++) {
        if (s + 1 < S2) { CP_WAIT1(); } else { CP_WAIT0(); }
        __syncthreads();
        if (s + 2 < S2)
            g2_load(tid, (s + 2) * KB, dyn + ((s + 2) % 3) * G2_STAGE, sP, bd);

        __half* st = dyn + (s % 3) * G2_STAGE;
        uint32_t sA_u = smem_u32(st);
        uint32_t sB_u = smem_u32(st + ST_A);

#pragma unroll
        for (int ks = 0; ks < 4; ks++) {
            unsigned ah[2][4];
#pragma unroll
            for (int mt = 0; mt < 2; mt++) {
                unsigned off = (unsigned)(((wm + mt * 16 + arow) * A_STRIDE + ks * 16 + ahalf) * 2);
                LDSM_X4(ah[mt][0], ah[mt][1], ah[mt][2], ah[mt][3], sA_u + off);
            }
            unsigned boff0 = (unsigned)((((ks * 16 + bk) * B_STRIDE) + bn) * 2);
#pragma unroll
            for (int np = 0; np < 2; np++) {
                unsigned boff = boff0 + np * 32;
                unsigned b0,b1,b2,b3;
                LDSM_X4T(b0,b1,b2,b3, sB_u + boff);
#pragma unroll
                for (int mt = 0; mt < 2; mt++) {
                    MMA_F16(cc[mt][2*np],   ah[mt][0],ah[mt][1],ah[mt][2],ah[mt][3], b0,b1);
                    MMA_F16(cc[mt][2*np+1], ah[mt][0],ah[mt][1],ah[mt][2],ah[mt][3], b2,b3);
                }
            }
        }
    }

#pragma unroll
    for (int mt = 0; mt < 2; mt++)
#pragma unroll
    for (int half = 0; half < 2; half++) {
        int lr = wm + mt * 16 + (lane >> 2) + half * 8;
        if (lr < nRows) {
            int p = sP[lr];
            size_t base = (size_t)p * D_DIM;
#pragma unroll
            for (int nt = 0; nt < 4; nt++) {
                int col = colBase + wn + nt * 8 + (lane & 3) * 2;
                *reinterpret_cast<unsigned*>(g_op + base + col) =
                    round_pack2h(cc[mt][nt][half*2], cc[mt][nt][half*2+1]);
            }
        }
    }
}

// ---- combine: out[t] = sum over the token's 8 pairs (atomic-free, fp32 sum of fp16 partials) ----
__global__ void combine_kernel(float* __restrict__ out) {
    int idx = blockIdx.x * blockDim.x + threadIdx.x;
    int idx4 = idx * 4;
    if (idx4 >= T_TOK * D_DIM) return;
    int t = idx4 >> 11;
    int d = idx4 & (D_DIM - 1);
    float4 s = make_float4(0.f, 0.f, 0.f, 0.f);
#pragma unroll
    for (int k = 0; k < K_TOP; k++) {
        uint2 v = *reinterpret_cast<const uint2*>(
            g_op + ((size_t)(t * K_TOP + k)) * D_DIM + d);
        __half2 h01 = *reinterpret_cast<__half2*>(&v.x);
        __half2 h23 = *reinterpret_cast<__half2*>(&v.y);
        float2 f01 = __half22float2(h01);
        float2 f23 = __half22float2(h23);
        s.x += f01.x; s.y += f01.y; s.z += f23.x; s.w += f23.y;
    }
    *reinterpret_cast<float4*>(out + idx4) = s;
}

__global__ void aux_kernel(float* __restrict__ out, int out_size) {
    int lane = threadIdx.x;
    float v = (lane < E_NUM) ? g_probs_sum[lane] * (float)g_counts[lane] : 0.f;
    for (int o = 16; o; o >>= 1) v += __shfl_xor_sync(0xffffffffu, v, o);
    if (lane == 0 && out_size > T_TOK * D_DIM)
        out[T_TOK * D_DIM] = v / ((float)T_TOK * (float)T_TOK);
}

// ---------------------------------------------------------------
extern "C" void kernel_launch(void* const* d_in, const int* in_sizes, int n_in,
                              void* d_out, int out_size) {
    const float* x     = (const float*)d_in[0];
    const float* Wgate = (const float*)d_in[1];
    const float* Wg    = (const float*)d_in[2];
    const float* Wu    = (const float*)d_in[3];
    const float* Wd    = (const float*)d_in[4];
    float* out = (float*)d_out;

    // Unconditional (idempotent) — no static guards per harness contract.
    cudaFuncSetAttribute(gemm_gateup_mma, cudaFuncAttributeMaxDynamicSharedMemorySize,
                         3 * G1_STAGE * 2);
    cudaFuncSetAttribute(gemm_down_mma, cudaFuncAttributeMaxDynamicSharedMemorySize,
                         3 * G2_STAGE * 2);

    convert_init_kernel<<<4096, 256>>>(x, Wg, Wu, Wd);
    routing_kernel<<<T_TOK / 8, 256>>>(x, Wgate);
    scan_kernel<<<1, 32>>>();
    scatter_kernel<<<P_NUM / 256, 256>>>();

    dim3 g1(I_DIM / BN, T_TOK / BM, E_NUM);   // (16, 64, 32)
    gemm_gateup_mma<<<g1, 256, 3 * G1_STAGE * 2>>>();

    dim3 g2(D_DIM / BN, T_TOK / BM, E_NUM);   // (32, 64, 32)
    gemm_down_mma<<<g2, 256, 3 * G2_STAGE * 2>>>();

    combine_kernel<<<(T_TOK * D_DIM / 4) / 256, 256>>>(out);
    aux_kernel<<<1, 32>>>(out, out_size);
}

// round 15
// speedup vs baseline: 9.0179x; 1.0106x over previous
#include <cuda_runtime.h>
#include <cuda_fp16.h>
#include <math.h>
#include <stdint.h>

#define T_TOK 8192
#define D_DIM 2048
#define I_DIM 1024
#define E_NUM 32
#define K_TOP 8
#define P_NUM (T_TOK * K_TOP)

#define BM 128
#define BN 64
#define KB 64
#define A_STRIDE 72   // fp16 elems per A smem row (64 + 8 pad) -> 144B, conflict-free LDSM
#define B_STRIDE 72   // fp16 elems per B smem row (64 + 8 pad)

#define ST_A (BM * A_STRIDE)           // 9216 elems
#define ST_B (KB * B_STRIDE)           // 4608 elems
#define G1_STAGE (ST_A + 2 * ST_B)     // 18432 elems (36864 B)
#define G2_STAGE (ST_A + ST_B)         // 13824 elems (27648 B)
#define S1 (D_DIM / KB)   // 32
#define S2 (I_DIM / KB)   // 16
#define MAX_TILES (P_NUM / BM + E_NUM) // 544

// ---- scratch (static device globals; no runtime allocation) ----
__device__ __half g_x[(size_t)T_TOK * D_DIM];            // single fp16 (rounded)
__device__ __half g_wg[(size_t)E_NUM * D_DIM * I_DIM];   // single fp16 (rounded)
__device__ __half g_wu[(size_t)E_NUM * D_DIM * I_DIM];
__device__ __half g_wd[(size_t)E_NUM * I_DIM * D_DIM];
__device__ __half g_h[(size_t)P_NUM * I_DIM];            // single fp16 (rounded)
__device__ __half g_op[(size_t)P_NUM * D_DIM];           // fp16 partials
__device__ float g_pair_w[P_NUM];
__device__ int   g_pair_e[P_NUM];
__device__ int   g_counts[E_NUM];
__device__ int   g_offsets[E_NUM + 1];
__device__ int   g_cursor[E_NUM];
__device__ float g_probs_sum[E_NUM];
__device__ int   g_list[P_NUM];
__device__ int   g_tile_e[MAX_TILES];
__device__ int   g_tile_row[MAX_TILES];
__device__ int   g_ntiles;

// ---- PTX helpers ----
#define LDSM_X4(R0,R1,R2,R3,ADDR) \
    asm volatile("ldmatrix.sync.aligned.m8n8.x4.shared.b16 {%0,%1,%2,%3}, [%4];" \
        : "=r"(R0),"=r"(R1),"=r"(R2),"=r"(R3) : "r"(ADDR))
#define LDSM_X4T(R0,R1,R2,R3,ADDR) \
    asm volatile("ldmatrix.sync.aligned.m8n8.x4.trans.shared.b16 {%0,%1,%2,%3}, [%4];" \
        : "=r"(R0),"=r"(R1),"=r"(R2),"=r"(R3) : "r"(ADDR))
#define MMA_F16(C,A0,A1,A2,A3,B0,B1) \
    asm volatile("mma.sync.aligned.m16n8k16.row.col.f32.f16.f16.f32 " \
        "{%0,%1,%2,%3},{%4,%5,%6,%7},{%8,%9},{%0,%1,%2,%3};" \
        : "+f"((C)[0]),"+f"((C)[1]),"+f"((C)[2]),"+f"((C)[3]) \
        : "r"(A0),"r"(A1),"r"(A2),"r"(A3),"r"(B0),"r"(B1))
#define CP16(dst, srcp) asm volatile("cp.async.cg.shared.global [%0], [%1], 16;" :: "r"(dst), "l"(srcp))
#define CP_COMMIT() asm volatile("cp.async.commit_group;" ::: "memory")
#define CP_WAIT1()  asm volatile("cp.async.wait_group 1;" ::: "memory")
#define CP_WAIT0()  asm volatile("cp.async.wait_group 0;" ::: "memory")

__device__ __forceinline__ uint32_t smem_u32(const void* p) {
    return (uint32_t)__cvta_generic_to_shared(p);
}
__device__ __forceinline__ unsigned round_pack2h(float a, float b) {
    __half2 hh = __halves2half2(__float2half_rn(a), __float2half_rn(b));
    return *reinterpret_cast<unsigned*>(&hh);
}

// ---------------------------------------------------------------
// Launch #1: init router state + convert x, Wg, Wu, Wd -> single fp16.
__global__ void convert_init_kernel(const float* __restrict__ x,
                                    const float* __restrict__ Wg,
                                    const float* __restrict__ Wu,
                                    const float* __restrict__ Wd) {
    if (blockIdx.x == 0 && threadIdx.x < E_NUM) {
        g_counts[threadIdx.x] = 0;
        g_probs_sum[threadIdx.x] = 0.f;
    }
    const size_t QX = (size_t)T_TOK * D_DIM / 4;
    const size_t QW = (size_t)E_NUM * D_DIM * I_DIM / 4;
    const size_t total = QX + 3 * QW;
    size_t q = (size_t)blockIdx.x * blockDim.x + threadIdx.x;
    size_t step = (size_t)gridDim.x * blockDim.x;
    for (; q < total; q += step) {
        const float* src; __half* dst; size_t i;
        if (q < QX)               { src = x;  dst = g_x;  i = q; }
        else if (q < QX + QW)     { src = Wg; dst = g_wg; i = q - QX; }
        else if (q < QX + 2 * QW) { src = Wu; dst = g_wu; i = q - QX - QW; }
        else                      { src = Wd; dst = g_wd; i = q - QX - 2 * QW; }
        float4 f = reinterpret_cast<const float4*>(src)[i];
        uint2 H;
        H.x = round_pack2h(f.x, f.y);
        H.y = round_pack2h(f.z, f.w);
        reinterpret_cast<uint2*>(dst)[i] = H;
    }
}

// Launch #2: one warp per token; lane == expert (E == 32). (fp32, exact routing)
__global__ void routing_kernel(const float* __restrict__ x,
                               const float* __restrict__ Wgate) {
    int gwarp = (blockIdx.x * blockDim.x + threadIdx.x) >> 5;
    int lane  = threadIdx.x & 31;
    if (gwarp >= T_TOK) return;

    const float4* xr4 = reinterpret_cast<const float4*>(x + (size_t)gwarp * D_DIM);
    float a0 = 0.f, a1 = 0.f, a2 = 0.f, a3 = 0.f;
#pragma unroll 2
    for (int d4 = 0; d4 < D_DIM / 4; d4++) {
        float4 xv = xr4[d4];
        int d = d4 * 4;
        a0 += xv.x * Wgate[(d + 0) * E_NUM + lane];
        a1 += xv.y * Wgate[(d + 1) * E_NUM + lane];
        a2 += xv.z * Wgate[(d + 2) * E_NUM + lane];
        a3 += xv.w * Wgate[(d + 3) * E_NUM + lane];
    }
    float acc = (a0 + a1) + (a2 + a3);

    float m = acc;
    for (int o = 16; o; o >>= 1) m = fmaxf(m, __shfl_xor_sync(0xffffffffu, m, o));
    float pe = expf(acc - m);
    float s = pe;
    for (int o = 16; o; o >>= 1) s += __shfl_xor_sync(0xffffffffu, s, o);
    atomicAdd(&g_probs_sum[lane], pe / s);

    float v = acc;
    float selv = 0.f; int seli = 0;
#pragma unroll
    for (int k = 0; k < K_TOP; k++) {
        float mv = v;
        for (int o = 16; o; o >>= 1) mv = fmaxf(mv, __shfl_xor_sync(0xffffffffu, mv, o));
        unsigned b = __ballot_sync(0xffffffffu, v == mv);
        int src = __ffs(b) - 1;
        if (lane == k)   { selv = mv; seli = src; }
        if (lane == src) v = -INFINITY;
    }

    float top0 = __shfl_sync(0xffffffffu, selv, 0);
    float ev = (lane < K_TOP) ? expf(selv - top0) : 0.f;
    float es = ev;
    for (int o = 16; o; o >>= 1) es += __shfl_xor_sync(0xffffffffu, es, o);

    if (lane < K_TOP) {
        int p = gwarp * K_TOP + lane;
        g_pair_w[p] = ev / es;
        g_pair_e[p] = seli;
        atomicAdd(&g_counts[seli], 1);
    }
}

// Launch #3: scan (single warp) + build dense tile table.
__global__ void scan_kernel() {
    int lane = threadIdx.x;
    int c = g_counts[lane];
    int v = c;
    for (int o = 1; o < 32; o <<= 1) {
        int n = __shfl_up_sync(0xffffffffu, v, o);
        if (lane >= o) v += n;
    }
    int excl = v - c;
    g_offsets[lane] = excl;
    if (lane == 31) g_offsets[32] = v;
    g_cursor[lane] = excl;

    // tile table: per-expert tile count, prefix-scanned into a dense list
    int nt = (c + BM - 1) / BM;
    int tv = nt;
    for (int o = 1; o < 32; o <<= 1) {
        int n = __shfl_up_sync(0xffffffffu, tv, o);
        if (lane >= o) tv += n;
    }
    int texcl = tv - nt;
    if (lane == 31) g_ntiles = tv;
    for (int i = 0; i < nt; i++) {
        g_tile_e[texcl + i]   = lane;
        g_tile_row[texcl + i] = i;
    }
}

// Launch #4: scatter (grid-wide; g_list order is schedule-dependent but every
// per-row result and the combine read locations are fixed -> output bits deterministic).
__global__ void scatter_kernel() {
    int p = blockIdx.x * blockDim.x + threadIdx.x;
    if (p >= P_NUM) return;
    int e = g_pair_e[p];
    int pos = atomicAdd(&g_cursor[e], 1);
    g_list[pos] = p;
}

// ---- cp.async stage loaders (KB = 64) ----
__device__ __forceinline__ void g1_load(int tid, int k0, __half* st,
                                        const int* sT,
                                        const __half* bg, const __half* bu) {
#pragma unroll
    for (int i = 0; i < 4; i++) {
        int q = tid + i * 256;
        int r = q >> 3, c = (q & 7) * 8;
        size_t so = (size_t)sT[r] * D_DIM + k0 + c;
        CP16(smem_u32(st + r * A_STRIDE + c), g_x + so);
    }
#pragma unroll
    for (int i = 0; i < 2; i++) {
        int q = tid + i * 256;
        int r = q >> 3, c = (q & 7) * 8;
        size_t so = (size_t)(k0 + r) * I_DIM + c;   // caller pre-offsets by colBase
        uint32_t d = smem_u32(st + ST_A + r * B_STRIDE + c);
        CP16(d,            bg + so);
        CP16(d + ST_B * 2, bu + so);
    }
    CP_COMMIT();
}

__device__ __forceinline__ void g2_load(int tid, int k0, __half* st,
                                        const int* sPp,
                                        const __half* bd) {
#pragma unroll
    for (int i = 0; i < 4; i++) {
        int q = tid + i * 256;
        int r = q >> 3, c = (q & 7) * 8;
        size_t so = (size_t)sPp[r] * I_DIM + k0 + c;
        CP16(smem_u32(st + r * A_STRIDE + c), g_h + so);
    }
#pragma unroll
    for (int i = 0; i < 2; i++) {
        int q = tid + i * 256;
        int r = q >> 3, c = (q & 7) * 8;
        size_t so = (size_t)(k0 + r) * D_DIM + c;   // caller pre-offsets by colBase
        CP16(smem_u32(st + ST_A + r * B_STRIDE + c), bd + so);
    }
    CP_COMMIT();
}

// ---- Launch #5: grouped GEMM1 (fp16x1, KB=64, 3-buffer, single sync/stage) ----
__global__ __launch_bounds__(256, 2) void gemm_gateup_mma() {
    extern __shared__ __half dyn[];
    int t = blockIdx.y;
    if (t >= g_ntiles) return;
    int e = g_tile_e[t];
    int start = g_offsets[e], end = g_offsets[e + 1];
    int rowBase = start + g_tile_row[t] * BM;
    int nRows = min(BM, end - rowBase);
    int colBase = blockIdx.x * BN;  // over I

    __shared__ int   sP[BM];
    __shared__ int   sT[BM];
    __shared__ float sW[BM];

    int tid = threadIdx.x, lane = tid & 31, warp = tid >> 5;
    int wm = (warp & 3) * 32, wn = (warp >> 2) * 32;

    if (tid < BM) {
        int p = g_list[rowBase + min(tid, nRows - 1)];
        sP[tid] = p; sT[tid] = p >> 3; sW[tid] = g_pair_w[p];
    }
    __syncthreads();

    const __half* bg = g_wg + (size_t)e * D_DIM * I_DIM + colBase;
    const __half* bu = g_wu + (size_t)e * D_DIM * I_DIM + colBase;

    int arow = lane & 15, ahalf = (lane >> 4) * 8;
    int bk   = ((lane >> 3) & 1) * 8 + (lane & 7);
    int bn   = wn + (lane >> 4) * 8;

    float cg[2][4][4] = {}, cu[2][4][4] = {};

    g1_load(tid, 0, dyn, sT, bg, bu);
    g1_load(tid, KB, dyn + G1_STAGE, sT, bg, bu);

#pragma unroll 3
    for (int s = 0; s < S1; s++) {
        // in flight: groups s, s+1 -> WAIT1 proves group s done; last: WAIT0.
        if (s + 1 < S1) { CP_WAIT1(); } else { CP_WAIT0(); }
        __syncthreads();   // publishes stage s; proves stage s-1 reads done
        if (s + 2 < S1)
            g1_load(tid, (s + 2) * KB, dyn + ((s + 2) % 3) * G1_STAGE, sT, bg, bu);

        __half* st = dyn + (s % 3) * G1_STAGE;
        uint32_t sA_u = smem_u32(st);
        uint32_t sB_u = smem_u32(st + ST_A);

#pragma unroll
        for (int ks = 0; ks < 4; ks++) {
            unsigned ah[2][4];
#pragma unroll
            for (int mt = 0; mt < 2; mt++) {
                unsigned off = (unsigned)(((wm + mt * 16 + arow) * A_STRIDE + ks * 16 + ahalf) * 2);
                LDSM_X4(ah[mt][0], ah[mt][1], ah[mt][2], ah[mt][3], sA_u + off);
            }
            unsigned boff0 = (unsigned)((((ks * 16 + bk) * B_STRIDE) + bn) * 2);
#pragma unroll
            for (int np = 0; np < 2; np++) {
                unsigned boff = boff0 + np * 32;
                unsigned b0,b1,b2,b3;
                LDSM_X4T(b0,b1,b2,b3, sB_u + boff);
#pragma unroll
                for (int mt = 0; mt < 2; mt++) {
                    MMA_F16(cg[mt][2*np],   ah[mt][0],ah[mt][1],ah[mt][2],ah[mt][3], b0,b1);
                    MMA_F16(cg[mt][2*np+1], ah[mt][0],ah[mt][1],ah[mt][2],ah[mt][3], b2,b3);
                }
            }
#pragma unroll
            for (int np = 0; np < 2; np++) {
                unsigned boff = boff0 + np * 32;
                unsigned b0,b1,b2,b3;
                LDSM_X4T(b0,b1,b2,b3, sB_u + ST_B * 2 + boff);
#pragma unroll
                for (int mt = 0; mt < 2; mt++) {
                    MMA_F16(cu[mt][2*np],   ah[mt][0],ah[mt][1],ah[mt][2],ah[mt][3], b0,b1);
                    MMA_F16(cu[mt][2*np+1], ah[mt][0],ah[mt][1],ah[mt][2],ah[mt][3], b2,b3);
                }
            }
        }
    }

    // epilogue: v = w * silu(gate) * up -> single fp16
#pragma unroll
    for (int mt = 0; mt < 2; mt++)
#pragma unroll
    for (int half = 0; half < 2; half++) {
        int lr = wm + mt * 16 + (lane >> 2) + half * 8;
        if (lr < nRows) {
            int p = sP[lr]; float w = sW[lr];
            size_t base = (size_t)p * I_DIM;
#pragma unroll
            for (int nt = 0; nt < 4; nt++) {
                int col = colBase + wn + nt * 8 + (lane & 3) * 2;
                float z0 = cg[mt][nt][half*2], z1 = cg[mt][nt][half*2+1];
                float u0 = cu[mt][nt][half*2], u1 = cu[mt][nt][half*2+1];
                float v0 = w * u0 * z0 / (1.f + expf(-z0));
                float v1 = w * u1 * z1 / (1.f + expf(-z1));
                *reinterpret_cast<unsigned*>(g_h + base + col) = round_pack2h(v0, v1);
            }
        }
    }
}

// ---- Launch #6: grouped GEMM2 (fp16x1, KB=64, 3-buffer, single sync/stage) ----
__global__ __launch_bounds__(256, 2) void gemm_down_mma() {
    extern __shared__ __half dyn[];
    int t = blockIdx.y;
    if (t >= g_ntiles) return;
    int e = g_tile_e[t];
    int start = g_offsets[e], end = g_offsets[e + 1];
    int rowBase = start + g_tile_row[t] * BM;
    int nRows = min(BM, end - rowBase);
    int colBase = blockIdx.x * BN;  // over D

    __shared__ int sP[BM];

    int tid = threadIdx.x, lane = tid & 31, warp = tid >> 5;
    int wm = (warp & 3) * 32, wn = (warp >> 2) * 32;

    if (tid < BM) sP[tid] = g_list[rowBase + min(tid, nRows - 1)];
    __syncthreads();

    const __half* bd = g_wd + (size_t)e * I_DIM * D_DIM + colBase;

    int arow = lane & 15, ahalf = (lane >> 4) * 8;
    int bk = ((lane >> 3) & 1) * 8 + (lane & 7);
    int bn = wn + (lane >> 4) * 8;

    float cc[2][4][4] = {};

    g2_load(tid, 0, dyn, sP, bd);
    g2_load(tid, KB, dyn + G2_STAGE, sP, bd);

#pragma unroll 3
    for (int s = 0; s < S2; s++) {
        if (s + 1 < S2) { CP_WAIT1(); } else { CP_WAIT0(); }
        __syncthreads();
        if (s + 2 < S2)
            g2_load(tid, (s + 2) * KB, dyn + ((s + 2) % 3) * G2_STAGE, sP, bd);

        __half* st = dyn + (s % 3) * G2_STAGE;
        uint32_t sA_u = smem_u32(st);
        uint32_t sB_u = smem_u32(st + ST_A);

#pragma unroll
        for (int ks = 0; ks < 4; ks++) {
            unsigned ah[2][4];
#pragma unroll
            for (int mt = 0; mt < 2; mt++) {
                unsigned off = (unsigned)(((wm + mt * 16 + arow) * A_STRIDE + ks * 16 + ahalf) * 2);
                LDSM_X4(ah[mt][0], ah[mt][1], ah[mt][2], ah[mt][3], sA_u + off);
            }
            unsigned boff0 = (unsigned)((((ks * 16 + bk) * B_STRIDE) + bn) * 2);
#pragma unroll
            for (int np = 0; np < 2; np++) {
                unsigned boff = boff0 + np * 32;
                unsigned b0,b1,b2,b3;
                LDSM_X4T(b0,b1,b2,b3, sB_u + boff);
#pragma unroll
                for (int mt = 0; mt < 2; mt++) {
                    MMA_F16(cc[mt][2*np],   ah[mt][0],ah[mt][1],ah[mt][2],ah[mt][3], b0,b1);
                    MMA_F16(cc[mt][2*np+1], ah[mt][0],ah[mt][1],ah[mt][2],ah[mt][3], b2,b3);
                }
            }
        }
    }

#pragma unroll
    for (int mt = 0; mt < 2; mt++)
#pragma unroll
    for (int half = 0; half < 2; half++) {
        int lr = wm + mt * 16 + (lane >> 2) + half * 8;
        if (lr < nRows) {
            int p = sP[lr];
            size_t base = (size_t)p * D_DIM;
#pragma unroll
            for (int nt = 0; nt < 4; nt++) {
                int col = colBase + wn + nt * 8 + (lane & 3) * 2;
                *reinterpret_cast<unsigned*>(g_op + base + col) =
                    round_pack2h(cc[mt][nt][half*2], cc[mt][nt][half*2+1]);
            }
        }
    }
}

// ---- combine: out[t] = sum over the token's 8 pairs (atomic-free, fp32 sum of fp16 partials) ----
__global__ void combine_kernel(float* __restrict__ out) {
    int idx = blockIdx.x * blockDim.x + threadIdx.x;
    int idx4 = idx * 4;
    if (idx4 >= T_TOK * D_DIM) return;
    int t = idx4 >> 11;
    int d = idx4 & (D_DIM - 1);
    float4 s = make_float4(0.f, 0.f, 0.f, 0.f);
#pragma unroll
    for (int k = 0; k < K_TOP; k++) {
        uint2 v = *reinterpret_cast<const uint2*>(
            g_op + ((size_t)(t * K_TOP + k)) * D_DIM + d);
        __half2 h01 = *reinterpret_cast<__half2*>(&v.x);
        __half2 h23 = *reinterpret_cast<__half2*>(&v.y);
        float2 f01 = __half22float2(h01);
        float2 f23 = __half22float2(h23);
        s.x += f01.x; s.y += f01.y; s.z += f23.x; s.w += f23.y;
    }
    *reinterpret_cast<float4*>(out + idx4) = s;
}

__global__ void aux_kernel(float* __restrict__ out, int out_size) {
    int lane = threadIdx.x;
    float v = (lane < E_NUM) ? g_probs_sum[lane] * (float)g_counts[lane] : 0.f;
    for (int o = 16; o; o >>= 1) v += __shfl_xor_sync(0xffffffffu, v, o);
    if (lane == 0 && out_size > T_TOK * D_DIM)
        out[T_TOK * D_DIM] = v / ((float)T_TOK * (float)T_TOK);
}

// ---------------------------------------------------------------
extern "C" void kernel_launch(void* const* d_in, const int* in_sizes, int n_in,
                              void* d_out, int out_size) {
    const float* x     = (const float*)d_in[0];
    const float* Wgate = (const float*)d_in[1];
    const float* Wg    = (const float*)d_in[2];
    const float* Wu    = (const float*)d_in[3];
    const float* Wd    = (const float*)d_in[4];
    float* out = (float*)d_out;

    // Unconditional (idempotent) — no static guards per harness contract.
    cudaFuncSetAttribute(gemm_gateup_mma, cudaFuncAttributeMaxDynamicSharedMemorySize,
                         3 * G1_STAGE * 2);
    cudaFuncSetAttribute(gemm_down_mma, cudaFuncAttributeMaxDynamicSharedMemorySize,
                         3 * G2_STAGE * 2);

    convert_init_kernel<<<4096, 256>>>(x, Wg, Wu, Wd);
    routing_kernel<<<T_TOK / 8, 256>>>(x, Wgate);
    scan_kernel<<<1, 32>>>();
    scatter_kernel<<<P_NUM / 256, 256>>>();

    dim3 g1(I_DIM / BN, MAX_TILES);   // (16, 544)
    gemm_gateup_mma<<<g1, 256, 3 * G1_STAGE * 2>>>();

    dim3 g2(D_DIM / BN, MAX_TILES);   // (32, 544)
    gemm_down_mma<<<g2, 256, 3 * G2_STAGE * 2>>>();

    combine_kernel<<<(T_TOK * D_DIM / 4) / 256, 256>>>(out);
    aux_kernel<<<1, 32>>>(out, out_size);
}

// round 16
// speedup vs baseline: 9.9732x; 1.1059x over previous
#include <cuda_runtime.h>
#include <cuda_fp16.h>
#include <math.h>
#include <stdint.h>

#define T_TOK 8192
#define D_DIM 2048
#define I_DIM 1024
#define E_NUM 32
#define K_TOP 8
#define P_NUM (T_TOK * K_TOP)

#define BM 128
#define BN 64
#define KB 64
#define A_STRIDE 72    // fp16 elems per A smem row (64 + 8 pad)
#define B_STRIDE 72    // fp16 elems per B smem row (64 + 8 pad)   [GEMM1]
#define BN2 128
#define B2_STRIDE 136  // fp16 elems per B smem row (128 + 8 pad)  [GEMM2]

#define ST_A (BM * A_STRIDE)           // 9216 elems
#define ST_B (KB * B_STRIDE)           // 4608 elems
#define ST_B2 (KB * B2_STRIDE)         // 8704 elems
#define G1_STAGE (ST_A + 2 * ST_B)     // 18432 elems (36864 B)
#define G2_STAGE (ST_A + ST_B2)        // 17920 elems (35840 B)
#define S1 (D_DIM / KB)   // 32
#define S2 (I_DIM / KB)   // 16
#define MAX_TILES (P_NUM / BM + E_NUM) // 544

// ---- scratch (static device globals; no runtime allocation) ----
__device__ __half g_x[(size_t)T_TOK * D_DIM];
__device__ __half g_wg[(size_t)E_NUM * D_DIM * I_DIM];
__device__ __half g_wu[(size_t)E_NUM * D_DIM * I_DIM];
__device__ __half g_wd[(size_t)E_NUM * I_DIM * D_DIM];
__device__ __half g_h[(size_t)P_NUM * I_DIM];
__device__ __half g_op[(size_t)P_NUM * D_DIM];
__device__ float g_pair_w[P_NUM];
__device__ int   g_pair_e[P_NUM];
__device__ int   g_counts[E_NUM];
__device__ int   g_offsets[E_NUM + 1];
__device__ int   g_cursor[E_NUM];
__device__ float g_probs_sum[E_NUM];
__device__ int   g_list[P_NUM];
__device__ int   g_tile_e[MAX_TILES];
__device__ int   g_tile_row[MAX_TILES];
__device__ int   g_ntiles;

// ---- PTX helpers ----
#define LDSM_X4(R0,R1,R2,R3,ADDR) \
    asm volatile("ldmatrix.sync.aligned.m8n8.x4.shared.b16 {%0,%1,%2,%3}, [%4];" \
        : "=r"(R0),"=r"(R1),"=r"(R2),"=r"(R3) : "r"(ADDR))
#define LDSM_X4T(R0,R1,R2,R3,ADDR) \
    asm volatile("ldmatrix.sync.aligned.m8n8.x4.trans.shared.b16 {%0,%1,%2,%3}, [%4];" \
        : "=r"(R0),"=r"(R1),"=r"(R2),"=r"(R3) : "r"(ADDR))
#define MMA_F16(C,A0,A1,A2,A3,B0,B1) \
    asm volatile("mma.sync.aligned.m16n8k16.row.col.f32.f16.f16.f32 " \
        "{%0,%1,%2,%3},{%4,%5,%6,%7},{%8,%9},{%0,%1,%2,%3};" \
        : "+f"((C)[0]),"+f"((C)[1]),"+f"((C)[2]),"+f"((C)[3]) \
        : "r"(A0),"r"(A1),"r"(A2),"r"(A3),"r"(B0),"r"(B1))
#define CP16(dst, srcp) asm volatile("cp.async.cg.shared.global [%0], [%1], 16;" :: "r"(dst), "l"(srcp))
#define CP_COMMIT() asm volatile("cp.async.commit_group;" ::: "memory")
#define CP_WAIT1()  asm volatile("cp.async.wait_group 1;" ::: "memory")
#define CP_WAIT0()  asm volatile("cp.async.wait_group 0;" ::: "memory")

__device__ __forceinline__ uint32_t smem_u32(const void* p) {
    return (uint32_t)__cvta_generic_to_shared(p);
}
__device__ __forceinline__ unsigned round_pack2h(float a, float b) {
    __half2 hh = __halves2half2(__float2half_rn(a), __float2half_rn(b));
    return *reinterpret_cast<unsigned*>(&hh);
}

// ---------------------------------------------------------------
// Launch #1: init router state + convert x, Wg, Wu, Wd -> single fp16.
__global__ void convert_init_kernel(const float* __restrict__ x,
                                    const float* __restrict__ Wg,
                                    const float* __restrict__ Wu,
                                    const float* __restrict__ Wd) {
    if (blockIdx.x == 0 && threadIdx.x < E_NUM) {
        g_counts[threadIdx.x] = 0;
        g_probs_sum[threadIdx.x] = 0.f;
    }
    const size_t QX = (size_t)T_TOK * D_DIM / 4;
    const size_t QW = (size_t)E_NUM * D_DIM * I_DIM / 4;
    const size_t total = QX + 3 * QW;
    size_t q = (size_t)blockIdx.x * blockDim.x + threadIdx.x;
    size_t step = (size_t)gridDim.x * blockDim.x;
    for (; q < total; q += step) {
        const float* src; __half* dst; size_t i;
        if (q < QX)               { src = x;  dst = g_x;  i = q; }
        else if (q < QX + QW)     { src = Wg; dst = g_wg; i = q - QX; }
        else if (q < QX + 2 * QW) { src = Wu; dst = g_wu; i = q - QX - QW; }
        else                      { src = Wd; dst = g_wd; i = q - QX - 2 * QW; }
        float4 f = reinterpret_cast<const float4*>(src)[i];
        uint2 H;
        H.x = round_pack2h(f.x, f.y);
        H.y = round_pack2h(f.z, f.w);
        reinterpret_cast<uint2*>(dst)[i] = H;
    }
}

// Launch #2: one warp per token; lane == expert (E == 32). (fp32, exact routing)
__global__ void routing_kernel(const float* __restrict__ x,
                               const float* __restrict__ Wgate) {
    int gwarp = (blockIdx.x * blockDim.x + threadIdx.x) >> 5;
    int lane  = threadIdx.x & 31;
    if (gwarp >= T_TOK) return;

    const float4* xr4 = reinterpret_cast<const float4*>(x + (size_t)gwarp * D_DIM);
    float a0 = 0.f, a1 = 0.f, a2 = 0.f, a3 = 0.f;
#pragma unroll 2
    for (int d4 = 0; d4 < D_DIM / 4; d4++) {
        float4 xv = xr4[d4];
        int d = d4 * 4;
        a0 += xv.x * Wgate[(d + 0) * E_NUM + lane];
        a1 += xv.y * Wgate[(d + 1) * E_NUM + lane];
        a2 += xv.z * Wgate[(d + 2) * E_NUM + lane];
        a3 += xv.w * Wgate[(d + 3) * E_NUM + lane];
    }
    float acc = (a0 + a1) + (a2 + a3);

    float m = acc;
    for (int o = 16; o; o >>= 1) m = fmaxf(m, __shfl_xor_sync(0xffffffffu, m, o));
    float pe = expf(acc - m);
    float s = pe;
    for (int o = 16; o; o >>= 1) s += __shfl_xor_sync(0xffffffffu, s, o);
    atomicAdd(&g_probs_sum[lane], pe / s);

    float v = acc;
    float selv = 0.f; int seli = 0;
#pragma unroll
    for (int k = 0; k < K_TOP; k++) {
        float mv = v;
        for (int o = 16; o; o >>= 1) mv = fmaxf(mv, __shfl_xor_sync(0xffffffffu, mv, o));
        unsigned b = __ballot_sync(0xffffffffu, v == mv);
        int src = __ffs(b) - 1;
        if (lane == k)   { selv = mv; seli = src; }
        if (lane == src) v = -INFINITY;
    }

    float top0 = __shfl_sync(0xffffffffu, selv, 0);
    float ev = (lane < K_TOP) ? expf(selv - top0) : 0.f;
    float es = ev;
    for (int o = 16; o; o >>= 1) es += __shfl_xor_sync(0xffffffffu, es, o);

    if (lane < K_TOP) {
        int p = gwarp * K_TOP + lane;
        g_pair_w[p] = ev / es;
        g_pair_e[p] = seli;
        atomicAdd(&g_counts[seli], 1);
    }
}

// Launch #3: scan (single warp) + build dense tile table.
__global__ void scan_kernel() {
    int lane = threadIdx.x;
    int c = g_counts[lane];
    int v = c;
    for (int o = 1; o < 32; o <<= 1) {
        int n = __shfl_up_sync(0xffffffffu, v, o);
        if (lane >= o) v += n;
    }
    int excl = v - c;
    g_offsets[lane] = excl;
    if (lane == 31) g_offsets[32] = v;
    g_cursor[lane] = excl;

    int nt = (c + BM - 1) / BM;
    int tv = nt;
    for (int o = 1; o < 32; o <<= 1) {
        int n = __shfl_up_sync(0xffffffffu, tv, o);
        if (lane >= o) tv += n;
    }
    int texcl = tv - nt;
    if (lane == 31) g_ntiles = tv;
    for (int i = 0; i < nt; i++) {
        g_tile_e[texcl + i]   = lane;
        g_tile_row[texcl + i] = i;
    }
}

// Launch #4: scatter.
__global__ void scatter_kernel() {
    int p = blockIdx.x * blockDim.x + threadIdx.x;
    if (p >= P_NUM) return;
    int e = g_pair_e[p];
    int pos = atomicAdd(&g_cursor[e], 1);
    g_list[pos] = p;
}

// ---- cp.async stage loaders (KB = 64) ----
__device__ __forceinline__ void g1_load(int tid, int k0, __half* st,
                                        const int* sT,
                                        const __half* bg, const __half* bu) {
#pragma unroll
    for (int i = 0; i < 4; i++) {
        int q = tid + i * 256;
        int r = q >> 3, c = (q & 7) * 8;
        size_t so = (size_t)sT[r] * D_DIM + k0 + c;
        CP16(smem_u32(st + r * A_STRIDE + c), g_x + so);
    }
#pragma unroll
    for (int i = 0; i < 2; i++) {
        int q = tid + i * 256;
        int r = q >> 3, c = (q & 7) * 8;
        size_t so = (size_t)(k0 + r) * I_DIM + c;   // caller pre-offsets by colBase
        uint32_t d = smem_u32(st + ST_A + r * B_STRIDE + c);
        CP16(d,            bg + so);
        CP16(d + ST_B * 2, bu + so);
    }
    CP_COMMIT();
}

__device__ __forceinline__ void g2_load(int tid, int k0, __half* st,
                                        const int* sPp,
                                        const __half* bd) {
#pragma unroll
    for (int i = 0; i < 4; i++) {
        int q = tid + i * 256;
        int r = q >> 3, c = (q & 7) * 8;
        size_t so = (size_t)sPp[r] * I_DIM + k0 + c;
        CP16(smem_u32(st + r * A_STRIDE + c), g_h + so);
    }
#pragma unroll
    for (int i = 0; i < 4; i++) {
        int q = tid + i * 256;
        int r = q >> 4, c = (q & 15) * 8;           // 128-wide B tile
        size_t so = (size_t)(k0 + r) * D_DIM + c;   // caller pre-offsets by colBase
        CP16(smem_u32(st + ST_A + r * B2_STRIDE + c), bd + so);
    }
    CP_COMMIT();
}

// ---- Launch #5: grouped GEMM1 (fp16x1, KB=64, 3-buffer, single sync/stage) ----
__global__ __launch_bounds__(256, 2) void gemm_gateup_mma() {
    extern __shared__ __half dyn[];
    int t = blockIdx.y;
    if (t >= g_ntiles) return;
    int e = g_tile_e[t];
    int start = g_offsets[e], end = g_offsets[e + 1];
    int rowBase = start + g_tile_row[t] * BM;
    int nRows = min(BM, end - rowBase);
    int colBase = blockIdx.x * BN;  // over I

    __shared__ int   sP[BM];
    __shared__ int   sT[BM];
    __shared__ float sW[BM];

    int tid = threadIdx.x, lane = tid & 31, warp = tid >> 5;
    int wm = (warp & 3) * 32, wn = (warp >> 2) * 32;

    if (tid < BM) {
        int p = g_list[rowBase + min(tid, nRows - 1)];
        sP[tid] = p; sT[tid] = p >> 3; sW[tid] = g_pair_w[p];
    }
    __syncthreads();

    const __half* bg = g_wg + (size_t)e * D_DIM * I_DIM + colBase;
    const __half* bu = g_wu + (size_t)e * D_DIM * I_DIM + colBase;

    int arow = lane & 15, ahalf = (lane >> 4) * 8;
    int bk   = ((lane >> 3) & 1) * 8 + (lane & 7);
    int bn   = wn + (lane >> 4) * 8;

    float cg[2][4][4] = {}, cu[2][4][4] = {};

    g1_load(tid, 0, dyn, sT, bg, bu);
    g1_load(tid, KB, dyn + G1_STAGE, sT, bg, bu);

#pragma unroll 3
    for (int s = 0; s < S1; s++) {
        if (s + 1 < S1) { CP_WAIT1(); } else { CP_WAIT0(); }
        __syncthreads();
        if (s + 2 < S1)
            g1_load(tid, (s + 2) * KB, dyn + ((s + 2) % 3) * G1_STAGE, sT, bg, bu);

        __half* st = dyn + (s % 3) * G1_STAGE;
        uint32_t sA_u = smem_u32(st);
        uint32_t sB_u = smem_u32(st + ST_A);

#pragma unroll
        for (int ks = 0; ks < 4; ks++) {
            unsigned ah[2][4];
#pragma unroll
            for (int mt = 0; mt < 2; mt++) {
                unsigned off = (unsigned)(((wm + mt * 16 + arow) * A_STRIDE + ks * 16 + ahalf) * 2);
                LDSM_X4(ah[mt][0], ah[mt][1], ah[mt][2], ah[mt][3], sA_u + off);
            }
            unsigned boff0 = (unsigned)((((ks * 16 + bk) * B_STRIDE) + bn) * 2);
#pragma unroll
            for (int np = 0; np < 2; np++) {
                unsigned boff = boff0 + np * 32;
                unsigned b0,b1,b2,b3;
                LDSM_X4T(b0,b1,b2,b3, sB_u + boff);
#pragma unroll
                for (int mt = 0; mt < 2; mt++) {
                    MMA_F16(cg[mt][2*np],   ah[mt][0],ah[mt][1],ah[mt][2],ah[mt][3], b0,b1);
                    MMA_F16(cg[mt][2*np+1], ah[mt][0],ah[mt][1],ah[mt][2],ah[mt][3], b2,b3);
                }
            }
#pragma unroll
            for (int np = 0; np < 2; np++) {
                unsigned boff = boff0 + np * 32;
                unsigned b0,b1,b2,b3;
                LDSM_X4T(b0,b1,b2,b3, sB_u + ST_B * 2 + boff);
#pragma unroll
                for (int mt = 0; mt < 2; mt++) {
                    MMA_F16(cu[mt][2*np],   ah[mt][0],ah[mt][1],ah[mt][2],ah[mt][3], b0,b1);
                    MMA_F16(cu[mt][2*np+1], ah[mt][0],ah[mt][1],ah[mt][2],ah[mt][3], b2,b3);
                }
            }
        }
    }

    // epilogue: v = w * silu(gate) * up -> single fp16
#pragma unroll
    for (int mt = 0; mt < 2; mt++)
#pragma unroll
    for (int half = 0; half < 2; half++) {
        int lr = wm + mt * 16 + (lane >> 2) + half * 8;
        if (lr < nRows) {
            int p = sP[lr]; float w = sW[lr];
            size_t base = (size_t)p * I_DIM;
#pragma unroll
            for (int nt = 0; nt < 4; nt++) {
                int col = colBase + wn + nt * 8 + (lane & 3) * 2;
                float z0 = cg[mt][nt][half*2], z1 = cg[mt][nt][half*2+1];
                float u0 = cu[mt][nt][half*2], u1 = cu[mt][nt][half*2+1];
                float v0 = w * u0 * z0 / (1.f + expf(-z0));
                float v1 = w * u1 * z1 / (1.f + expf(-z1));
                *reinterpret_cast<unsigned*>(g_h + base + col) = round_pack2h(v0, v1);
            }
        }
    }
}

// ---- Launch #6: grouped GEMM2 (fp16x1, 128x128 tile, warp 32x64, 3-buffer) ----
__global__ __launch_bounds__(256, 2) void gemm_down_mma() {
    extern __shared__ __half dyn[];
    int t = blockIdx.y;
    if (t >= g_ntiles) return;
    int e = g_tile_e[t];
    int start = g_offsets[e], end = g_offsets[e + 1];
    int rowBase = start + g_tile_row[t] * BM;
    int nRows = min(BM, end - rowBase);
    int colBase = blockIdx.x * BN2;  // over D

    __shared__ int sP[BM];

    int tid = threadIdx.x, lane = tid & 31, warp = tid >> 5;
    int wm = (warp & 3) * 32, wn = (warp >> 2) * 64;

    if (tid < BM) sP[tid] = g_list[rowBase + min(tid, nRows - 1)];
    __syncthreads();

    const __half* bd = g_wd + (size_t)e * I_DIM * D_DIM + colBase;

    int arow = lane & 15, ahalf = (lane >> 4) * 8;
    int bk = ((lane >> 3) & 1) * 8 + (lane & 7);
    int bn = wn + (lane >> 4) * 8;

    float cc[2][8][4] = {};

    g2_load(tid, 0, dyn, sP, bd);
    g2_load(tid, KB, dyn + G2_STAGE, sP, bd);

#pragma unroll 3
    for (int s = 0; s < S2; s++) {
        if (s + 1 < S2) { CP_WAIT1(); } else { CP_WAIT0(); }
        __syncthreads();
        if (s + 2 < S2)
            g2_load(tid, (s + 2) * KB, dyn + ((s + 2) % 3) * G2_STAGE, sP, bd);

        __half* st = dyn + (s % 3) * G2_STAGE;
        uint32_t sA_u = smem_u32(st);
        uint32_t sB_u = smem_u32(st + ST_A);

#pragma unroll
        for (int ks = 0; ks < 4; ks++) {
            unsigned ah[2][4];
#pragma unroll
            for (int mt = 0; mt < 2; mt++) {
                unsigned off = (unsigned)(((wm + mt * 16 + arow) * A_STRIDE + ks * 16 + ahalf) * 2);
                LDSM_X4(ah[mt][0], ah[mt][1], ah[mt][2], ah[mt][3], sA_u + off);
            }
            unsigned boff0 = (unsigned)((((ks * 16 + bk) * B2_STRIDE) + bn) * 2);
#pragma unroll
            for (int np = 0; np < 4; np++) {
                unsigned boff = boff0 + np * 32;   // +16 elems per np
                unsigned b0,b1,b2,b3;
                LDSM_X4T(b0,b1,b2,b3, sB_u + boff);
#pragma unroll
                for (int mt = 0; mt < 2; mt++) {
                    MMA_F16(cc[mt][2*np],   ah[mt][0],ah[mt][1],ah[mt][2],ah[mt][3], b0,b1);
                    MMA_F16(cc[mt][2*np+1], ah[mt][0],ah[mt][1],ah[mt][2],ah[mt][3], b2,b3);
                }
            }
        }
    }

#pragma unroll
    for (int mt = 0; mt < 2; mt++)
#pragma unroll
    for (int half = 0; half < 2; half++) {
        int lr = wm + mt * 16 + (lane >> 2) + half * 8;
        if (lr < nRows) {
            int p = sP[lr];
            size_t base = (size_t)p * D_DIM;
#pragma unroll
            for (int nt = 0; nt < 8; nt++) {
                int col = colBase + wn + nt * 8 + (lane & 3) * 2;
                *reinterpret_cast<unsigned*>(g_op + base + col) =
                    round_pack2h(cc[mt][nt][half*2], cc[mt][nt][half*2+1]);
            }
        }
    }
}

// ---- combine: out[t] = sum over the token's 8 pairs (atomic-free, fp32 sum of fp16 partials) ----
__global__ void combine_kernel(float* __restrict__ out) {
    int idx = blockIdx.x * blockDim.x + threadIdx.x;
    int idx4 = idx * 4;
    if (idx4 >= T_TOK * D_DIM) return;
    int t = idx4 >> 11;
    int d = idx4 & (D_DIM - 1);
    float4 s = make_float4(0.f, 0.f, 0.f, 0.f);
#pragma unroll
    for (int k = 0; k < K_TOP; k++) {
        uint2 v = *reinterpret_cast<const uint2*>(
            g_op + ((size_t)(t * K_TOP + k)) * D_DIM + d);
        __half2 h01 = *reinterpret_cast<__half2*>(&v.x);
        __half2 h23 = *reinterpret_cast<__half2*>(&v.y);
        float2 f01 = __half22float2(h01);
        float2 f23 = __half22float2(h23);
        s.x += f01.x; s.y += f01.y; s.z += f23.x; s.w += f23.y;
    }
    *reinterpret_cast<float4*>(out + idx4) = s;
}

__global__ void aux_kernel(float* __restrict__ out, int out_size) {
    int lane = threadIdx.x;
    float v = (lane < E_NUM) ? g_probs_sum[lane] * (float)g_counts[lane] : 0.f;
    for (int o = 16; o; o >>= 1) v += __shfl_xor_sync(0xffffffffu, v, o);
    if (lane == 0 && out_size > T_TOK * D_DIM)
        out[T_TOK * D_DIM] = v / ((float)T_TOK * (float)T_TOK);
}

// ---------------------------------------------------------------
extern "C" void kernel_launch(void* const* d_in, const int* in_sizes, int n_in,
                              void* d_out, int out_size) {
    const float* x     = (const float*)d_in[0];
    const float* Wgate = (const float*)d_in[1];
    const float* Wg    = (const float*)d_in[2];
    const float* Wu    = (const float*)d_in[3];
    const float* Wd    = (const float*)d_in[4];
    float* out = (float*)d_out;

    // Unconditional (idempotent) — no static guards per harness contract.
    cudaFuncSetAttribute(gemm_gateup_mma, cudaFuncAttributeMaxDynamicSharedMemorySize,
                         3 * G1_STAGE * 2);
    cudaFuncSetAttribute(gemm_down_mma, cudaFuncAttributeMaxDynamicSharedMemorySize,
                         3 * G2_STAGE * 2);

    convert_init_kernel<<<4096, 256>>>(x, Wg, Wu, Wd);
    routing_kernel<<<T_TOK / 8, 256>>>(x, Wgate);
    scan_kernel<<<1, 32>>>();
    scatter_kernel<<<P_NUM / 256, 256>>>();

    dim3 g1(I_DIM / BN, MAX_TILES);    // (16, 544)
    gemm_gateup_mma<<<g1, 256, 3 * G1_STAGE * 2>>>();

    dim3 g2(D_DIM / BN2, MAX_TILES);   // (16, 544)
    gemm_down_mma<<<g2, 256, 3 * G2_STAGE * 2>>>();

    combine_kernel<<<(T_TOK * D_DIM / 4) / 256, 256>>>(out);
    aux_kernel<<<1, 32>>>(out, out_size);
}